// round 9
// baseline (speedup 1.0000x reference)
#include <cuda_runtime.h>
#include <math.h>

typedef unsigned long long ull;
typedef unsigned int uint;

#define B_    2
#define L_    1728
#define NTOK  3456
#define C_    256
#define U_    256
#define H_    8
#define HD    32
#define FF_   1024
#define EPS_  1e-3f
#define NKT   27

#define FRELU   1
#define FRESID  2
#define FPLANES 4
#define FOUT    8

// ---------------- cp.async helpers ------------------------------------------
__device__ __forceinline__ void cp16(uint saddr, const void* gptr) {
    asm volatile("cp.async.cg.shared.global [%0], [%1], 16;" :: "r"(saddr), "l"(gptr));
}
__device__ __forceinline__ uint sa(const void* p) {
    return (uint)__cvta_generic_to_shared(p);
}
#define CP_COMMIT() asm volatile("cp.async.commit_group;")
#define CP_WAIT0()  asm volatile("cp.async.wait_group 0;")
#define CP_WAIT1()  asm volatile("cp.async.wait_group 1;")

// ---------------- fast exp2 --------------------------------------------------
__device__ __forceinline__ float ex2(float x) {
    float y; asm("ex2.approx.f32 %0,%1;" : "=f"(y) : "f"(x)); return y;
}

// ---------------- bf16 split helpers ---------------------------------------
__device__ __forceinline__ uint bf16_of(float f) {
    unsigned short u; asm("cvt.rn.bf16.f32 %0,%1;" : "=h"(u) : "f"(f));
    return (uint)u;
}
__device__ __forceinline__ void split_pair(float f0, float f1, uint& hi, uint& lo) {
    uint h0 = bf16_of(f0), h1 = bf16_of(f1);
    hi = h0 | (h1 << 16);
    float r0 = f0 - __uint_as_float(h0 << 16);
    float r1 = f1 - __uint_as_float(h1 << 16);
    lo = bf16_of(r0) | (bf16_of(r1) << 16);
}

// ---------------- mma m16n8k16 bf16 -----------------------------------------
__device__ __forceinline__ void mma_bf16(float* c, uint a0, uint a1, uint a2, uint a3,
                                         uint b0, uint b1) {
    asm volatile("mma.sync.aligned.m16n8k16.row.col.f32.bf16.bf16.f32 "
                 "{%0,%1,%2,%3},{%4,%5,%6,%7},{%8,%9},{%0,%1,%2,%3};"
                 : "+f"(c[0]), "+f"(c[1]), "+f"(c[2]), "+f"(c[3])
                 : "r"(a0), "r"(a1), "r"(a2), "r"(a3), "r"(b0), "r"(b1));
}

// ---------------- scratch ---------------------------------------------------
__device__ float d_h   [NTOK*U_];
__device__ float d_v1  [NTOK*U_];
__device__ float d_v2  [NTOK*U_];
__device__ float d_ffo [NTOK*U_];
__device__ float d_acc [NTOK*U_];
__device__ float d_O1  [NTOK*U_];
__device__ float d_O2  [NTOK*U_];

__device__ uint d_xhi [NTOK*128], d_xlo [NTOK*128];
__device__ uint d_cthi[NTOK*128], d_ctlo[NTOK*128];
__device__ uint d_hhi [NTOK*128], d_hlo [NTOK*128];
__device__ uint d_nhi [NTOK*128], d_nlo [NTOK*128];
__device__ uint d_f1hi[NTOK*512], d_f1lo[NTOK*512];
__device__ uint d_ahi [NTOK*128], d_alo [NTOK*128];
__device__ uint d_q1hi[NTOK*128], d_q1lo[NTOK*128];
__device__ uint d_k1hi[NTOK*128], d_k1lo[NTOK*128];
__device__ uint d_q2hi[NTOK*128], d_q2lo[NTOK*128];
__device__ uint d_k2hi[NTOK*128], d_k2lo[NTOK*128];
__device__ uint d_vthi[32*32*864], d_vtlo[32*32*864];

__device__ uint d_Wpin_h[256*128], d_Wpin_l[256*128];
__device__ uint d_Wq1_h [256*128], d_Wq1_l [256*128];
__device__ uint d_Wq2_h [256*128], d_Wq2_l [256*128];
__device__ uint d_Wk_h  [256*128], d_Wk_l  [256*128];
__device__ uint d_Wv_h  [256*128], d_Wv_l  [256*128];
__device__ uint d_Wpout_h[256*128], d_Wpout_l[256*128];
__device__ uint d_Wff1_h[1024*128], d_Wff1_l[1024*128];
__device__ uint d_Wff2_h[256*512],  d_Wff2_l[256*512];

__device__ float d_bpin[U_], d_bq1[U_], d_bq2[U_], d_bff1[FF_];

// ---------------- prep_all (one launch) --------------------------------------
__global__ void __launch_bounds__(256) prep_all(
    const float* __restrict__ x,    const float* __restrict__ ctx,
    const float* __restrict__ bn_g, const float* __restrict__ bn_b,
    const float* __restrict__ bn_m, const float* __restrict__ bn_v,
    const float* __restrict__ ln1_g, const float* __restrict__ ln1_b,
    const float* __restrict__ ln2_g, const float* __restrict__ ln2_b,
    const float* __restrict__ ln3_g, const float* __restrict__ ln3_b,
    const float* __restrict__ pin_w, const float* __restrict__ pin_b,
    const float* __restrict__ q_w,  const float* __restrict__ q_b,
    const float* __restrict__ k_w,  const float* __restrict__ v_w,
    const float* __restrict__ ff1_w, const float* __restrict__ ff1_b,
    const float* __restrict__ ff2_w, const float* __restrict__ pout_w)
{
    int blk = blockIdx.x;
    int tid = threadIdx.x;

    if (blk < 1792) {
        int w = blk * 256 + tid;
        float w0, w1;
        uint *dh, *dl;
        size_t oidx;
        if (w < 196608) {
            int r = w >> 15;
            int idx = w & 32767;
            int u = idx >> 7, k2 = idx & 127;
            int k = k2 * 2;
            oidx = (size_t)u * 128 + k2;
            switch (r) {
            case 0: {
                float s0 = rsqrtf(bn_v[k] + EPS_) * bn_g[k];
                float s1 = rsqrtf(bn_v[k+1] + EPS_) * bn_g[k+1];
                w0 = s0 * pin_w[k*256 + u]; w1 = s1 * pin_w[(k+1)*256 + u];
                dh = d_Wpin_h; dl = d_Wpin_l; } break;
            case 1:
                w0 = ln1_g[k] * q_w[k*256 + u]; w1 = ln1_g[k+1] * q_w[(k+1)*256 + u];
                dh = d_Wq1_h; dl = d_Wq1_l; break;
            case 2:
                w0 = ln2_g[k] * q_w[k*256 + u]; w1 = ln2_g[k+1] * q_w[(k+1)*256 + u];
                dh = d_Wq2_h; dl = d_Wq2_l; break;
            case 3:
                w0 = k_w[k*256 + u]; w1 = k_w[(k+1)*256 + u];
                dh = d_Wk_h; dl = d_Wk_l; break;
            case 4:
                w0 = v_w[k*256 + u]; w1 = v_w[(k+1)*256 + u];
                dh = d_Wv_h; dl = d_Wv_l; break;
            default:
                w0 = pout_w[k*256 + u]; w1 = pout_w[(k+1)*256 + u];
                dh = d_Wpout_h; dl = d_Wpout_l; break;
            }
        } else if (w < 327680) {
            int idx = w - 196608;
            int u = idx >> 7, k2 = idx & 127;
            int k = k2 * 2;
            oidx = (size_t)u * 128 + k2;
            w0 = ln3_g[k] * ff1_w[k*1024 + u]; w1 = ln3_g[k+1] * ff1_w[(k+1)*1024 + u];
            dh = d_Wff1_h; dl = d_Wff1_l;
        } else {
            int idx = w - 327680;
            int u = idx >> 9, k2 = idx & 511;
            int k = k2 * 2;
            oidx = (size_t)u * 512 + k2;
            w0 = ff2_w[k*256 + u]; w1 = ff2_w[(k+1)*256 + u];
            dh = d_Wff2_h; dl = d_Wff2_l;
        }
        uint hi, lo; split_pair(w0, w1, hi, lo);
        dh[oidx] = hi; dl[oidx] = lo;
    } else if (blk < 5248) {
        int rel = blk - 1792;
        const float* s; uint *ph, *pl;
        if (rel < 1728) { s = x; ph = d_xhi; pl = d_xlo; }
        else { rel -= 1728; s = ctx; ph = d_cthi; pl = d_ctlo; }
        int i = rel * 256 + tid;
        float2 f = ((const float2*)s)[i];
        uint h, l; split_pair(f.x, f.y, h, l);
        ph[i] = h; pl[i] = l;
    } else {
        int gw = (blk - 5248) * 8 + (tid >> 5);
        int lane = tid & 31;
        float part = 0.f;
        int u;
        if (gw < 256) {
            u = gw;
            for (int k = lane; k < 256; k += 32) {
                float sc = rsqrtf(bn_v[k] + EPS_) * bn_g[k];
                part += (bn_b[k] - bn_m[k] * sc) * pin_w[k*256 + u];
            }
        } else if (gw < 512) {
            u = gw - 256;
            for (int k = lane; k < 256; k += 32) part += ln1_b[k] * q_w[k*256 + u];
        } else if (gw < 768) {
            u = gw - 512;
            for (int k = lane; k < 256; k += 32) part += ln2_b[k] * q_w[k*256 + u];
        } else {
            u = gw - 768;
            for (int k = lane; k < 256; k += 32) part += ln3_b[k] * ff1_w[k*1024 + u];
        }
        #pragma unroll
        for (int o = 16; o > 0; o >>= 1) part += __shfl_xor_sync(0xffffffffu, part, o);
        if (lane == 0) {
            if (gw < 256)      d_bpin[u] = pin_b[u] + part;
            else if (gw < 512) d_bq1[u]  = q_b[u]  + part;
            else if (gw < 768) d_bq2[u]  = q_b[u]  + part;
            else               d_bff1[u] = ff1_b[u] + part;
        }
    }
}

// ---------------- tensor-core batched GEMM: 64x128 tiles, 256 thr, 3-stage --
struct GOp {
    const uint* Ahi; const uint* Alo;
    const uint* Whi; const uint* Wlo;
    const float* bias; const float* resid;
    float* out; uint* Ohi; uint* Olo;
    int N; int K; int flags; int tileStart;
};
struct GBatch { GOp op[8]; int nops; };

__global__ void __launch_bounds__(256, 2) gemmT(GBatch P)
{
    __shared__ __align__(16) uint As_hi[3][64][12],  As_lo[3][64][12];
    __shared__ __align__(16) uint Ws_hi[3][128][12], Ws_lo[3][128][12];

    int bid = blockIdx.x;
    int sel = 0;
    #pragma unroll
    for (int i = 1; i < 8; i++)
        if (i < P.nops && bid >= P.op[i].tileStart) sel = i;
    GOp g = P.op[sel];

    int local = bid - g.tileStart;
    int ntn = g.N >> 7;                 // 128-col tiles
    int mt = local / ntn;
    int nt = local - mt * ntn;
    int m0 = mt * 64, n0 = nt * 128;
    int tid = threadIdx.x;
    int warp = tid >> 5, lane = tid & 31;
    int gq = lane >> 2, t = lane & 3;
    int rw = warp & 3;                  // row slice 0..3
    int ch = warp >> 2;                 // col half 0..1
    int K2 = g.K >> 1;

    float acc[8][4];
    #pragma unroll
    for (int j = 0; j < 8; j++)
        #pragma unroll
        for (int i = 0; i < 4; i++) acc[j][i] = 0.f;

    // fill indices
    int arow = tid >> 1;                // valid for tid<128
    int ahf  = (tid & 1) * 4;
    int wrow = tid >> 1;                // 0..127
    int whf  = (tid & 1) * 4;
    const size_t abase = (size_t)(m0 + arow) * K2 + ahf;
    const size_t wbase = (size_t)(n0 + wrow) * K2 + whf;

    int nc = K2 >> 3;

    #pragma unroll
    for (int s = 0; s < 2; s++) {
        size_t off = (size_t)s * 8;
        if (tid < 128) {
            cp16(sa(&As_hi[s][arow][ahf]), g.Ahi + abase + off);
            cp16(sa(&As_lo[s][arow][ahf]), g.Alo + abase + off);
        }
        cp16(sa(&Ws_hi[s][wrow][whf]), g.Whi + wbase + off);
        cp16(sa(&Ws_lo[s][wrow][whf]), g.Wlo + wbase + off);
        CP_COMMIT();
    }

    for (int c = 0; c < nc; c++) {
        CP_WAIT1();
        __syncthreads();
        int pc = c + 2;
        if (pc < nc) {
            int nb = pc % 3;
            size_t off = (size_t)pc * 8;
            if (tid < 128) {
                cp16(sa(&As_hi[nb][arow][ahf]), g.Ahi + abase + off);
                cp16(sa(&As_lo[nb][arow][ahf]), g.Alo + abase + off);
            }
            cp16(sa(&Ws_hi[nb][wrow][whf]), g.Whi + wbase + off);
            cp16(sa(&Ws_lo[nb][wrow][whf]), g.Wlo + wbase + off);
        }
        CP_COMMIT();

        int bb = c % 3;
        int rs = rw * 16;
        uint a0h = As_hi[bb][rs+gq  ][t  ], a1h = As_hi[bb][rs+gq+8][t  ];
        uint a2h = As_hi[bb][rs+gq  ][t+4], a3h = As_hi[bb][rs+gq+8][t+4];
        uint a0l = As_lo[bb][rs+gq  ][t  ], a1l = As_lo[bb][rs+gq+8][t  ];
        uint a2l = As_lo[bb][rs+gq  ][t+4], a3l = As_lo[bb][rs+gq+8][t+4];

        #pragma unroll
        for (int j = 0; j < 8; j++) {
            int n = ch * 64 + j*8 + gq;
            uint b0h = Ws_hi[bb][n][t], b1h = Ws_hi[bb][n][t+4];
            uint b0l = Ws_lo[bb][n][t], b1l = Ws_lo[bb][n][t+4];
            mma_bf16(acc[j], a0h, a1h, a2h, a3h, b0h, b1h);
            mma_bf16(acc[j], a0h, a1h, a2h, a3h, b0l, b1l);
            mma_bf16(acc[j], a0l, a1l, a2l, a3l, b0h, b1h);
        }
    }

    int K2o = g.N >> 1;
    int r0 = m0 + rw*16 + gq;
    int r1 = r0 + 8;
    #pragma unroll
    for (int j = 0; j < 8; j++) {
        int c0 = n0 + ch*64 + j*8 + 2*t;
        float b0 = g.bias[c0], b1 = g.bias[c0+1];
        float v00 = acc[j][0] + b0, v01 = acc[j][1] + b1;
        float v10 = acc[j][2] + b0, v11 = acc[j][3] + b1;
        if (g.flags & FRELU) {
            v00 = fmaxf(v00, 0.f); v01 = fmaxf(v01, 0.f);
            v10 = fmaxf(v10, 0.f); v11 = fmaxf(v11, 0.f);
        }
        if (g.flags & FRESID) {
            float2 ra = *(const float2*)&g.resid[(size_t)r0*g.N + c0];
            float2 rb = *(const float2*)&g.resid[(size_t)r1*g.N + c0];
            v00 += ra.x; v01 += ra.y; v10 += rb.x; v11 += rb.y;
        }
        if (g.flags & FOUT) {
            *(float2*)&g.out[(size_t)r0*g.N + c0] = make_float2(v00, v01);
            *(float2*)&g.out[(size_t)r1*g.N + c0] = make_float2(v10, v11);
        }
        if (g.flags & FPLANES) {
            uint h, l;
            split_pair(v00, v01, h, l);
            g.Ohi[(size_t)r0*K2o + (c0>>1)] = h; g.Olo[(size_t)r0*K2o + (c0>>1)] = l;
            split_pair(v10, v11, h, l);
            g.Ohi[(size_t)r1*K2o + (c0>>1)] = h; g.Olo[(size_t)r1*K2o + (c0>>1)] = l;
        }
    }
}

// ---------------- LayerNorm -> planes ----------------------------------------
__global__ void __launch_bounds__(256) lnorm_kernel(const float* __restrict__ h,
                                                    uint* __restrict__ nhi,
                                                    uint* __restrict__ nlo)
{
    int row = blockIdx.x;
    int tid = threadIdx.x;
    float v = h[(size_t)row * 256 + tid];
    __shared__ float red[8];
    float s = v;
    #pragma unroll
    for (int o = 16; o > 0; o >>= 1) s += __shfl_xor_sync(0xffffffffu, s, o);
    if ((tid & 31) == 0) red[tid >> 5] = s;
    __syncthreads();
    float tot = 0.f;
    #pragma unroll
    for (int i = 0; i < 8; i++) tot += red[i];
    float mu = tot * (1.f / 256.f);
    float d = v - mu;
    float s2 = d * d;
    #pragma unroll
    for (int o = 16; o > 0; o >>= 1) s2 += __shfl_xor_sync(0xffffffffu, s2, o);
    __syncthreads();
    if ((tid & 31) == 0) red[tid >> 5] = s2;
    __syncthreads();
    float tot2 = 0.f;
    #pragma unroll
    for (int i = 0; i < 8; i++) tot2 += red[i];
    float var = tot2 * (1.f / 256.f);
    float o = d * rsqrtf(var + EPS_);
    float pn = __shfl_xor_sync(0xffffffffu, o, 1);
    if (!(tid & 1)) {
        uint hi, lo; split_pair(o, pn, hi, lo);
        nhi[(size_t)row * 128 + (tid >> 1)] = hi;
        nlo[(size_t)row * 128 + (tid >> 1)] = lo;
    }
}

// ---------------- V transpose into packed key-pair planes -------------------
__global__ void __launch_bounds__(128) vplanes_T(
    const float* __restrict__ V1, const float* __restrict__ V2,
    uint* __restrict__ vthi, uint* __restrict__ vtlo)
{
    __shared__ float Vs[64][33];
    int tid = threadIdx.x;
    int kt = blockIdx.x;
    int head = blockIdx.y;
    int br = blockIdx.z >> 1, b = blockIdx.z & 1;
    const float* V = br ? V2 : V1;
    #pragma unroll
    for (int i = 0; i < 4; i++) {
        int idx = tid + i * 128;
        int key = idx >> 3, f4 = (idx & 7) * 4;
        const float* p = &V[(size_t)(b * L_ + kt * 64 + key) * 256 + head * 32 + f4];
        float4 t4 = *(const float4*)p;
        Vs[key][f4] = t4.x; Vs[key][f4+1] = t4.y;
        Vs[key][f4+2] = t4.z; Vs[key][f4+3] = t4.w;
    }
    __syncthreads();
    int g = (br * 2 + b) * 8 + head;
    #pragma unroll
    for (int i = 0; i < 8; i++) {
        int widx = tid + i * 128;
        int d = widx >> 5, kp = widx & 31;
        uint hi, lo;
        split_pair(Vs[2*kp][d], Vs[2*kp+1][d], hi, lo);
        size_t o = ((size_t)g * 32 + d) * 864 + kt * 32 + kp;
        vthi[o] = hi; vtlo[o] = lo;
    }
}

// ---------------- tensor-core flash attention --------------------------------
__global__ void __launch_bounds__(128) attn_mma(
    const uint* __restrict__ Q1hi, const uint* __restrict__ Q1lo,
    const uint* __restrict__ K1hi, const uint* __restrict__ K1lo,
    const uint* __restrict__ Q2hi, const uint* __restrict__ Q2lo,
    const uint* __restrict__ K2hi, const uint* __restrict__ K2lo,
    const uint* __restrict__ VThi, const uint* __restrict__ VTlo,
    float* __restrict__ O1, float* __restrict__ O2)
{
    __shared__ __align__(16) uint Khi[2][64][20], Klo[2][64][20];
    __shared__ __align__(16) uint Vhi[2][32][36], Vlo[2][32][36];

    int tid = threadIdx.x, warp = tid >> 5, lane = tid & 31;
    int gq = lane >> 2, t = lane & 3;
    int qt = blockIdx.x, head = blockIdx.y;
    int br = blockIdx.z >> 1, b = blockIdx.z & 1;
    const uint* Qhi = br ? Q2hi : Q1hi;
    const uint* Qlo = br ? Q2lo : Q1lo;
    const uint* KhG = br ? K2hi : K1hi;
    const uint* KlG = br ? K2lo : K1lo;
    float* Ob = br ? O2 : O1;
    const float scale2 = 0.0625f * 1.44269504089f;

    int vg = (br * 2 + b) * 8 + head;

    int fkey = tid >> 1;
    int fkw  = (tid & 1) * 8;
    int fd   = tid >> 2;
    int fvw  = (tid & 3) * 8;
    const size_t kbase = (size_t)(b * L_ + fkey) * 128 + head * 16 + fkw;
    const size_t vbase = ((size_t)vg * 32 + fd) * 864 + fvw;

    {
        cp16(sa(&Khi[0][fkey][fkw]),   KhG + kbase);
        cp16(sa(&Khi[0][fkey][fkw+4]), KhG + kbase + 4);
        cp16(sa(&Klo[0][fkey][fkw]),   KlG + kbase);
        cp16(sa(&Klo[0][fkey][fkw+4]), KlG + kbase + 4);
        cp16(sa(&Vhi[0][fd][fvw]),     VThi + vbase);
        cp16(sa(&Vhi[0][fd][fvw+4]),   VThi + vbase + 4);
        cp16(sa(&Vlo[0][fd][fvw]),     VTlo + vbase);
        cp16(sa(&Vlo[0][fd][fvw+4]),   VTlo + vbase + 4);
        CP_COMMIT();
    }

    int r0 = qt * 64 + warp * 16 + gq;
    int r1 = r0 + 8;

    uint qh[2][4], ql[2][4];
    {
        size_t q0 = (size_t)(b * L_ + r0) * 128 + head * 16;
        size_t q1 = (size_t)(b * L_ + r1) * 128 + head * 16;
        #pragma unroll
        for (int ks = 0; ks < 2; ks++) {
            qh[ks][0] = Qhi[q0 + ks*8 + t];     qh[ks][1] = Qhi[q1 + ks*8 + t];
            qh[ks][2] = Qhi[q0 + ks*8 + t + 4]; qh[ks][3] = Qhi[q1 + ks*8 + t + 4];
            ql[ks][0] = Qlo[q0 + ks*8 + t];     ql[ks][1] = Qlo[q1 + ks*8 + t];
            ql[ks][2] = Qlo[q0 + ks*8 + t + 4]; ql[ks][3] = Qlo[q1 + ks*8 + t + 4];
        }
    }

    float Oacc[4][4];
    #pragma unroll
    for (int j = 0; j < 4; j++)
        #pragma unroll
        for (int i = 0; i < 4; i++) Oacc[j][i] = 0.f;
    float m0r = -1e30f, m1r = -1e30f, l0r = 0.f, l1r = 0.f;

    for (int kt = 0; kt < NKT; kt++) {
        CP_WAIT0();
        __syncthreads();
        if (kt + 1 < NKT) {
            int nb = (kt + 1) & 1;
            size_t ko = kbase + (size_t)(kt + 1) * 64 * 128;
            size_t vo = vbase + (size_t)(kt + 1) * 32;
            cp16(sa(&Khi[nb][fkey][fkw]),   KhG + ko);
            cp16(sa(&Khi[nb][fkey][fkw+4]), KhG + ko + 4);
            cp16(sa(&Klo[nb][fkey][fkw]),   KlG + ko);
            cp16(sa(&Klo[nb][fkey][fkw+4]), KlG + ko + 4);
            cp16(sa(&Vhi[nb][fd][fvw]),     VThi + vo);
            cp16(sa(&Vhi[nb][fd][fvw+4]),   VThi + vo + 4);
            cp16(sa(&Vlo[nb][fd][fvw]),     VTlo + vo);
            cp16(sa(&Vlo[nb][fd][fvw+4]),   VTlo + vo + 4);
            CP_COMMIT();
        }
        int bb = kt & 1;

        float s[8][4];
        #pragma unroll
        for (int j = 0; j < 8; j++) {
            s[j][0] = s[j][1] = s[j][2] = s[j][3] = 0.f;
            int n = j * 8 + gq;
            #pragma unroll
            for (int ks = 0; ks < 2; ks++) {
                uint b0h = Khi[bb][n][ks*8 + t], b1h = Khi[bb][n][ks*8 + t + 4];
                uint b0l = Klo[bb][n][ks*8 + t], b1l = Klo[bb][n][ks*8 + t + 4];
                mma_bf16(s[j], qh[ks][0], qh[ks][1], qh[ks][2], qh[ks][3], b0h, b1h);
                mma_bf16(s[j], qh[ks][0], qh[ks][1], qh[ks][2], qh[ks][3], b0l, b1l);
                mma_bf16(s[j], ql[ks][0], ql[ks][1], ql[ks][2], ql[ks][3], b0h, b1h);
            }
            s[j][0] *= scale2; s[j][1] *= scale2;
            s[j][2] *= scale2; s[j][3] *= scale2;
        }

        float mx0 = -1e30f, mx1 = -1e30f;
        #pragma unroll
        for (int j = 0; j < 8; j++) {
            mx0 = fmaxf(mx0, fmaxf(s[j][0], s[j][1]));
            mx1 = fmaxf(mx1, fmaxf(s[j][2], s[j][3]));
        }
        mx0 = fmaxf(mx0, __shfl_xor_sync(0xffffffffu, mx0, 1));
        mx0 = fmaxf(mx0, __shfl_xor_sync(0xffffffffu, mx0, 2));
        mx1 = fmaxf(mx1, __shfl_xor_sync(0xffffffffu, mx1, 1));
        mx1 = fmaxf(mx1, __shfl_xor_sync(0xffffffffu, mx1, 2));
        float nm0 = fmaxf(m0r, mx0), nm1 = fmaxf(m1r, mx1);
        float c0 = ex2(m0r - nm0), c1 = ex2(m1r - nm1);

        float ls0 = 0.f, ls1 = 0.f;
        #pragma unroll
        for (int j = 0; j < 8; j++) {
            s[j][0] = ex2(s[j][0] - nm0); ls0 += s[j][0];
            s[j][1] = ex2(s[j][1] - nm0); ls0 += s[j][1];
            s[j][2] = ex2(s[j][2] - nm1); ls1 += s[j][2];
            s[j][3] = ex2(s[j][3] - nm1); ls1 += s[j][3];
        }
        ls0 += __shfl_xor_sync(0xffffffffu, ls0, 1);
        ls0 += __shfl_xor_sync(0xffffffffu, ls0, 2);
        ls1 += __shfl_xor_sync(0xffffffffu, ls1, 1);
        ls1 += __shfl_xor_sync(0xffffffffu, ls1, 2);
        l0r = l0r * c0 + ls0;
        l1r = l1r * c1 + ls1;
        m0r = nm0; m1r = nm1;

        #pragma unroll
        for (int jn = 0; jn < 4; jn++) {
            Oacc[jn][0] *= c0; Oacc[jn][1] *= c0;
            Oacc[jn][2] *= c1; Oacc[jn][3] *= c1;
        }

        uint ph[4][4], pl[4][4];
        #pragma unroll
        for (int ks = 0; ks < 4; ks++) {
            split_pair(s[2*ks  ][0], s[2*ks  ][1], ph[ks][0], pl[ks][0]);
            split_pair(s[2*ks  ][2], s[2*ks  ][3], ph[ks][1], pl[ks][1]);
            split_pair(s[2*ks+1][0], s[2*ks+1][1], ph[ks][2], pl[ks][2]);
            split_pair(s[2*ks+1][2], s[2*ks+1][3], ph[ks][3], pl[ks][3]);
        }

        #pragma unroll
        for (int jn = 0; jn < 4; jn++) {
            int n = jn * 8 + gq;
            #pragma unroll
            for (int ks = 0; ks < 4; ks++) {
                uint b0h = Vhi[bb][n][ks*8 + t], b1h = Vhi[bb][n][ks*8 + t + 4];
                uint b0l = Vlo[bb][n][ks*8 + t], b1l = Vlo[bb][n][ks*8 + t + 4];
                mma_bf16(Oacc[jn], ph[ks][0], ph[ks][1], ph[ks][2], ph[ks][3], b0h, b1h);
                mma_bf16(Oacc[jn], ph[ks][0], ph[ks][1], ph[ks][2], ph[ks][3], b0l, b1l);
                mma_bf16(Oacc[jn], pl[ks][0], pl[ks][1], pl[ks][2], pl[ks][3], b0h, b1h);
            }
        }
    }

    float inv0 = 1.f / l0r, inv1 = 1.f / l1r;
    #pragma unroll
    for (int jn = 0; jn < 4; jn++) {
        int col = head * 32 + jn * 8 + 2 * t;
        *(float2*)&Ob[(size_t)(b * L_ + r0) * 256 + col] =
            make_float2(Oacc[jn][0] * inv0, Oacc[jn][1] * inv0);
        *(float2*)&Ob[(size_t)(b * L_ + r1) * 256 + col] =
            make_float2(Oacc[jn][2] * inv1, Oacc[jn][3] * inv1);
    }
}

// ---------------- combine ------------------------------------------------------
__global__ void __launch_bounds__(256) combine_kernel(
    const float* __restrict__ O1, const float* __restrict__ O2,
    const float* __restrict__ h, const float* __restrict__ ffo,
    float* __restrict__ acc, uint* __restrict__ ahi, uint* __restrict__ alo)
{
    int tok = blockIdx.x;
    int u = threadIdx.x;
    size_t i = (size_t)tok * 256 + u;
    float o = h[i] + ffo[i] + O1[i] + O2[i];
    acc[i] = o;
    float pn = __shfl_xor_sync(0xffffffffu, o, 1);
    if (!(u & 1)) {
        uint hi, lo; split_pair(o, pn, hi, lo);
        ahi[(size_t)tok * 128 + (u >> 1)] = hi;
        alo[(size_t)tok * 128 + (u >> 1)] = lo;
    }
}

// ---------------- launch --------------------------------------------------------
extern "C" void kernel_launch(void* const* d_in, const int* in_sizes, int n_in,
                              void* d_out, int out_size)
{
    const float* x       = (const float*)d_in[0];
    const float* context = (const float*)d_in[1];
    const float* bn_g = (const float*)d_in[2];
    const float* bn_b = (const float*)d_in[3];
    const float* bn_m = (const float*)d_in[4];
    const float* bn_v = (const float*)d_in[5];
    const float* ln1_g = (const float*)d_in[6];
    const float* ln1_b = (const float*)d_in[7];
    const float* ln2_g = (const float*)d_in[8];
    const float* ln2_b = (const float*)d_in[9];
    const float* ln3_g = (const float*)d_in[10];
    const float* ln3_b = (const float*)d_in[11];
    const float* pin_w = (const float*)d_in[12];
    const float* pin_b = (const float*)d_in[13];
    const float* q_w   = (const float*)d_in[14];
    const float* q_b   = (const float*)d_in[15];
    const float* k_w   = (const float*)d_in[16];
    const float* k_b   = (const float*)d_in[17];
    const float* v_w   = (const float*)d_in[18];
    const float* v_b   = (const float*)d_in[19];
    const float* ff1_w = (const float*)d_in[20];
    const float* ff1_b = (const float*)d_in[21];
    const float* ff2_w = (const float*)d_in[22];
    const float* ff2_b = (const float*)d_in[23];
    const float* pout_w = (const float*)d_in[24];
    const float* pout_b = (const float*)d_in[25];
    float* out = (float*)d_out;

    float *p_h, *p_v1, *p_v2, *p_ffo, *p_acc, *p_O1, *p_O2;
    uint *p_xhi, *p_xlo, *p_cthi, *p_ctlo, *p_hhi, *p_hlo, *p_nhi, *p_nlo;
    uint *p_f1hi, *p_f1lo, *p_ahi, *p_alo;
    uint *p_q1hi, *p_q1lo, *p_k1hi, *p_k1lo, *p_q2hi, *p_q2lo, *p_k2hi, *p_k2lo;
    uint *p_vthi, *p_vtlo;
    uint *w_pin_h, *w_pin_l, *w_q1_h, *w_q1_l, *w_q2_h, *w_q2_l;
    uint *w_k_h, *w_k_l, *w_v_h, *w_v_l, *w_po_h, *w_po_l;
    uint *w_f1_h, *w_f1_l, *w_f2_h, *w_f2_l;
    float *p_bpin, *p_bq1, *p_bq2, *p_bff1;

    cudaGetSymbolAddress((void**)&p_h,    d_h);
    cudaGetSymbolAddress((void**)&p_v1,   d_v1);
    cudaGetSymbolAddress((void**)&p_v2,   d_v2);
    cudaGetSymbolAddress((void**)&p_ffo,  d_ffo);
    cudaGetSymbolAddress((void**)&p_acc,  d_acc);
    cudaGetSymbolAddress((void**)&p_O1,   d_O1);
    cudaGetSymbolAddress((void**)&p_O2,   d_O2);
    cudaGetSymbolAddress((void**)&p_xhi,  d_xhi);
    cudaGetSymbolAddress((void**)&p_xlo,  d_xlo);
    cudaGetSymbolAddress((void**)&p_cthi, d_cthi);
    cudaGetSymbolAddress((void**)&p_ctlo, d_ctlo);
    cudaGetSymbolAddress((void**)&p_hhi,  d_hhi);
    cudaGetSymbolAddress((void**)&p_hlo,  d_hlo);
    cudaGetSymbolAddress((void**)&p_nhi,  d_nhi);
    cudaGetSymbolAddress((void**)&p_nlo,  d_nlo);
    cudaGetSymbolAddress((void**)&p_f1hi, d_f1hi);
    cudaGetSymbolAddress((void**)&p_f1lo, d_f1lo);
    cudaGetSymbolAddress((void**)&p_ahi,  d_ahi);
    cudaGetSymbolAddress((void**)&p_alo,  d_alo);
    cudaGetSymbolAddress((void**)&p_q1hi, d_q1hi);
    cudaGetSymbolAddress((void**)&p_q1lo, d_q1lo);
    cudaGetSymbolAddress((void**)&p_k1hi, d_k1hi);
    cudaGetSymbolAddress((void**)&p_k1lo, d_k1lo);
    cudaGetSymbolAddress((void**)&p_q2hi, d_q2hi);
    cudaGetSymbolAddress((void**)&p_q2lo, d_q2lo);
    cudaGetSymbolAddress((void**)&p_k2hi, d_k2hi);
    cudaGetSymbolAddress((void**)&p_k2lo, d_k2lo);
    cudaGetSymbolAddress((void**)&p_vthi, d_vthi);
    cudaGetSymbolAddress((void**)&p_vtlo, d_vtlo);
    cudaGetSymbolAddress((void**)&w_pin_h, d_Wpin_h);
    cudaGetSymbolAddress((void**)&w_pin_l, d_Wpin_l);
    cudaGetSymbolAddress((void**)&w_q1_h,  d_Wq1_h);
    cudaGetSymbolAddress((void**)&w_q1_l,  d_Wq1_l);
    cudaGetSymbolAddress((void**)&w_q2_h,  d_Wq2_h);
    cudaGetSymbolAddress((void**)&w_q2_l,  d_Wq2_l);
    cudaGetSymbolAddress((void**)&w_k_h,   d_Wk_h);
    cudaGetSymbolAddress((void**)&w_k_l,   d_Wk_l);
    cudaGetSymbolAddress((void**)&w_v_h,   d_Wv_h);
    cudaGetSymbolAddress((void**)&w_v_l,   d_Wv_l);
    cudaGetSymbolAddress((void**)&w_po_h,  d_Wpout_h);
    cudaGetSymbolAddress((void**)&w_po_l,  d_Wpout_l);
    cudaGetSymbolAddress((void**)&w_f1_h,  d_Wff1_h);
    cudaGetSymbolAddress((void**)&w_f1_l,  d_Wff1_l);
    cudaGetSymbolAddress((void**)&w_f2_h,  d_Wff2_h);
    cudaGetSymbolAddress((void**)&w_f2_l,  d_Wff2_l);
    cudaGetSymbolAddress((void**)&p_bpin,  d_bpin);
    cudaGetSymbolAddress((void**)&p_bq1,   d_bq1);
    cudaGetSymbolAddress((void**)&p_bq2,   d_bq2);
    cudaGetSymbolAddress((void**)&p_bff1,  d_bff1);

    // 1. all prep
    prep_all<<<5472, 256>>>(x, context, bn_g, bn_b, bn_m, bn_v,
                            ln1_g, ln1_b, ln2_g, ln2_b, ln3_g, ln3_b,
                            pin_w, pin_b, q_w, q_b, k_w, v_w,
                            ff1_w, ff1_b, ff2_w, pout_w);

    auto mkop = [](const uint* Ahi, const uint* Alo, const uint* Whi, const uint* Wlo,
                   const float* bias, const float* resid, float* o,
                   uint* Ohi, uint* Olo, int N, int K, int flags, int start) {
        GOp g; g.Ahi = Ahi; g.Alo = Alo; g.Whi = Whi; g.Wlo = Wlo;
        g.bias = bias; g.resid = resid; g.out = o; g.Ohi = Ohi; g.Olo = Olo;
        g.N = N; g.K = K; g.flags = flags; g.tileStart = start;
        return g;
    };
    const int RT = NTOK / 64;          // 54 row tiles
    const int T256 = RT * 2;           // 108 blocks for N=256 (128-col tiles)

    // 2. batch A: pin + k2 + v2
    {
        GBatch P = {};
        P.op[0] = mkop(p_xhi, p_xlo, w_pin_h, w_pin_l, p_bpin, nullptr,
                       p_h, p_hhi, p_hlo, 256, 256, FOUT | FRELU | FPLANES, 0);
        P.op[1] = mkop(p_cthi, p_ctlo, w_k_h, w_k_l, k_b, nullptr,
                       nullptr, p_k2hi, p_k2lo, 256, 256, FPLANES, T256);
        P.op[2] = mkop(p_cthi, p_ctlo, w_v_h, w_v_l, v_b, nullptr,
                       p_v2, nullptr, nullptr, 256, 256, FOUT, T256*2);
        P.nops = 3;
        gemmT<<<T256*3, 256>>>(P);
    }

    // 3. hhat planes
    lnorm_kernel<<<NTOK, 256>>>(p_h, p_nhi, p_nlo);

    // 4. batch B: q1, k1, v1, q2, ff1
    {
        GBatch P = {};
        P.op[0] = mkop(p_nhi, p_nlo, w_q1_h, w_q1_l, p_bq1, nullptr,
                       nullptr, p_q1hi, p_q1lo, 256, 256, FPLANES, 0);
        P.op[1] = mkop(p_hhi, p_hlo, w_k_h, w_k_l, k_b, nullptr,
                       nullptr, p_k1hi, p_k1lo, 256, 256, FPLANES, T256);
        P.op[2] = mkop(p_hhi, p_hlo, w_v_h, w_v_l, v_b, nullptr,
                       p_v1, nullptr, nullptr, 256, 256, FOUT, T256*2);
        P.op[3] = mkop(p_nhi, p_nlo, w_q2_h, w_q2_l, p_bq2, nullptr,
                       nullptr, p_q2hi, p_q2lo, 256, 256, FPLANES, T256*3);
        P.op[4] = mkop(p_nhi, p_nlo, w_f1_h, w_f1_l, p_bff1, nullptr,
                       nullptr, p_f1hi, p_f1lo, 1024, 256, FRELU | FPLANES, T256*4);
        P.nops = 5;
        gemmT<<<T256*4 + RT*8, 256>>>(P);   // 432 + 432 = 864
    }

    // 5. V transpose planes
    {
        dim3 gv(NKT, H_, 4);
        vplanes_T<<<gv, 128>>>(p_v1, p_v2, p_vthi, p_vtlo);
    }

    // 6. attention
    {
        dim3 ga(NKT, H_, 4);
        attn_mma<<<ga, 128>>>(p_q1hi, p_q1lo, p_k1hi, p_k1lo,
                              p_q2hi, p_q2lo, p_k2hi, p_k2lo,
                              p_vthi, p_vtlo, p_O1, p_O2);
    }

    // 7. ff2
    {
        GBatch P = {};
        P.op[0] = mkop(p_f1hi, p_f1lo, w_f2_h, w_f2_l, ff2_b, nullptr,
                       p_ffo, nullptr, nullptr, 256, 1024, FOUT, 0);
        P.nops = 1;
        gemmT<<<T256, 256>>>(P);
    }

    // 8. combine
    combine_kernel<<<NTOK, 256>>>(p_O1, p_O2, p_h, p_ffo, p_acc, p_ahi, p_alo);

    // 9. out = relu(acc @ pout + b) + x
    {
        GBatch P = {};
        P.op[0] = mkop(p_ahi, p_alo, w_po_h, w_po_l, pout_b, x,
                       out, nullptr, nullptr, 256, 256, FOUT | FRELU | FRESID, 0);
        P.nops = 1;
        gemmT<<<T256, 256>>>(P);
    }
}

// round 10
// speedup vs baseline: 1.0331x; 1.0331x over previous
#include <cuda_runtime.h>
#include <math.h>

typedef unsigned long long ull;
typedef unsigned int uint;

#define B_    2
#define L_    1728
#define NTOK  3456
#define C_    256
#define U_    256
#define H_    8
#define HD    32
#define FF_   1024
#define EPS_  1e-3f
#define NKT   27

#define FRELU   1
#define FRESID  2
#define FPLANES 4
#define FOUT    8

// ---------------- cp.async helpers ------------------------------------------
__device__ __forceinline__ void cp16(uint saddr, const void* gptr) {
    asm volatile("cp.async.cg.shared.global [%0], [%1], 16;" :: "r"(saddr), "l"(gptr));
}
__device__ __forceinline__ uint sa(const void* p) {
    return (uint)__cvta_generic_to_shared(p);
}
#define CP_COMMIT() asm volatile("cp.async.commit_group;")
#define CP_WAIT0()  asm volatile("cp.async.wait_group 0;")
#define CP_WAIT1()  asm volatile("cp.async.wait_group 1;")

// ---------------- ldmatrix ----------------------------------------------------
__device__ __forceinline__ void ldsm4(uint& r0, uint& r1, uint& r2, uint& r3, uint saddr) {
    asm volatile("ldmatrix.sync.aligned.m8n8.x4.shared.b16 {%0,%1,%2,%3}, [%4];"
                 : "=r"(r0), "=r"(r1), "=r"(r2), "=r"(r3) : "r"(saddr));
}

// ---------------- fast exp2 --------------------------------------------------
__device__ __forceinline__ float ex2(float x) {
    float y; asm("ex2.approx.f32 %0,%1;" : "=f"(y) : "f"(x)); return y;
}

// ---------------- bf16 split helpers ---------------------------------------
__device__ __forceinline__ uint bf16_of(float f) {
    unsigned short u; asm("cvt.rn.bf16.f32 %0,%1;" : "=h"(u) : "f"(f));
    return (uint)u;
}
__device__ __forceinline__ void split_pair(float f0, float f1, uint& hi, uint& lo) {
    uint h0 = bf16_of(f0), h1 = bf16_of(f1);
    hi = h0 | (h1 << 16);
    float r0 = f0 - __uint_as_float(h0 << 16);
    float r1 = f1 - __uint_as_float(h1 << 16);
    lo = bf16_of(r0) | (bf16_of(r1) << 16);
}

// ---------------- mma m16n8k16 bf16 -----------------------------------------
__device__ __forceinline__ void mma_bf16(float* c, uint a0, uint a1, uint a2, uint a3,
                                         uint b0, uint b1) {
    asm volatile("mma.sync.aligned.m16n8k16.row.col.f32.bf16.bf16.f32 "
                 "{%0,%1,%2,%3},{%4,%5,%6,%7},{%8,%9},{%0,%1,%2,%3};"
                 : "+f"(c[0]), "+f"(c[1]), "+f"(c[2]), "+f"(c[3])
                 : "r"(a0), "r"(a1), "r"(a2), "r"(a3), "r"(b0), "r"(b1));
}

// ---------------- scratch ---------------------------------------------------
__device__ float d_h   [NTOK*U_];
__device__ float d_v1  [NTOK*U_];
__device__ float d_v2  [NTOK*U_];
__device__ float d_ffo [NTOK*U_];
__device__ float d_acc [NTOK*U_];
__device__ float d_O1  [NTOK*U_];
__device__ float d_O2  [NTOK*U_];

__device__ uint d_xhi [NTOK*128], d_xlo [NTOK*128];
__device__ uint d_cthi[NTOK*128], d_ctlo[NTOK*128];
__device__ uint d_hhi [NTOK*128], d_hlo [NTOK*128];
__device__ uint d_nhi [NTOK*128], d_nlo [NTOK*128];
__device__ uint d_f1hi[NTOK*512], d_f1lo[NTOK*512];
__device__ uint d_ahi [NTOK*128], d_alo [NTOK*128];
__device__ uint d_q1hi[NTOK*128], d_q1lo[NTOK*128];
__device__ uint d_k1hi[NTOK*128], d_k1lo[NTOK*128];
__device__ uint d_q2hi[NTOK*128], d_q2lo[NTOK*128];
__device__ uint d_k2hi[NTOK*128], d_k2lo[NTOK*128];
__device__ uint d_vthi[32*32*864], d_vtlo[32*32*864];

__device__ uint d_Wpin_h[256*128], d_Wpin_l[256*128];
__device__ uint d_Wq1_h [256*128], d_Wq1_l [256*128];
__device__ uint d_Wq2_h [256*128], d_Wq2_l [256*128];
__device__ uint d_Wk_h  [256*128], d_Wk_l  [256*128];
__device__ uint d_Wv_h  [256*128], d_Wv_l  [256*128];
__device__ uint d_Wpout_h[256*128], d_Wpout_l[256*128];
__device__ uint d_Wff1_h[1024*128], d_Wff1_l[1024*128];
__device__ uint d_Wff2_h[256*512],  d_Wff2_l[256*512];

__device__ float d_bpin[U_], d_bq1[U_], d_bq2[U_], d_bff1[FF_];

// ---------------- prep_all (one launch) --------------------------------------
__global__ void __launch_bounds__(256) prep_all(
    const float* __restrict__ x,    const float* __restrict__ ctx,
    const float* __restrict__ bn_g, const float* __restrict__ bn_b,
    const float* __restrict__ bn_m, const float* __restrict__ bn_v,
    const float* __restrict__ ln1_g, const float* __restrict__ ln1_b,
    const float* __restrict__ ln2_g, const float* __restrict__ ln2_b,
    const float* __restrict__ ln3_g, const float* __restrict__ ln3_b,
    const float* __restrict__ pin_w, const float* __restrict__ pin_b,
    const float* __restrict__ q_w,  const float* __restrict__ q_b,
    const float* __restrict__ k_w,  const float* __restrict__ v_w,
    const float* __restrict__ ff1_w, const float* __restrict__ ff1_b,
    const float* __restrict__ ff2_w, const float* __restrict__ pout_w)
{
    int blk = blockIdx.x;
    int tid = threadIdx.x;

    if (blk < 1792) {
        int w = blk * 256 + tid;
        float w0, w1;
        uint *dh, *dl;
        size_t oidx;
        if (w < 196608) {
            int r = w >> 15;
            int idx = w & 32767;
            int u = idx >> 7, k2 = idx & 127;
            int k = k2 * 2;
            oidx = (size_t)u * 128 + k2;
            switch (r) {
            case 0: {
                float s0 = rsqrtf(bn_v[k] + EPS_) * bn_g[k];
                float s1 = rsqrtf(bn_v[k+1] + EPS_) * bn_g[k+1];
                w0 = s0 * pin_w[k*256 + u]; w1 = s1 * pin_w[(k+1)*256 + u];
                dh = d_Wpin_h; dl = d_Wpin_l; } break;
            case 1:
                w0 = ln1_g[k] * q_w[k*256 + u]; w1 = ln1_g[k+1] * q_w[(k+1)*256 + u];
                dh = d_Wq1_h; dl = d_Wq1_l; break;
            case 2:
                w0 = ln2_g[k] * q_w[k*256 + u]; w1 = ln2_g[k+1] * q_w[(k+1)*256 + u];
                dh = d_Wq2_h; dl = d_Wq2_l; break;
            case 3:
                w0 = k_w[k*256 + u]; w1 = k_w[(k+1)*256 + u];
                dh = d_Wk_h; dl = d_Wk_l; break;
            case 4:
                w0 = v_w[k*256 + u]; w1 = v_w[(k+1)*256 + u];
                dh = d_Wv_h; dl = d_Wv_l; break;
            default:
                w0 = pout_w[k*256 + u]; w1 = pout_w[(k+1)*256 + u];
                dh = d_Wpout_h; dl = d_Wpout_l; break;
            }
        } else if (w < 327680) {
            int idx = w - 196608;
            int u = idx >> 7, k2 = idx & 127;
            int k = k2 * 2;
            oidx = (size_t)u * 128 + k2;
            w0 = ln3_g[k] * ff1_w[k*1024 + u]; w1 = ln3_g[k+1] * ff1_w[(k+1)*1024 + u];
            dh = d_Wff1_h; dl = d_Wff1_l;
        } else {
            int idx = w - 327680;
            int u = idx >> 9, k2 = idx & 511;
            int k = k2 * 2;
            oidx = (size_t)u * 512 + k2;
            w0 = ff2_w[k*256 + u]; w1 = ff2_w[(k+1)*256 + u];
            dh = d_Wff2_h; dl = d_Wff2_l;
        }
        uint hi, lo; split_pair(w0, w1, hi, lo);
        dh[oidx] = hi; dl[oidx] = lo;
    } else if (blk < 5248) {
        int rel = blk - 1792;
        const float* s; uint *ph, *pl;
        if (rel < 1728) { s = x; ph = d_xhi; pl = d_xlo; }
        else { rel -= 1728; s = ctx; ph = d_cthi; pl = d_ctlo; }
        int i = rel * 256 + tid;
        float2 f = ((const float2*)s)[i];
        uint h, l; split_pair(f.x, f.y, h, l);
        ph[i] = h; pl[i] = l;
    } else {
        int gw = (blk - 5248) * 8 + (tid >> 5);
        int lane = tid & 31;
        float part = 0.f;
        int u;
        if (gw < 256) {
            u = gw;
            for (int k = lane; k < 256; k += 32) {
                float sc = rsqrtf(bn_v[k] + EPS_) * bn_g[k];
                part += (bn_b[k] - bn_m[k] * sc) * pin_w[k*256 + u];
            }
        } else if (gw < 512) {
            u = gw - 256;
            for (int k = lane; k < 256; k += 32) part += ln1_b[k] * q_w[k*256 + u];
        } else if (gw < 768) {
            u = gw - 512;
            for (int k = lane; k < 256; k += 32) part += ln2_b[k] * q_w[k*256 + u];
        } else {
            u = gw - 768;
            for (int k = lane; k < 256; k += 32) part += ln3_b[k] * ff1_w[k*1024 + u];
        }
        #pragma unroll
        for (int o = 16; o > 0; o >>= 1) part += __shfl_xor_sync(0xffffffffu, part, o);
        if (lane == 0) {
            if (gw < 256)      d_bpin[u] = pin_b[u] + part;
            else if (gw < 512) d_bq1[u]  = q_b[u]  + part;
            else if (gw < 768) d_bq2[u]  = q_b[u]  + part;
            else               d_bff1[u] = ff1_b[u] + part;
        }
    }
}

// ---------------- tensor-core batched GEMM: 64x128, 256 thr, ldmatrix -------
struct GOp {
    const uint* Ahi; const uint* Alo;
    const uint* Whi; const uint* Wlo;
    const float* bias; const float* resid;
    float* out; uint* Ohi; uint* Olo;
    int N; int K; int flags; int tileStart;
};
struct GBatch { GOp op[8]; int nops; };

__global__ void __launch_bounds__(256, 2) gemmT(GBatch P)
{
    __shared__ __align__(16) uint As_hi[3][64][12],  As_lo[3][64][12];
    __shared__ __align__(16) uint Ws_hi[3][128][12], Ws_lo[3][128][12];

    int bid = blockIdx.x;
    int sel = 0;
    #pragma unroll
    for (int i = 1; i < 8; i++)
        if (i < P.nops && bid >= P.op[i].tileStart) sel = i;
    GOp g = P.op[sel];

    int local = bid - g.tileStart;
    int ntn = g.N >> 7;
    int mt = local / ntn;
    int nt = local - mt * ntn;
    int m0 = mt * 64, n0 = nt * 128;
    int tid = threadIdx.x;
    int warp = tid >> 5, lane = tid & 31;
    int gq = lane >> 2, t = lane & 3;
    int rw = warp & 3;
    int ch = warp >> 2;
    int K2 = g.K >> 1;

    int lrow = lane & 7, lm = lane >> 3;

    float acc[8][4];
    #pragma unroll
    for (int j = 0; j < 8; j++)
        #pragma unroll
        for (int i = 0; i < 4; i++) acc[j][i] = 0.f;

    int arow = tid >> 1;
    int ahf  = (tid & 1) * 4;
    int wrow = tid >> 1;
    int whf  = (tid & 1) * 4;
    const size_t abase = (size_t)(m0 + arow) * K2 + ahf;
    const size_t wbase = (size_t)(n0 + wrow) * K2 + whf;

    int nc = K2 >> 3;

    #pragma unroll
    for (int s = 0; s < 2; s++) {
        size_t off = (size_t)s * 8;
        if (tid < 128) {
            cp16(sa(&As_hi[s][arow][ahf]), g.Ahi + abase + off);
            cp16(sa(&As_lo[s][arow][ahf]), g.Alo + abase + off);
        }
        cp16(sa(&Ws_hi[s][wrow][whf]), g.Whi + wbase + off);
        cp16(sa(&Ws_lo[s][wrow][whf]), g.Wlo + wbase + off);
        CP_COMMIT();
    }

    // ldmatrix lane offsets
    int a_r = (rw << 4) + ((lm & 1) << 3) + lrow;   // rs + (lm&1)*8 + lrow
    int a_w = (lm >> 1) << 2;                        // (lm>>1)*4
    int b_rbase = (ch << 6) + ((lm >> 1) << 3) + lrow;
    int b_w = (lm & 1) << 2;

    for (int c = 0; c < nc; c++) {
        CP_WAIT1();
        __syncthreads();
        int pc = c + 2;
        if (pc < nc) {
            int nb = pc % 3;
            size_t off = (size_t)pc * 8;
            if (tid < 128) {
                cp16(sa(&As_hi[nb][arow][ahf]), g.Ahi + abase + off);
                cp16(sa(&As_lo[nb][arow][ahf]), g.Alo + abase + off);
            }
            cp16(sa(&Ws_hi[nb][wrow][whf]), g.Whi + wbase + off);
            cp16(sa(&Ws_lo[nb][wrow][whf]), g.Wlo + wbase + off);
        }
        CP_COMMIT();

        int bb = c % 3;
        uint a0h, a1h, a2h, a3h, a0l, a1l, a2l, a3l;
        ldsm4(a0h, a1h, a2h, a3h, sa(&As_hi[bb][a_r][a_w]));
        ldsm4(a0l, a1l, a2l, a3l, sa(&As_lo[bb][a_r][a_w]));

        #pragma unroll
        for (int jp = 0; jp < 4; jp++) {
            uint bh0, bh1, bh2, bh3, bl0, bl1, bl2, bl3;
            ldsm4(bh0, bh1, bh2, bh3, sa(&Ws_hi[bb][b_rbase + jp*16][b_w]));
            ldsm4(bl0, bl1, bl2, bl3, sa(&Ws_lo[bb][b_rbase + jp*16][b_w]));
            mma_bf16(acc[jp*2  ], a0h, a1h, a2h, a3h, bh0, bh1);
            mma_bf16(acc[jp*2  ], a0h, a1h, a2h, a3h, bl0, bl1);
            mma_bf16(acc[jp*2  ], a0l, a1l, a2l, a3l, bh0, bh1);
            mma_bf16(acc[jp*2+1], a0h, a1h, a2h, a3h, bh2, bh3);
            mma_bf16(acc[jp*2+1], a0h, a1h, a2h, a3h, bl2, bl3);
            mma_bf16(acc[jp*2+1], a0l, a1l, a2l, a3l, bh2, bh3);
        }
    }

    int K2o = g.N >> 1;
    int r0 = m0 + rw*16 + gq;
    int r1 = r0 + 8;
    #pragma unroll
    for (int j = 0; j < 8; j++) {
        int c0 = n0 + ch*64 + j*8 + 2*t;
        float b0 = g.bias[c0], b1 = g.bias[c0+1];
        float v00 = acc[j][0] + b0, v01 = acc[j][1] + b1;
        float v10 = acc[j][2] + b0, v11 = acc[j][3] + b1;
        if (g.flags & FRELU) {
            v00 = fmaxf(v00, 0.f); v01 = fmaxf(v01, 0.f);
            v10 = fmaxf(v10, 0.f); v11 = fmaxf(v11, 0.f);
        }
        if (g.flags & FRESID) {
            float2 ra = *(const float2*)&g.resid[(size_t)r0*g.N + c0];
            float2 rb = *(const float2*)&g.resid[(size_t)r1*g.N + c0];
            v00 += ra.x; v01 += ra.y; v10 += rb.x; v11 += rb.y;
        }
        if (g.flags & FOUT) {
            *(float2*)&g.out[(size_t)r0*g.N + c0] = make_float2(v00, v01);
            *(float2*)&g.out[(size_t)r1*g.N + c0] = make_float2(v10, v11);
        }
        if (g.flags & FPLANES) {
            uint h, l;
            split_pair(v00, v01, h, l);
            g.Ohi[(size_t)r0*K2o + (c0>>1)] = h; g.Olo[(size_t)r0*K2o + (c0>>1)] = l;
            split_pair(v10, v11, h, l);
            g.Ohi[(size_t)r1*K2o + (c0>>1)] = h; g.Olo[(size_t)r1*K2o + (c0>>1)] = l;
        }
    }
}

// ---------------- LayerNorm -> planes ----------------------------------------
__global__ void __launch_bounds__(256) lnorm_kernel(const float* __restrict__ h,
                                                    uint* __restrict__ nhi,
                                                    uint* __restrict__ nlo)
{
    int row = blockIdx.x;
    int tid = threadIdx.x;
    float v = h[(size_t)row * 256 + tid];
    __shared__ float red[8];
    float s = v;
    #pragma unroll
    for (int o = 16; o > 0; o >>= 1) s += __shfl_xor_sync(0xffffffffu, s, o);
    if ((tid & 31) == 0) red[tid >> 5] = s;
    __syncthreads();
    float tot = 0.f;
    #pragma unroll
    for (int i = 0; i < 8; i++) tot += red[i];
    float mu = tot * (1.f / 256.f);
    float d = v - mu;
    float s2 = d * d;
    #pragma unroll
    for (int o = 16; o > 0; o >>= 1) s2 += __shfl_xor_sync(0xffffffffu, s2, o);
    __syncthreads();
    if ((tid & 31) == 0) red[tid >> 5] = s2;
    __syncthreads();
    float tot2 = 0.f;
    #pragma unroll
    for (int i = 0; i < 8; i++) tot2 += red[i];
    float var = tot2 * (1.f / 256.f);
    float o = d * rsqrtf(var + EPS_);
    float pn = __shfl_xor_sync(0xffffffffu, o, 1);
    if (!(tid & 1)) {
        uint hi, lo; split_pair(o, pn, hi, lo);
        nhi[(size_t)row * 128 + (tid >> 1)] = hi;
        nlo[(size_t)row * 128 + (tid >> 1)] = lo;
    }
}

// ---------------- V transpose into packed key-pair planes -------------------
__global__ void __launch_bounds__(128) vplanes_T(
    const float* __restrict__ V1, const float* __restrict__ V2,
    uint* __restrict__ vthi, uint* __restrict__ vtlo)
{
    __shared__ float Vs[64][33];
    int tid = threadIdx.x;
    int kt = blockIdx.x;
    int head = blockIdx.y;
    int br = blockIdx.z >> 1, b = blockIdx.z & 1;
    const float* V = br ? V2 : V1;
    #pragma unroll
    for (int i = 0; i < 4; i++) {
        int idx = tid + i * 128;
        int key = idx >> 3, f4 = (idx & 7) * 4;
        const float* p = &V[(size_t)(b * L_ + kt * 64 + key) * 256 + head * 32 + f4];
        float4 t4 = *(const float4*)p;
        Vs[key][f4] = t4.x; Vs[key][f4+1] = t4.y;
        Vs[key][f4+2] = t4.z; Vs[key][f4+3] = t4.w;
    }
    __syncthreads();
    int g = (br * 2 + b) * 8 + head;
    #pragma unroll
    for (int i = 0; i < 8; i++) {
        int widx = tid + i * 128;
        int d = widx >> 5, kp = widx & 31;
        uint hi, lo;
        split_pair(Vs[2*kp][d], Vs[2*kp+1][d], hi, lo);
        size_t o = ((size_t)g * 32 + d) * 864 + kt * 32 + kp;
        vthi[o] = hi; vtlo[o] = lo;
    }
}

// ---------------- tensor-core flash attention (ldmatrix) --------------------
__global__ void __launch_bounds__(128) attn_mma(
    const uint* __restrict__ Q1hi, const uint* __restrict__ Q1lo,
    const uint* __restrict__ K1hi, const uint* __restrict__ K1lo,
    const uint* __restrict__ Q2hi, const uint* __restrict__ Q2lo,
    const uint* __restrict__ K2hi, const uint* __restrict__ K2lo,
    const uint* __restrict__ VThi, const uint* __restrict__ VTlo,
    float* __restrict__ O1, float* __restrict__ O2)
{
    __shared__ __align__(16) uint Khi[2][64][20], Klo[2][64][20];
    __shared__ __align__(16) uint Vhi[2][32][36], Vlo[2][32][36];

    int tid = threadIdx.x, warp = tid >> 5, lane = tid & 31;
    int gq = lane >> 2, t = lane & 3;
    int lrow = lane & 7, lm = lane >> 3;
    int qt = blockIdx.x, head = blockIdx.y;
    int br = blockIdx.z >> 1, b = blockIdx.z & 1;
    const uint* Qhi = br ? Q2hi : Q1hi;
    const uint* Qlo = br ? Q2lo : Q1lo;
    const uint* KhG = br ? K2hi : K1hi;
    const uint* KlG = br ? K2lo : K1lo;
    float* Ob = br ? O2 : O1;
    const float scale2 = 0.0625f * 1.44269504089f;

    int vg = (br * 2 + b) * 8 + head;

    int fkey = tid >> 1;
    int fkw  = (tid & 1) * 8;
    int fd   = tid >> 2;
    int fvw  = (tid & 3) * 8;
    const size_t kbase = (size_t)(b * L_ + fkey) * 128 + head * 16 + fkw;
    const size_t vbase = ((size_t)vg * 32 + fd) * 864 + fvw;

    {
        cp16(sa(&Khi[0][fkey][fkw]),   KhG + kbase);
        cp16(sa(&Khi[0][fkey][fkw+4]), KhG + kbase + 4);
        cp16(sa(&Klo[0][fkey][fkw]),   KlG + kbase);
        cp16(sa(&Klo[0][fkey][fkw+4]), KlG + kbase + 4);
        cp16(sa(&Vhi[0][fd][fvw]),     VThi + vbase);
        cp16(sa(&Vhi[0][fd][fvw+4]),   VThi + vbase + 4);
        cp16(sa(&Vlo[0][fd][fvw]),     VTlo + vbase);
        cp16(sa(&Vlo[0][fd][fvw+4]),   VTlo + vbase + 4);
        CP_COMMIT();
    }

    int r0 = qt * 64 + warp * 16 + gq;
    int r1 = r0 + 8;

    uint qh[2][4], ql[2][4];
    {
        size_t q0 = (size_t)(b * L_ + r0) * 128 + head * 16;
        size_t q1 = (size_t)(b * L_ + r1) * 128 + head * 16;
        #pragma unroll
        for (int ks = 0; ks < 2; ks++) {
            qh[ks][0] = Qhi[q0 + ks*8 + t];     qh[ks][1] = Qhi[q1 + ks*8 + t];
            qh[ks][2] = Qhi[q0 + ks*8 + t + 4]; qh[ks][3] = Qhi[q1 + ks*8 + t + 4];
            ql[ks][0] = Qlo[q0 + ks*8 + t];     ql[ks][1] = Qlo[q1 + ks*8 + t];
            ql[ks][2] = Qlo[q0 + ks*8 + t + 4]; ql[ks][3] = Qlo[q1 + ks*8 + t + 4];
        }
    }

    float Oacc[4][4];
    #pragma unroll
    for (int j = 0; j < 4; j++)
        #pragma unroll
        for (int i = 0; i < 4; i++) Oacc[j][i] = 0.f;
    float m0r = -1e30f, m1r = -1e30f, l0r = 0.f, l1r = 0.f;

    int klw = lm << 2;          // K ldmatrix word offset (0..12)

    for (int kt = 0; kt < NKT; kt++) {
        CP_WAIT0();
        __syncthreads();
        if (kt + 1 < NKT) {
            int nb = (kt + 1) & 1;
            size_t ko = kbase + (size_t)(kt + 1) * 64 * 128;
            size_t vo = vbase + (size_t)(kt + 1) * 32;
            cp16(sa(&Khi[nb][fkey][fkw]),   KhG + ko);
            cp16(sa(&Khi[nb][fkey][fkw+4]), KhG + ko + 4);
            cp16(sa(&Klo[nb][fkey][fkw]),   KlG + ko);
            cp16(sa(&Klo[nb][fkey][fkw+4]), KlG + ko + 4);
            cp16(sa(&Vhi[nb][fd][fvw]),     VThi + vo);
            cp16(sa(&Vhi[nb][fd][fvw+4]),   VThi + vo + 4);
            cp16(sa(&Vlo[nb][fd][fvw]),     VTlo + vo);
            cp16(sa(&Vlo[nb][fd][fvw+4]),   VTlo + vo + 4);
            CP_COMMIT();
        }
        int bb = kt & 1;

        float s[8][4];
        #pragma unroll
        for (int j = 0; j < 8; j++) {
            s[j][0] = s[j][1] = s[j][2] = s[j][3] = 0.f;
            uint kh0, kh1, kh2, kh3, kl0, kl1, kl2, kl3;
            ldsm4(kh0, kh1, kh2, kh3, sa(&Khi[bb][j*8 + lrow][klw]));
            ldsm4(kl0, kl1, kl2, kl3, sa(&Klo[bb][j*8 + lrow][klw]));
            mma_bf16(s[j], qh[0][0], qh[0][1], qh[0][2], qh[0][3], kh0, kh1);
            mma_bf16(s[j], qh[0][0], qh[0][1], qh[0][2], qh[0][3], kl0, kl1);
            mma_bf16(s[j], ql[0][0], ql[0][1], ql[0][2], ql[0][3], kh0, kh1);
            mma_bf16(s[j], qh[1][0], qh[1][1], qh[1][2], qh[1][3], kh2, kh3);
            mma_bf16(s[j], qh[1][0], qh[1][1], qh[1][2], qh[1][3], kl2, kl3);
            mma_bf16(s[j], ql[1][0], ql[1][1], ql[1][2], ql[1][3], kh2, kh3);
            s[j][0] *= scale2; s[j][1] *= scale2;
            s[j][2] *= scale2; s[j][3] *= scale2;
        }

        float mx0 = -1e30f, mx1 = -1e30f;
        #pragma unroll
        for (int j = 0; j < 8; j++) {
            mx0 = fmaxf(mx0, fmaxf(s[j][0], s[j][1]));
            mx1 = fmaxf(mx1, fmaxf(s[j][2], s[j][3]));
        }
        mx0 = fmaxf(mx0, __shfl_xor_sync(0xffffffffu, mx0, 1));
        mx0 = fmaxf(mx0, __shfl_xor_sync(0xffffffffu, mx0, 2));
        mx1 = fmaxf(mx1, __shfl_xor_sync(0xffffffffu, mx1, 1));
        mx1 = fmaxf(mx1, __shfl_xor_sync(0xffffffffu, mx1, 2));
        float nm0 = fmaxf(m0r, mx0), nm1 = fmaxf(m1r, mx1);
        float c0 = ex2(m0r - nm0), c1 = ex2(m1r - nm1);

        float ls0 = 0.f, ls1 = 0.f;
        #pragma unroll
        for (int j = 0; j < 8; j++) {
            s[j][0] = ex2(s[j][0] - nm0); ls0 += s[j][0];
            s[j][1] = ex2(s[j][1] - nm0); ls0 += s[j][1];
            s[j][2] = ex2(s[j][2] - nm1); ls1 += s[j][2];
            s[j][3] = ex2(s[j][3] - nm1); ls1 += s[j][3];
        }
        ls0 += __shfl_xor_sync(0xffffffffu, ls0, 1);
        ls0 += __shfl_xor_sync(0xffffffffu, ls0, 2);
        ls1 += __shfl_xor_sync(0xffffffffu, ls1, 1);
        ls1 += __shfl_xor_sync(0xffffffffu, ls1, 2);
        l0r = l0r * c0 + ls0;
        l1r = l1r * c1 + ls1;
        m0r = nm0; m1r = nm1;

        #pragma unroll
        for (int jn = 0; jn < 4; jn++) {
            Oacc[jn][0] *= c0; Oacc[jn][1] *= c0;
            Oacc[jn][2] *= c1; Oacc[jn][3] *= c1;
        }

        uint ph[4][4], pl[4][4];
        #pragma unroll
        for (int ks = 0; ks < 4; ks++) {
            split_pair(s[2*ks  ][0], s[2*ks  ][1], ph[ks][0], pl[ks][0]);
            split_pair(s[2*ks  ][2], s[2*ks  ][3], ph[ks][1], pl[ks][1]);
            split_pair(s[2*ks+1][0], s[2*ks+1][1], ph[ks][2], pl[ks][2]);
            split_pair(s[2*ks+1][2], s[2*ks+1][3], ph[ks][3], pl[ks][3]);
        }

        #pragma unroll
        for (int jn = 0; jn < 4; jn++) {
            #pragma unroll
            for (int h2 = 0; h2 < 2; h2++) {
                uint vh0, vh1, vh2, vh3, vl0, vl1, vl2, vl3;
                ldsm4(vh0, vh1, vh2, vh3, sa(&Vhi[bb][jn*8 + lrow][(h2<<4) + klw]));
                ldsm4(vl0, vl1, vl2, vl3, sa(&Vlo[bb][jn*8 + lrow][(h2<<4) + klw]));
                int ka = 2*h2, kb2 = 2*h2 + 1;
                mma_bf16(Oacc[jn], ph[ka][0], ph[ka][1], ph[ka][2], ph[ka][3], vh0, vh1);
                mma_bf16(Oacc[jn], ph[ka][0], ph[ka][1], ph[ka][2], ph[ka][3], vl0, vl1);
                mma_bf16(Oacc[jn], pl[ka][0], pl[ka][1], pl[ka][2], pl[ka][3], vh0, vh1);
                mma_bf16(Oacc[jn], ph[kb2][0], ph[kb2][1], ph[kb2][2], ph[kb2][3], vh2, vh3);
                mma_bf16(Oacc[jn], ph[kb2][0], ph[kb2][1], ph[kb2][2], ph[kb2][3], vl2, vl3);
                mma_bf16(Oacc[jn], pl[kb2][0], pl[kb2][1], pl[kb2][2], pl[kb2][3], vh2, vh3);
            }
        }
    }

    float inv0 = 1.f / l0r, inv1 = 1.f / l1r;
    #pragma unroll
    for (int jn = 0; jn < 4; jn++) {
        int col = head * 32 + jn * 8 + 2 * t;
        *(float2*)&Ob[(size_t)(b * L_ + r0) * 256 + col] =
            make_float2(Oacc[jn][0] * inv0, Oacc[jn][1] * inv0);
        *(float2*)&Ob[(size_t)(b * L_ + r1) * 256 + col] =
            make_float2(Oacc[jn][2] * inv1, Oacc[jn][3] * inv1);
    }
}

// ---------------- combine ------------------------------------------------------
__global__ void __launch_bounds__(256) combine_kernel(
    const float* __restrict__ O1, const float* __restrict__ O2,
    const float* __restrict__ h, const float* __restrict__ ffo,
    float* __restrict__ acc, uint* __restrict__ ahi, uint* __restrict__ alo)
{
    int tok = blockIdx.x;
    int u = threadIdx.x;
    size_t i = (size_t)tok * 256 + u;
    float o = h[i] + ffo[i] + O1[i] + O2[i];
    acc[i] = o;
    float pn = __shfl_xor_sync(0xffffffffu, o, 1);
    if (!(u & 1)) {
        uint hi, lo; split_pair(o, pn, hi, lo);
        ahi[(size_t)tok * 128 + (u >> 1)] = hi;
        alo[(size_t)tok * 128 + (u >> 1)] = lo;
    }
}

// ---------------- launch --------------------------------------------------------
extern "C" void kernel_launch(void* const* d_in, const int* in_sizes, int n_in,
                              void* d_out, int out_size)
{
    const float* x       = (const float*)d_in[0];
    const float* context = (const float*)d_in[1];
    const float* bn_g = (const float*)d_in[2];
    const float* bn_b = (const float*)d_in[3];
    const float* bn_m = (const float*)d_in[4];
    const float* bn_v = (const float*)d_in[5];
    const float* ln1_g = (const float*)d_in[6];
    const float* ln1_b = (const float*)d_in[7];
    const float* ln2_g = (const float*)d_in[8];
    const float* ln2_b = (const float*)d_in[9];
    const float* ln3_g = (const float*)d_in[10];
    const float* ln3_b = (const float*)d_in[11];
    const float* pin_w = (const float*)d_in[12];
    const float* pin_b = (const float*)d_in[13];
    const float* q_w   = (const float*)d_in[14];
    const float* q_b   = (const float*)d_in[15];
    const float* k_w   = (const float*)d_in[16];
    const float* k_b   = (const float*)d_in[17];
    const float* v_w   = (const float*)d_in[18];
    const float* v_b   = (const float*)d_in[19];
    const float* ff1_w = (const float*)d_in[20];
    const float* ff1_b = (const float*)d_in[21];
    const float* ff2_w = (const float*)d_in[22];
    const float* ff2_b = (const float*)d_in[23];
    const float* pout_w = (const float*)d_in[24];
    const float* pout_b = (const float*)d_in[25];
    float* out = (float*)d_out;

    float *p_h, *p_v1, *p_v2, *p_ffo, *p_acc, *p_O1, *p_O2;
    uint *p_xhi, *p_xlo, *p_cthi, *p_ctlo, *p_hhi, *p_hlo, *p_nhi, *p_nlo;
    uint *p_f1hi, *p_f1lo, *p_ahi, *p_alo;
    uint *p_q1hi, *p_q1lo, *p_k1hi, *p_k1lo, *p_q2hi, *p_q2lo, *p_k2hi, *p_k2lo;
    uint *p_vthi, *p_vtlo;
    uint *w_pin_h, *w_pin_l, *w_q1_h, *w_q1_l, *w_q2_h, *w_q2_l;
    uint *w_k_h, *w_k_l, *w_v_h, *w_v_l, *w_po_h, *w_po_l;
    uint *w_f1_h, *w_f1_l, *w_f2_h, *w_f2_l;
    float *p_bpin, *p_bq1, *p_bq2, *p_bff1;

    cudaGetSymbolAddress((void**)&p_h,    d_h);
    cudaGetSymbolAddress((void**)&p_v1,   d_v1);
    cudaGetSymbolAddress((void**)&p_v2,   d_v2);
    cudaGetSymbolAddress((void**)&p_ffo,  d_ffo);
    cudaGetSymbolAddress((void**)&p_acc,  d_acc);
    cudaGetSymbolAddress((void**)&p_O1,   d_O1);
    cudaGetSymbolAddress((void**)&p_O2,   d_O2);
    cudaGetSymbolAddress((void**)&p_xhi,  d_xhi);
    cudaGetSymbolAddress((void**)&p_xlo,  d_xlo);
    cudaGetSymbolAddress((void**)&p_cthi, d_cthi);
    cudaGetSymbolAddress((void**)&p_ctlo, d_ctlo);
    cudaGetSymbolAddress((void**)&p_hhi,  d_hhi);
    cudaGetSymbolAddress((void**)&p_hlo,  d_hlo);
    cudaGetSymbolAddress((void**)&p_nhi,  d_nhi);
    cudaGetSymbolAddress((void**)&p_nlo,  d_nlo);
    cudaGetSymbolAddress((void**)&p_f1hi, d_f1hi);
    cudaGetSymbolAddress((void**)&p_f1lo, d_f1lo);
    cudaGetSymbolAddress((void**)&p_ahi,  d_ahi);
    cudaGetSymbolAddress((void**)&p_alo,  d_alo);
    cudaGetSymbolAddress((void**)&p_q1hi, d_q1hi);
    cudaGetSymbolAddress((void**)&p_q1lo, d_q1lo);
    cudaGetSymbolAddress((void**)&p_k1hi, d_k1hi);
    cudaGetSymbolAddress((void**)&p_k1lo, d_k1lo);
    cudaGetSymbolAddress((void**)&p_q2hi, d_q2hi);
    cudaGetSymbolAddress((void**)&p_q2lo, d_q2lo);
    cudaGetSymbolAddress((void**)&p_k2hi, d_k2hi);
    cudaGetSymbolAddress((void**)&p_k2lo, d_k2lo);
    cudaGetSymbolAddress((void**)&p_vthi, d_vthi);
    cudaGetSymbolAddress((void**)&p_vtlo, d_vtlo);
    cudaGetSymbolAddress((void**)&w_pin_h, d_Wpin_h);
    cudaGetSymbolAddress((void**)&w_pin_l, d_Wpin_l);
    cudaGetSymbolAddress((void**)&w_q1_h,  d_Wq1_h);
    cudaGetSymbolAddress((void**)&w_q1_l,  d_Wq1_l);
    cudaGetSymbolAddress((void**)&w_q2_h,  d_Wq2_h);
    cudaGetSymbolAddress((void**)&w_q2_l,  d_Wq2_l);
    cudaGetSymbolAddress((void**)&w_k_h,   d_Wk_h);
    cudaGetSymbolAddress((void**)&w_k_l,   d_Wk_l);
    cudaGetSymbolAddress((void**)&w_v_h,   d_Wv_h);
    cudaGetSymbolAddress((void**)&w_v_l,   d_Wv_l);
    cudaGetSymbolAddress((void**)&w_po_h,  d_Wpout_h);
    cudaGetSymbolAddress((void**)&w_po_l,  d_Wpout_l);
    cudaGetSymbolAddress((void**)&w_f1_h,  d_Wff1_h);
    cudaGetSymbolAddress((void**)&w_f1_l,  d_Wff1_l);
    cudaGetSymbolAddress((void**)&w_f2_h,  d_Wff2_h);
    cudaGetSymbolAddress((void**)&w_f2_l,  d_Wff2_l);
    cudaGetSymbolAddress((void**)&p_bpin,  d_bpin);
    cudaGetSymbolAddress((void**)&p_bq1,   d_bq1);
    cudaGetSymbolAddress((void**)&p_bq2,   d_bq2);
    cudaGetSymbolAddress((void**)&p_bff1,  d_bff1);

    // 1. all prep
    prep_all<<<5472, 256>>>(x, context, bn_g, bn_b, bn_m, bn_v,
                            ln1_g, ln1_b, ln2_g, ln2_b, ln3_g, ln3_b,
                            pin_w, pin_b, q_w, q_b, k_w, v_w,
                            ff1_w, ff1_b, ff2_w, pout_w);

    auto mkop = [](const uint* Ahi, const uint* Alo, const uint* Whi, const uint* Wlo,
                   const float* bias, const float* resid, float* o,
                   uint* Ohi, uint* Olo, int N, int K, int flags, int start) {
        GOp g; g.Ahi = Ahi; g.Alo = Alo; g.Whi = Whi; g.Wlo = Wlo;
        g.bias = bias; g.resid = resid; g.out = o; g.Ohi = Ohi; g.Olo = Olo;
        g.N = N; g.K = K; g.flags = flags; g.tileStart = start;
        return g;
    };
    const int RT = NTOK / 64;
    const int T256 = RT * 2;

    // 2. batch A: pin + k2 + v2
    {
        GBatch P = {};
        P.op[0] = mkop(p_xhi, p_xlo, w_pin_h, w_pin_l, p_bpin, nullptr,
                       p_h, p_hhi, p_hlo, 256, 256, FOUT | FRELU | FPLANES, 0);
        P.op[1] = mkop(p_cthi, p_ctlo, w_k_h, w_k_l, k_b, nullptr,
                       nullptr, p_k2hi, p_k2lo, 256, 256, FPLANES, T256);
        P.op[2] = mkop(p_cthi, p_ctlo, w_v_h, w_v_l, v_b, nullptr,
                       p_v2, nullptr, nullptr, 256, 256, FOUT, T256*2);
        P.nops = 3;
        gemmT<<<T256*3, 256>>>(P);
    }

    // 3. hhat planes
    lnorm_kernel<<<NTOK, 256>>>(p_h, p_nhi, p_nlo);

    // 4. batch B: q1, k1, v1, q2, ff1
    {
        GBatch P = {};
        P.op[0] = mkop(p_nhi, p_nlo, w_q1_h, w_q1_l, p_bq1, nullptr,
                       nullptr, p_q1hi, p_q1lo, 256, 256, FPLANES, 0);
        P.op[1] = mkop(p_hhi, p_hlo, w_k_h, w_k_l, k_b, nullptr,
                       nullptr, p_k1hi, p_k1lo, 256, 256, FPLANES, T256);
        P.op[2] = mkop(p_hhi, p_hlo, w_v_h, w_v_l, v_b, nullptr,
                       p_v1, nullptr, nullptr, 256, 256, FOUT, T256*2);
        P.op[3] = mkop(p_nhi, p_nlo, w_q2_h, w_q2_l, p_bq2, nullptr,
                       nullptr, p_q2hi, p_q2lo, 256, 256, FPLANES, T256*3);
        P.op[4] = mkop(p_nhi, p_nlo, w_f1_h, w_f1_l, p_bff1, nullptr,
                       nullptr, p_f1hi, p_f1lo, 1024, 256, FRELU | FPLANES, T256*4);
        P.nops = 5;
        gemmT<<<T256*4 + RT*8, 256>>>(P);
    }

    // 5. V transpose planes
    {
        dim3 gv(NKT, H_, 4);
        vplanes_T<<<gv, 128>>>(p_v1, p_v2, p_vthi, p_vtlo);
    }

    // 6. attention
    {
        dim3 ga(NKT, H_, 4);
        attn_mma<<<ga, 128>>>(p_q1hi, p_q1lo, p_k1hi, p_k1lo,
                              p_q2hi, p_q2lo, p_k2hi, p_k2lo,
                              p_vthi, p_vtlo, p_O1, p_O2);
    }

    // 7. ff2
    {
        GBatch P = {};
        P.op[0] = mkop(p_f1hi, p_f1lo, w_f2_h, w_f2_l, ff2_b, nullptr,
                       p_ffo, nullptr, nullptr, 256, 1024, FOUT, 0);
        P.nops = 1;
        gemmT<<<T256, 256>>>(P);
    }

    // 8. combine
    combine_kernel<<<NTOK, 256>>>(p_O1, p_O2, p_h, p_ffo, p_acc, p_ahi, p_alo);

    // 9. out = relu(acc @ pout + b) + x
    {
        GBatch P = {};
        P.op[0] = mkop(p_ahi, p_alo, w_po_h, w_po_l, pout_b, x,
                       out, nullptr, nullptr, 256, 256, FOUT | FRELU | FRESID, 0);
        P.nops = 1;
        gemmT<<<T256, 256>>>(P);
    }
}

// round 11
// speedup vs baseline: 1.1358x; 1.0994x over previous
#include <cuda_runtime.h>
#include <math.h>

typedef unsigned long long ull;
typedef unsigned int uint;

#define B_    2
#define L_    1728
#define NTOK  3456
#define C_    256
#define U_    256
#define H_    8
#define HD    32
#define FF_   1024
#define EPS_  1e-3f
#define NKT   27

#define FRELU   1
#define FRESID  2
#define FPLANES 4
#define FOUT    8

// ---------------- cp.async helpers ------------------------------------------
__device__ __forceinline__ void cp16(uint saddr, const void* gptr) {
    asm volatile("cp.async.cg.shared.global [%0], [%1], 16;" :: "r"(saddr), "l"(gptr));
}
__device__ __forceinline__ uint sa(const void* p) {
    return (uint)__cvta_generic_to_shared(p);
}
#define CP_COMMIT() asm volatile("cp.async.commit_group;")
#define CP_WAIT0()  asm volatile("cp.async.wait_group 0;")
#define CP_WAIT1()  asm volatile("cp.async.wait_group 1;")

// ---------------- ldmatrix ----------------------------------------------------
__device__ __forceinline__ void ldsm4(uint& r0, uint& r1, uint& r2, uint& r3, uint saddr) {
    asm volatile("ldmatrix.sync.aligned.m8n8.x4.shared.b16 {%0,%1,%2,%3}, [%4];"
                 : "=r"(r0), "=r"(r1), "=r"(r2), "=r"(r3) : "r"(saddr));
}

// ---------------- fast exp2 --------------------------------------------------
__device__ __forceinline__ float ex2(float x) {
    float y; asm("ex2.approx.f32 %0,%1;" : "=f"(y) : "f"(x)); return y;
}

// ---------------- bf16 split helpers ---------------------------------------
__device__ __forceinline__ uint bf16_of(float f) {
    unsigned short u; asm("cvt.rn.bf16.f32 %0,%1;" : "=h"(u) : "f"(f));
    return (uint)u;
}
__device__ __forceinline__ void split_pair(float f0, float f1, uint& hi, uint& lo) {
    uint h0 = bf16_of(f0), h1 = bf16_of(f1);
    hi = h0 | (h1 << 16);
    float r0 = f0 - __uint_as_float(h0 << 16);
    float r1 = f1 - __uint_as_float(h1 << 16);
    lo = bf16_of(r0) | (bf16_of(r1) << 16);
}

// ---------------- mma m16n8k16 bf16 -----------------------------------------
__device__ __forceinline__ void mma_bf16(float* c, uint a0, uint a1, uint a2, uint a3,
                                         uint b0, uint b1) {
    asm volatile("mma.sync.aligned.m16n8k16.row.col.f32.bf16.bf16.f32 "
                 "{%0,%1,%2,%3},{%4,%5,%6,%7},{%8,%9},{%0,%1,%2,%3};"
                 : "+f"(c[0]), "+f"(c[1]), "+f"(c[2]), "+f"(c[3])
                 : "r"(a0), "r"(a1), "r"(a2), "r"(a3), "r"(b0), "r"(b1));
}

// ---------------- scratch ---------------------------------------------------
__device__ float d_h   [NTOK*U_];
__device__ float d_v1  [NTOK*U_];
__device__ float d_v2  [NTOK*U_];
__device__ float d_ffo [NTOK*U_];
__device__ float d_acc [NTOK*U_];
__device__ float d_O1  [NTOK*U_];
__device__ float d_O2  [NTOK*U_];

__device__ uint d_xhi [NTOK*128], d_xlo [NTOK*128];
__device__ uint d_cthi[NTOK*128], d_ctlo[NTOK*128];
__device__ uint d_hhi [NTOK*128], d_hlo [NTOK*128];
__device__ uint d_nhi [NTOK*128], d_nlo [NTOK*128];
__device__ uint d_f1hi[NTOK*512], d_f1lo[NTOK*512];
__device__ uint d_ahi [NTOK*128], d_alo [NTOK*128];
__device__ uint d_q1hi[NTOK*128], d_q1lo[NTOK*128];
__device__ uint d_k1hi[NTOK*128], d_k1lo[NTOK*128];
__device__ uint d_q2hi[NTOK*128], d_q2lo[NTOK*128];
__device__ uint d_k2hi[NTOK*128], d_k2lo[NTOK*128];
__device__ uint d_vthi[32*32*864], d_vtlo[32*32*864];

__device__ uint d_Wpin_h[256*128], d_Wpin_l[256*128];
__device__ uint d_Wq1_h [256*128], d_Wq1_l [256*128];
__device__ uint d_Wq2_h [256*128], d_Wq2_l [256*128];
__device__ uint d_Wk_h  [256*128], d_Wk_l  [256*128];
__device__ uint d_Wv_h  [256*128], d_Wv_l  [256*128];
__device__ uint d_Wpout_h[256*128], d_Wpout_l[256*128];
__device__ uint d_Wff1_h[1024*128], d_Wff1_l[1024*128];
__device__ uint d_Wff2_h[256*512],  d_Wff2_l[256*512];

__device__ float d_bpin[U_], d_bq1[U_], d_bq2[U_], d_bff1[FF_];

// ---------------- prep_all (one launch) --------------------------------------
__global__ void __launch_bounds__(256) prep_all(
    const float* __restrict__ x,    const float* __restrict__ ctx,
    const float* __restrict__ bn_g, const float* __restrict__ bn_b,
    const float* __restrict__ bn_m, const float* __restrict__ bn_v,
    const float* __restrict__ ln1_g, const float* __restrict__ ln1_b,
    const float* __restrict__ ln2_g, const float* __restrict__ ln2_b,
    const float* __restrict__ ln3_g, const float* __restrict__ ln3_b,
    const float* __restrict__ pin_w, const float* __restrict__ pin_b,
    const float* __restrict__ q_w,  const float* __restrict__ q_b,
    const float* __restrict__ k_w,  const float* __restrict__ v_w,
    const float* __restrict__ ff1_w, const float* __restrict__ ff1_b,
    const float* __restrict__ ff2_w, const float* __restrict__ pout_w)
{
    int blk = blockIdx.x;
    int tid = threadIdx.x;

    if (blk < 1792) {
        int w = blk * 256 + tid;
        float w0, w1;
        uint *dh, *dl;
        size_t oidx;
        if (w < 196608) {
            int r = w >> 15;
            int idx = w & 32767;
            int u = idx >> 7, k2 = idx & 127;
            int k = k2 * 2;
            oidx = (size_t)u * 128 + k2;
            switch (r) {
            case 0: {
                float s0 = rsqrtf(bn_v[k] + EPS_) * bn_g[k];
                float s1 = rsqrtf(bn_v[k+1] + EPS_) * bn_g[k+1];
                w0 = s0 * pin_w[k*256 + u]; w1 = s1 * pin_w[(k+1)*256 + u];
                dh = d_Wpin_h; dl = d_Wpin_l; } break;
            case 1:
                w0 = ln1_g[k] * q_w[k*256 + u]; w1 = ln1_g[k+1] * q_w[(k+1)*256 + u];
                dh = d_Wq1_h; dl = d_Wq1_l; break;
            case 2:
                w0 = ln2_g[k] * q_w[k*256 + u]; w1 = ln2_g[k+1] * q_w[(k+1)*256 + u];
                dh = d_Wq2_h; dl = d_Wq2_l; break;
            case 3:
                w0 = k_w[k*256 + u]; w1 = k_w[(k+1)*256 + u];
                dh = d_Wk_h; dl = d_Wk_l; break;
            case 4:
                w0 = v_w[k*256 + u]; w1 = v_w[(k+1)*256 + u];
                dh = d_Wv_h; dl = d_Wv_l; break;
            default:
                w0 = pout_w[k*256 + u]; w1 = pout_w[(k+1)*256 + u];
                dh = d_Wpout_h; dl = d_Wpout_l; break;
            }
        } else if (w < 327680) {
            int idx = w - 196608;
            int u = idx >> 7, k2 = idx & 127;
            int k = k2 * 2;
            oidx = (size_t)u * 128 + k2;
            w0 = ln3_g[k] * ff1_w[k*1024 + u]; w1 = ln3_g[k+1] * ff1_w[(k+1)*1024 + u];
            dh = d_Wff1_h; dl = d_Wff1_l;
        } else {
            int idx = w - 327680;
            int u = idx >> 9, k2 = idx & 511;
            int k = k2 * 2;
            oidx = (size_t)u * 512 + k2;
            w0 = ff2_w[k*256 + u]; w1 = ff2_w[(k+1)*256 + u];
            dh = d_Wff2_h; dl = d_Wff2_l;
        }
        uint hi, lo; split_pair(w0, w1, hi, lo);
        dh[oidx] = hi; dl[oidx] = lo;
    } else if (blk < 5248) {
        int rel = blk - 1792;
        const float* s; uint *ph, *pl;
        if (rel < 1728) { s = x; ph = d_xhi; pl = d_xlo; }
        else { rel -= 1728; s = ctx; ph = d_cthi; pl = d_ctlo; }
        int i = rel * 256 + tid;
        float2 f = ((const float2*)s)[i];
        uint h, l; split_pair(f.x, f.y, h, l);
        ph[i] = h; pl[i] = l;
    } else {
        int gw = (blk - 5248) * 8 + (tid >> 5);
        int lane = tid & 31;
        float part = 0.f;
        int u;
        if (gw < 256) {
            u = gw;
            for (int k = lane; k < 256; k += 32) {
                float sc = rsqrtf(bn_v[k] + EPS_) * bn_g[k];
                part += (bn_b[k] - bn_m[k] * sc) * pin_w[k*256 + u];
            }
        } else if (gw < 512) {
            u = gw - 256;
            for (int k = lane; k < 256; k += 32) part += ln1_b[k] * q_w[k*256 + u];
        } else if (gw < 768) {
            u = gw - 512;
            for (int k = lane; k < 256; k += 32) part += ln2_b[k] * q_w[k*256 + u];
        } else {
            u = gw - 768;
            for (int k = lane; k < 256; k += 32) part += ln3_b[k] * ff1_w[k*1024 + u];
        }
        #pragma unroll
        for (int o = 16; o > 0; o >>= 1) part += __shfl_xor_sync(0xffffffffu, part, o);
        if (lane == 0) {
            if (gw < 256)      d_bpin[u] = pin_b[u] + part;
            else if (gw < 512) d_bq1[u]  = q_b[u]  + part;
            else if (gw < 768) d_bq2[u]  = q_b[u]  + part;
            else               d_bff1[u] = ff1_b[u] + part;
        }
    }
}

// ---------------- tensor-core batched GEMM: 64x128, 256 thr, ldmatrix -------
struct GOp {
    const uint* Ahi; const uint* Alo;
    const uint* Whi; const uint* Wlo;
    const float* bias; const float* resid;
    float* out; uint* Ohi; uint* Olo;
    int N; int K; int flags; int tileStart;
};
struct GBatch { GOp op[8]; int nops; };

__global__ void __launch_bounds__(256, 2) gemmT(GBatch P)
{
    __shared__ __align__(16) uint As_hi[3][64][12],  As_lo[3][64][12];
    __shared__ __align__(16) uint Ws_hi[3][128][12], Ws_lo[3][128][12];

    int bid = blockIdx.x;
    int sel = 0;
    #pragma unroll
    for (int i = 1; i < 8; i++)
        if (i < P.nops && bid >= P.op[i].tileStart) sel = i;
    GOp g = P.op[sel];

    int local = bid - g.tileStart;
    int ntn = g.N >> 7;
    int mt = local / ntn;
    int nt = local - mt * ntn;
    int m0 = mt * 64, n0 = nt * 128;
    int tid = threadIdx.x;
    int warp = tid >> 5, lane = tid & 31;
    int gq = lane >> 2, t = lane & 3;
    int rw = warp & 3;
    int ch = warp >> 2;
    int K2 = g.K >> 1;

    int lrow = lane & 7, lm = lane >> 3;

    float acc[8][4];
    #pragma unroll
    for (int j = 0; j < 8; j++)
        #pragma unroll
        for (int i = 0; i < 4; i++) acc[j][i] = 0.f;

    int arow = tid >> 1;
    int ahf  = (tid & 1) * 4;
    int wrow = tid >> 1;
    int whf  = (tid & 1) * 4;
    const size_t abase = (size_t)(m0 + arow) * K2 + ahf;
    const size_t wbase = (size_t)(n0 + wrow) * K2 + whf;

    int nc = K2 >> 3;

    #pragma unroll
    for (int s = 0; s < 2; s++) {
        size_t off = (size_t)s * 8;
        if (tid < 128) {
            cp16(sa(&As_hi[s][arow][ahf]), g.Ahi + abase + off);
            cp16(sa(&As_lo[s][arow][ahf]), g.Alo + abase + off);
        }
        cp16(sa(&Ws_hi[s][wrow][whf]), g.Whi + wbase + off);
        cp16(sa(&Ws_lo[s][wrow][whf]), g.Wlo + wbase + off);
        CP_COMMIT();
    }

    int a_r = (rw << 4) + ((lm & 1) << 3) + lrow;
    int a_w = (lm >> 1) << 2;
    int b_rbase = (ch << 6) + ((lm >> 1) << 3) + lrow;
    int b_w = (lm & 1) << 2;

    for (int c = 0; c < nc; c++) {
        CP_WAIT1();
        __syncthreads();
        int pc = c + 2;
        if (pc < nc) {
            int nb = pc % 3;
            size_t off = (size_t)pc * 8;
            if (tid < 128) {
                cp16(sa(&As_hi[nb][arow][ahf]), g.Ahi + abase + off);
                cp16(sa(&As_lo[nb][arow][ahf]), g.Alo + abase + off);
            }
            cp16(sa(&Ws_hi[nb][wrow][whf]), g.Whi + wbase + off);
            cp16(sa(&Ws_lo[nb][wrow][whf]), g.Wlo + wbase + off);
        }
        CP_COMMIT();

        int bb = c % 3;
        uint a0h, a1h, a2h, a3h, a0l, a1l, a2l, a3l;
        ldsm4(a0h, a1h, a2h, a3h, sa(&As_hi[bb][a_r][a_w]));
        ldsm4(a0l, a1l, a2l, a3l, sa(&As_lo[bb][a_r][a_w]));

        #pragma unroll
        for (int jp = 0; jp < 4; jp++) {
            uint bh0, bh1, bh2, bh3, bl0, bl1, bl2, bl3;
            ldsm4(bh0, bh1, bh2, bh3, sa(&Ws_hi[bb][b_rbase + jp*16][b_w]));
            ldsm4(bl0, bl1, bl2, bl3, sa(&Ws_lo[bb][b_rbase + jp*16][b_w]));
            mma_bf16(acc[jp*2  ], a0h, a1h, a2h, a3h, bh0, bh1);
            mma_bf16(acc[jp*2  ], a0h, a1h, a2h, a3h, bl0, bl1);
            mma_bf16(acc[jp*2  ], a0l, a1l, a2l, a3l, bh0, bh1);
            mma_bf16(acc[jp*2+1], a0h, a1h, a2h, a3h, bh2, bh3);
            mma_bf16(acc[jp*2+1], a0h, a1h, a2h, a3h, bl2, bl3);
            mma_bf16(acc[jp*2+1], a0l, a1l, a2l, a3l, bh2, bh3);
        }
    }

    int K2o = g.N >> 1;
    int r0 = m0 + rw*16 + gq;
    int r1 = r0 + 8;
    #pragma unroll
    for (int j = 0; j < 8; j++) {
        int c0 = n0 + ch*64 + j*8 + 2*t;
        float b0 = g.bias[c0], b1 = g.bias[c0+1];
        float v00 = acc[j][0] + b0, v01 = acc[j][1] + b1;
        float v10 = acc[j][2] + b0, v11 = acc[j][3] + b1;
        if (g.flags & FRELU) {
            v00 = fmaxf(v00, 0.f); v01 = fmaxf(v01, 0.f);
            v10 = fmaxf(v10, 0.f); v11 = fmaxf(v11, 0.f);
        }
        if (g.flags & FRESID) {
            float2 ra = *(const float2*)&g.resid[(size_t)r0*g.N + c0];
            float2 rb = *(const float2*)&g.resid[(size_t)r1*g.N + c0];
            v00 += ra.x; v01 += ra.y; v10 += rb.x; v11 += rb.y;
        }
        if (g.flags & FOUT) {
            *(float2*)&g.out[(size_t)r0*g.N + c0] = make_float2(v00, v01);
            *(float2*)&g.out[(size_t)r1*g.N + c0] = make_float2(v10, v11);
        }
        if (g.flags & FPLANES) {
            uint h, l;
            split_pair(v00, v01, h, l);
            g.Ohi[(size_t)r0*K2o + (c0>>1)] = h; g.Olo[(size_t)r0*K2o + (c0>>1)] = l;
            split_pair(v10, v11, h, l);
            g.Ohi[(size_t)r1*K2o + (c0>>1)] = h; g.Olo[(size_t)r1*K2o + (c0>>1)] = l;
        }
    }
}

// ---------------- LayerNorm -> planes ----------------------------------------
__global__ void __launch_bounds__(256) lnorm_kernel(const float* __restrict__ h,
                                                    uint* __restrict__ nhi,
                                                    uint* __restrict__ nlo)
{
    int row = blockIdx.x;
    int tid = threadIdx.x;
    float v = h[(size_t)row * 256 + tid];
    __shared__ float red[8];
    float s = v;
    #pragma unroll
    for (int o = 16; o > 0; o >>= 1) s += __shfl_xor_sync(0xffffffffu, s, o);
    if ((tid & 31) == 0) red[tid >> 5] = s;
    __syncthreads();
    float tot = 0.f;
    #pragma unroll
    for (int i = 0; i < 8; i++) tot += red[i];
    float mu = tot * (1.f / 256.f);
    float d = v - mu;
    float s2 = d * d;
    #pragma unroll
    for (int o = 16; o > 0; o >>= 1) s2 += __shfl_xor_sync(0xffffffffu, s2, o);
    __syncthreads();
    if ((tid & 31) == 0) red[tid >> 5] = s2;
    __syncthreads();
    float tot2 = 0.f;
    #pragma unroll
    for (int i = 0; i < 8; i++) tot2 += red[i];
    float var = tot2 * (1.f / 256.f);
    float o = d * rsqrtf(var + EPS_);
    float pn = __shfl_xor_sync(0xffffffffu, o, 1);
    if (!(tid & 1)) {
        uint hi, lo; split_pair(o, pn, hi, lo);
        nhi[(size_t)row * 128 + (tid >> 1)] = hi;
        nlo[(size_t)row * 128 + (tid >> 1)] = lo;
    }
}

// ---------------- V transpose into packed key-pair planes -------------------
__global__ void __launch_bounds__(128) vplanes_T(
    const float* __restrict__ V1, const float* __restrict__ V2,
    uint* __restrict__ vthi, uint* __restrict__ vtlo)
{
    __shared__ float Vs[64][33];
    int tid = threadIdx.x;
    int kt = blockIdx.x;
    int head = blockIdx.y;
    int br = blockIdx.z >> 1, b = blockIdx.z & 1;
    const float* V = br ? V2 : V1;
    #pragma unroll
    for (int i = 0; i < 4; i++) {
        int idx = tid + i * 128;
        int key = idx >> 3, f4 = (idx & 7) * 4;
        const float* p = &V[(size_t)(b * L_ + kt * 64 + key) * 256 + head * 32 + f4];
        float4 t4 = *(const float4*)p;
        Vs[key][f4] = t4.x; Vs[key][f4+1] = t4.y;
        Vs[key][f4+2] = t4.z; Vs[key][f4+3] = t4.w;
    }
    __syncthreads();
    int g = (br * 2 + b) * 8 + head;
    #pragma unroll
    for (int i = 0; i < 8; i++) {
        int widx = tid + i * 128;
        int d = widx >> 5, kp = widx & 31;
        uint hi, lo;
        split_pair(Vs[2*kp][d], Vs[2*kp+1][d], hi, lo);
        size_t o = ((size_t)g * 32 + d) * 864 + kt * 32 + kp;
        vthi[o] = hi; vtlo[o] = lo;
    }
}

// ---------------- tensor-core flash attention (static max, 3-stage) ---------
__global__ void __launch_bounds__(128) attn_mma(
    const uint* __restrict__ Q1hi, const uint* __restrict__ Q1lo,
    const uint* __restrict__ K1hi, const uint* __restrict__ K1lo,
    const uint* __restrict__ Q2hi, const uint* __restrict__ Q2lo,
    const uint* __restrict__ K2hi, const uint* __restrict__ K2lo,
    const uint* __restrict__ VThi, const uint* __restrict__ VTlo,
    float* __restrict__ O1, float* __restrict__ O2)
{
    __shared__ __align__(16) uint Khi[3][64][20], Klo[3][64][20];
    __shared__ __align__(16) uint Vhi[3][32][36], Vlo[3][32][36];

    int tid = threadIdx.x, warp = tid >> 5, lane = tid & 31;
    int gq = lane >> 2, t = lane & 3;
    int lrow = lane & 7, lm = lane >> 3;
    int qt = blockIdx.x, head = blockIdx.y;
    int br = blockIdx.z >> 1, b = blockIdx.z & 1;
    const uint* Qhi = br ? Q2hi : Q1hi;
    const uint* Qlo = br ? Q2lo : Q1lo;
    const uint* KhG = br ? K2hi : K1hi;
    const uint* KlG = br ? K2lo : K1lo;
    float* Ob = br ? O2 : O1;
    const float scale2 = 0.0625f * 1.44269504089f;
    const float MSTAT  = 12.0f;    // static log2-domain max; scores << this

    int vg = (br * 2 + b) * 8 + head;

    int fkey = tid >> 1;
    int fkw  = (tid & 1) * 8;
    int fd   = tid >> 2;
    int fvw  = (tid & 3) * 8;
    const size_t kbase = (size_t)(b * L_ + fkey) * 128 + head * 16 + fkw;
    const size_t vbase = ((size_t)vg * 32 + fd) * 864 + fvw;

    #pragma unroll
    for (int s = 0; s < 2; s++) {
        size_t ko = kbase + (size_t)s * 64 * 128;
        size_t vo = vbase + (size_t)s * 32;
        cp16(sa(&Khi[s][fkey][fkw]),   KhG + ko);
        cp16(sa(&Khi[s][fkey][fkw+4]), KhG + ko + 4);
        cp16(sa(&Klo[s][fkey][fkw]),   KlG + ko);
        cp16(sa(&Klo[s][fkey][fkw+4]), KlG + ko + 4);
        cp16(sa(&Vhi[s][fd][fvw]),     VThi + vo);
        cp16(sa(&Vhi[s][fd][fvw+4]),   VThi + vo + 4);
        cp16(sa(&Vlo[s][fd][fvw]),     VTlo + vo);
        cp16(sa(&Vlo[s][fd][fvw+4]),   VTlo + vo + 4);
        CP_COMMIT();
    }

    int r0 = qt * 64 + warp * 16 + gq;
    int r1 = r0 + 8;

    uint qh[2][4], ql[2][4];
    {
        size_t q0 = (size_t)(b * L_ + r0) * 128 + head * 16;
        size_t q1 = (size_t)(b * L_ + r1) * 128 + head * 16;
        #pragma unroll
        for (int ks = 0; ks < 2; ks++) {
            qh[ks][0] = Qhi[q0 + ks*8 + t];     qh[ks][1] = Qhi[q1 + ks*8 + t];
            qh[ks][2] = Qhi[q0 + ks*8 + t + 4]; qh[ks][3] = Qhi[q1 + ks*8 + t + 4];
            ql[ks][0] = Qlo[q0 + ks*8 + t];     ql[ks][1] = Qlo[q1 + ks*8 + t];
            ql[ks][2] = Qlo[q0 + ks*8 + t + 4]; ql[ks][3] = Qlo[q1 + ks*8 + t + 4];
        }
    }

    float Oacc[4][4];
    #pragma unroll
    for (int j = 0; j < 4; j++)
        #pragma unroll
        for (int i = 0; i < 4; i++) Oacc[j][i] = 0.f;
    float l0r = 0.f, l1r = 0.f;    // local partial sums (reduced at end)

    int klw = lm << 2;

    for (int kt = 0; kt < NKT; kt++) {
        CP_WAIT1();
        __syncthreads();
        int pt = kt + 2;
        if (pt < NKT) {
            int nb = pt % 3;
            size_t ko = kbase + (size_t)pt * 64 * 128;
            size_t vo = vbase + (size_t)pt * 32;
            cp16(sa(&Khi[nb][fkey][fkw]),   KhG + ko);
            cp16(sa(&Khi[nb][fkey][fkw+4]), KhG + ko + 4);
            cp16(sa(&Klo[nb][fkey][fkw]),   KlG + ko);
            cp16(sa(&Klo[nb][fkey][fkw+4]), KlG + ko + 4);
            cp16(sa(&Vhi[nb][fd][fvw]),     VThi + vo);
            cp16(sa(&Vhi[nb][fd][fvw+4]),   VThi + vo + 4);
            cp16(sa(&Vlo[nb][fd][fvw]),     VTlo + vo);
            cp16(sa(&Vlo[nb][fd][fvw+4]),   VTlo + vo + 4);
        }
        CP_COMMIT();
        int bb = kt % 3;

        // S = Q K^T -> p = 2^(s*scale2 - MSTAT), accumulate l locally
        float s[8][4];
        #pragma unroll
        for (int j = 0; j < 8; j++) {
            s[j][0] = s[j][1] = s[j][2] = s[j][3] = 0.f;
            uint kh0, kh1, kh2, kh3, kl0, kl1, kl2, kl3;
            ldsm4(kh0, kh1, kh2, kh3, sa(&Khi[bb][j*8 + lrow][klw]));
            ldsm4(kl0, kl1, kl2, kl3, sa(&Klo[bb][j*8 + lrow][klw]));
            mma_bf16(s[j], qh[0][0], qh[0][1], qh[0][2], qh[0][3], kh0, kh1);
            mma_bf16(s[j], qh[0][0], qh[0][1], qh[0][2], qh[0][3], kl0, kl1);
            mma_bf16(s[j], ql[0][0], ql[0][1], ql[0][2], ql[0][3], kh0, kh1);
            mma_bf16(s[j], qh[1][0], qh[1][1], qh[1][2], qh[1][3], kh2, kh3);
            mma_bf16(s[j], qh[1][0], qh[1][1], qh[1][2], qh[1][3], kl2, kl3);
            mma_bf16(s[j], ql[1][0], ql[1][1], ql[1][2], ql[1][3], kh2, kh3);
            s[j][0] = ex2(fmaf(s[j][0], scale2, -MSTAT)); l0r += s[j][0];
            s[j][1] = ex2(fmaf(s[j][1], scale2, -MSTAT)); l0r += s[j][1];
            s[j][2] = ex2(fmaf(s[j][2], scale2, -MSTAT)); l1r += s[j][2];
            s[j][3] = ex2(fmaf(s[j][3], scale2, -MSTAT)); l1r += s[j][3];
        }

        // P -> bf16x2 fragments
        uint ph[4][4], pl[4][4];
        #pragma unroll
        for (int ks = 0; ks < 4; ks++) {
            split_pair(s[2*ks  ][0], s[2*ks  ][1], ph[ks][0], pl[ks][0]);
            split_pair(s[2*ks  ][2], s[2*ks  ][3], ph[ks][1], pl[ks][1]);
            split_pair(s[2*ks+1][0], s[2*ks+1][1], ph[ks][2], pl[ks][2]);
            split_pair(s[2*ks+1][2], s[2*ks+1][3], ph[ks][3], pl[ks][3]);
        }

        // O += P V
        #pragma unroll
        for (int jn = 0; jn < 4; jn++) {
            #pragma unroll
            for (int h2 = 0; h2 < 2; h2++) {
                uint vh0, vh1, vh2, vh3, vl0, vl1, vl2, vl3;
                ldsm4(vh0, vh1, vh2, vh3, sa(&Vhi[bb][jn*8 + lrow][(h2<<4) + klw]));
                ldsm4(vl0, vl1, vl2, vl3, sa(&Vlo[bb][jn*8 + lrow][(h2<<4) + klw]));
                int ka = 2*h2, kb2 = 2*h2 + 1;
                mma_bf16(Oacc[jn], ph[ka][0], ph[ka][1], ph[ka][2], ph[ka][3], vh0, vh1);
                mma_bf16(Oacc[jn], ph[ka][0], ph[ka][1], ph[ka][2], ph[ka][3], vl0, vl1);
                mma_bf16(Oacc[jn], pl[ka][0], pl[ka][1], pl[ka][2], pl[ka][3], vh0, vh1);
                mma_bf16(Oacc[jn], ph[kb2][0], ph[kb2][1], ph[kb2][2], ph[kb2][3], vh2, vh3);
                mma_bf16(Oacc[jn], ph[kb2][0], ph[kb2][1], ph[kb2][2], ph[kb2][3], vl2, vl3);
                mma_bf16(Oacc[jn], pl[kb2][0], pl[kb2][1], pl[kb2][2], pl[kb2][3], vh2, vh3);
            }
        }
    }

    // final l reduction across the quad (lanes t=0..3 share a row)
    l0r += __shfl_xor_sync(0xffffffffu, l0r, 1);
    l0r += __shfl_xor_sync(0xffffffffu, l0r, 2);
    l1r += __shfl_xor_sync(0xffffffffu, l1r, 1);
    l1r += __shfl_xor_sync(0xffffffffu, l1r, 2);

    float inv0 = 1.f / l0r, inv1 = 1.f / l1r;
    #pragma unroll
    for (int jn = 0; jn < 4; jn++) {
        int col = head * 32 + jn * 8 + 2 * t;
        *(float2*)&Ob[(size_t)(b * L_ + r0) * 256 + col] =
            make_float2(Oacc[jn][0] * inv0, Oacc[jn][1] * inv0);
        *(float2*)&Ob[(size_t)(b * L_ + r1) * 256 + col] =
            make_float2(Oacc[jn][2] * inv1, Oacc[jn][3] * inv1);
    }
}

// ---------------- combine ------------------------------------------------------
__global__ void __launch_bounds__(256) combine_kernel(
    const float* __restrict__ O1, const float* __restrict__ O2,
    const float* __restrict__ h, const float* __restrict__ ffo,
    float* __restrict__ acc, uint* __restrict__ ahi, uint* __restrict__ alo)
{
    int tok = blockIdx.x;
    int u = threadIdx.x;
    size_t i = (size_t)tok * 256 + u;
    float o = h[i] + ffo[i] + O1[i] + O2[i];
    acc[i] = o;
    float pn = __shfl_xor_sync(0xffffffffu, o, 1);
    if (!(u & 1)) {
        uint hi, lo; split_pair(o, pn, hi, lo);
        ahi[(size_t)tok * 128 + (u >> 1)] = hi;
        alo[(size_t)tok * 128 + (u >> 1)] = lo;
    }
}

// ---------------- launch --------------------------------------------------------
extern "C" void kernel_launch(void* const* d_in, const int* in_sizes, int n_in,
                              void* d_out, int out_size)
{
    const float* x       = (const float*)d_in[0];
    const float* context = (const float*)d_in[1];
    const float* bn_g = (const float*)d_in[2];
    const float* bn_b = (const float*)d_in[3];
    const float* bn_m = (const float*)d_in[4];
    const float* bn_v = (const float*)d_in[5];
    const float* ln1_g = (const float*)d_in[6];
    const float* ln1_b = (const float*)d_in[7];
    const float* ln2_g = (const float*)d_in[8];
    const float* ln2_b = (const float*)d_in[9];
    const float* ln3_g = (const float*)d_in[10];
    const float* ln3_b = (const float*)d_in[11];
    const float* pin_w = (const float*)d_in[12];
    const float* pin_b = (const float*)d_in[13];
    const float* q_w   = (const float*)d_in[14];
    const float* q_b   = (const float*)d_in[15];
    const float* k_w   = (const float*)d_in[16];
    const float* k_b   = (const float*)d_in[17];
    const float* v_w   = (const float*)d_in[18];
    const float* v_b   = (const float*)d_in[19];
    const float* ff1_w = (const float*)d_in[20];
    const float* ff1_b = (const float*)d_in[21];
    const float* ff2_w = (const float*)d_in[22];
    const float* ff2_b = (const float*)d_in[23];
    const float* pout_w = (const float*)d_in[24];
    const float* pout_b = (const float*)d_in[25];
    float* out = (float*)d_out;

    float *p_h, *p_v1, *p_v2, *p_ffo, *p_acc, *p_O1, *p_O2;
    uint *p_xhi, *p_xlo, *p_cthi, *p_ctlo, *p_hhi, *p_hlo, *p_nhi, *p_nlo;
    uint *p_f1hi, *p_f1lo, *p_ahi, *p_alo;
    uint *p_q1hi, *p_q1lo, *p_k1hi, *p_k1lo, *p_q2hi, *p_q2lo, *p_k2hi, *p_k2lo;
    uint *p_vthi, *p_vtlo;
    uint *w_pin_h, *w_pin_l, *w_q1_h, *w_q1_l, *w_q2_h, *w_q2_l;
    uint *w_k_h, *w_k_l, *w_v_h, *w_v_l, *w_po_h, *w_po_l;
    uint *w_f1_h, *w_f1_l, *w_f2_h, *w_f2_l;
    float *p_bpin, *p_bq1, *p_bq2, *p_bff1;

    cudaGetSymbolAddress((void**)&p_h,    d_h);
    cudaGetSymbolAddress((void**)&p_v1,   d_v1);
    cudaGetSymbolAddress((void**)&p_v2,   d_v2);
    cudaGetSymbolAddress((void**)&p_ffo,  d_ffo);
    cudaGetSymbolAddress((void**)&p_acc,  d_acc);
    cudaGetSymbolAddress((void**)&p_O1,   d_O1);
    cudaGetSymbolAddress((void**)&p_O2,   d_O2);
    cudaGetSymbolAddress((void**)&p_xhi,  d_xhi);
    cudaGetSymbolAddress((void**)&p_xlo,  d_xlo);
    cudaGetSymbolAddress((void**)&p_cthi, d_cthi);
    cudaGetSymbolAddress((void**)&p_ctlo, d_ctlo);
    cudaGetSymbolAddress((void**)&p_hhi,  d_hhi);
    cudaGetSymbolAddress((void**)&p_hlo,  d_hlo);
    cudaGetSymbolAddress((void**)&p_nhi,  d_nhi);
    cudaGetSymbolAddress((void**)&p_nlo,  d_nlo);
    cudaGetSymbolAddress((void**)&p_f1hi, d_f1hi);
    cudaGetSymbolAddress((void**)&p_f1lo, d_f1lo);
    cudaGetSymbolAddress((void**)&p_ahi,  d_ahi);
    cudaGetSymbolAddress((void**)&p_alo,  d_alo);
    cudaGetSymbolAddress((void**)&p_q1hi, d_q1hi);
    cudaGetSymbolAddress((void**)&p_q1lo, d_q1lo);
    cudaGetSymbolAddress((void**)&p_k1hi, d_k1hi);
    cudaGetSymbolAddress((void**)&p_k1lo, d_k1lo);
    cudaGetSymbolAddress((void**)&p_q2hi, d_q2hi);
    cudaGetSymbolAddress((void**)&p_q2lo, d_q2lo);
    cudaGetSymbolAddress((void**)&p_k2hi, d_k2hi);
    cudaGetSymbolAddress((void**)&p_k2lo, d_k2lo);
    cudaGetSymbolAddress((void**)&p_vthi, d_vthi);
    cudaGetSymbolAddress((void**)&p_vtlo, d_vtlo);
    cudaGetSymbolAddress((void**)&w_pin_h, d_Wpin_h);
    cudaGetSymbolAddress((void**)&w_pin_l, d_Wpin_l);
    cudaGetSymbolAddress((void**)&w_q1_h,  d_Wq1_h);
    cudaGetSymbolAddress((void**)&w_q1_l,  d_Wq1_l);
    cudaGetSymbolAddress((void**)&w_q2_h,  d_Wq2_h);
    cudaGetSymbolAddress((void**)&w_q2_l,  d_Wq2_l);
    cudaGetSymbolAddress((void**)&w_k_h,   d_Wk_h);
    cudaGetSymbolAddress((void**)&w_k_l,   d_Wk_l);
    cudaGetSymbolAddress((void**)&w_v_h,   d_Wv_h);
    cudaGetSymbolAddress((void**)&w_v_l,   d_Wv_l);
    cudaGetSymbolAddress((void**)&w_po_h,  d_Wpout_h);
    cudaGetSymbolAddress((void**)&w_po_l,  d_Wpout_l);
    cudaGetSymbolAddress((void**)&w_f1_h,  d_Wff1_h);
    cudaGetSymbolAddress((void**)&w_f1_l,  d_Wff1_l);
    cudaGetSymbolAddress((void**)&w_f2_h,  d_Wff2_h);
    cudaGetSymbolAddress((void**)&w_f2_l,  d_Wff2_l);
    cudaGetSymbolAddress((void**)&p_bpin,  d_bpin);
    cudaGetSymbolAddress((void**)&p_bq1,   d_bq1);
    cudaGetSymbolAddress((void**)&p_bq2,   d_bq2);
    cudaGetSymbolAddress((void**)&p_bff1,  d_bff1);

    // 1. all prep
    prep_all<<<5472, 256>>>(x, context, bn_g, bn_b, bn_m, bn_v,
                            ln1_g, ln1_b, ln2_g, ln2_b, ln3_g, ln3_b,
                            pin_w, pin_b, q_w, q_b, k_w, v_w,
                            ff1_w, ff1_b, ff2_w, pout_w);

    auto mkop = [](const uint* Ahi, const uint* Alo, const uint* Whi, const uint* Wlo,
                   const float* bias, const float* resid, float* o,
                   uint* Ohi, uint* Olo, int N, int K, int flags, int start) {
        GOp g; g.Ahi = Ahi; g.Alo = Alo; g.Whi = Whi; g.Wlo = Wlo;
        g.bias = bias; g.resid = resid; g.out = o; g.Ohi = Ohi; g.Olo = Olo;
        g.N = N; g.K = K; g.flags = flags; g.tileStart = start;
        return g;
    };
    const int RT = NTOK / 64;
    const int T256 = RT * 2;

    // 2. batch A: pin + k2 + v2
    {
        GBatch P = {};
        P.op[0] = mkop(p_xhi, p_xlo, w_pin_h, w_pin_l, p_bpin, nullptr,
                       p_h, p_hhi, p_hlo, 256, 256, FOUT | FRELU | FPLANES, 0);
        P.op[1] = mkop(p_cthi, p_ctlo, w_k_h, w_k_l, k_b, nullptr,
                       nullptr, p_k2hi, p_k2lo, 256, 256, FPLANES, T256);
        P.op[2] = mkop(p_cthi, p_ctlo, w_v_h, w_v_l, v_b, nullptr,
                       p_v2, nullptr, nullptr, 256, 256, FOUT, T256*2);
        P.nops = 3;
        gemmT<<<T256*3, 256>>>(P);
    }

    // 3. hhat planes
    lnorm_kernel<<<NTOK, 256>>>(p_h, p_nhi, p_nlo);

    // 4. batch B: q1, k1, v1, q2, ff1
    {
        GBatch P = {};
        P.op[0] = mkop(p_nhi, p_nlo, w_q1_h, w_q1_l, p_bq1, nullptr,
                       nullptr, p_q1hi, p_q1lo, 256, 256, FPLANES, 0);
        P.op[1] = mkop(p_hhi, p_hlo, w_k_h, w_k_l, k_b, nullptr,
                       nullptr, p_k1hi, p_k1lo, 256, 256, FPLANES, T256);
        P.op[2] = mkop(p_hhi, p_hlo, w_v_h, w_v_l, v_b, nullptr,
                       p_v1, nullptr, nullptr, 256, 256, FOUT, T256*2);
        P.op[3] = mkop(p_nhi, p_nlo, w_q2_h, w_q2_l, p_bq2, nullptr,
                       nullptr, p_q2hi, p_q2lo, 256, 256, FPLANES, T256*3);
        P.op[4] = mkop(p_nhi, p_nlo, w_f1_h, w_f1_l, p_bff1, nullptr,
                       nullptr, p_f1hi, p_f1lo, 1024, 256, FRELU | FPLANES, T256*4);
        P.nops = 5;
        gemmT<<<T256*4 + RT*8, 256>>>(P);
    }

    // 5. V transpose planes
    {
        dim3 gv(NKT, H_, 4);
        vplanes_T<<<gv, 128>>>(p_v1, p_v2, p_vthi, p_vtlo);
    }

    // 6. attention
    {
        dim3 ga(NKT, H_, 4);
        attn_mma<<<ga, 128>>>(p_q1hi, p_q1lo, p_k1hi, p_k1lo,
                              p_q2hi, p_q2lo, p_k2hi, p_k2lo,
                              p_vthi, p_vtlo, p_O1, p_O2);
    }

    // 7. ff2
    {
        GBatch P = {};
        P.op[0] = mkop(p_f1hi, p_f1lo, w_f2_h, w_f2_l, ff2_b, nullptr,
                       p_ffo, nullptr, nullptr, 256, 1024, FOUT, 0);
        P.nops = 1;
        gemmT<<<T256, 256>>>(P);
    }

    // 8. combine
    combine_kernel<<<NTOK, 256>>>(p_O1, p_O2, p_h, p_ffo, p_acc, p_ahi, p_alo);

    // 9. out = relu(acc @ pout + b) + x
    {
        GBatch P = {};
        P.op[0] = mkop(p_ahi, p_alo, w_po_h, w_po_l, pout_b, x,
                       out, nullptr, nullptr, 256, 256, FOUT | FRELU | FRESID, 0);
        P.nops = 1;
        gemmT<<<T256, 256>>>(P);
    }
}

// round 12
// speedup vs baseline: 1.1888x; 1.0467x over previous
#include <cuda_runtime.h>
#include <math.h>

typedef unsigned long long ull;
typedef unsigned int uint;

#define B_    2
#define L_    1728
#define NTOK  3456
#define C_    256
#define U_    256
#define H_    8
#define HD    32
#define FF_   1024
#define EPS_  1e-3f
#define NKT   27

#define FRELU   1
#define FRESID  2
#define FPLANES 4
#define FOUT    8
#define FSUM3   16

// ---------------- cp.async helpers ------------------------------------------
__device__ __forceinline__ void cp16(uint saddr, const void* gptr) {
    asm volatile("cp.async.cg.shared.global [%0], [%1], 16;" :: "r"(saddr), "l"(gptr));
}
__device__ __forceinline__ uint sa(const void* p) {
    return (uint)__cvta_generic_to_shared(p);
}
#define CP_COMMIT() asm volatile("cp.async.commit_group;")
#define CP_WAIT0()  asm volatile("cp.async.wait_group 0;")
#define CP_WAIT1()  asm volatile("cp.async.wait_group 1;")

// ---------------- ldmatrix ----------------------------------------------------
__device__ __forceinline__ void ldsm4(uint& r0, uint& r1, uint& r2, uint& r3, uint saddr) {
    asm volatile("ldmatrix.sync.aligned.m8n8.x4.shared.b16 {%0,%1,%2,%3}, [%4];"
                 : "=r"(r0), "=r"(r1), "=r"(r2), "=r"(r3) : "r"(saddr));
}

// ---------------- fast exp2 --------------------------------------------------
__device__ __forceinline__ float ex2(float x) {
    float y; asm("ex2.approx.f32 %0,%1;" : "=f"(y) : "f"(x)); return y;
}

// ---------------- bf16 split helpers ---------------------------------------
__device__ __forceinline__ uint bf16_of(float f) {
    unsigned short u; asm("cvt.rn.bf16.f32 %0,%1;" : "=h"(u) : "f"(f));
    return (uint)u;
}
__device__ __forceinline__ void split_pair(float f0, float f1, uint& hi, uint& lo) {
    uint h0 = bf16_of(f0), h1 = bf16_of(f1);
    hi = h0 | (h1 << 16);
    float r0 = f0 - __uint_as_float(h0 << 16);
    float r1 = f1 - __uint_as_float(h1 << 16);
    lo = bf16_of(r0) | (bf16_of(r1) << 16);
}

// ---------------- mma m16n8k16 bf16 -----------------------------------------
__device__ __forceinline__ void mma_bf16(float* c, uint a0, uint a1, uint a2, uint a3,
                                         uint b0, uint b1) {
    asm volatile("mma.sync.aligned.m16n8k16.row.col.f32.bf16.bf16.f32 "
                 "{%0,%1,%2,%3},{%4,%5,%6,%7},{%8,%9},{%0,%1,%2,%3};"
                 : "+f"(c[0]), "+f"(c[1]), "+f"(c[2]), "+f"(c[3])
                 : "r"(a0), "r"(a1), "r"(a2), "r"(a3), "r"(b0), "r"(b1));
}

// ---------------- scratch ---------------------------------------------------
__device__ float d_h   [NTOK*U_];
__device__ float d_v1  [NTOK*U_];
__device__ float d_v2  [NTOK*U_];
__device__ float d_O1  [NTOK*U_];
__device__ float d_O2  [NTOK*U_];

__device__ uint d_xhi [NTOK*128], d_xlo [NTOK*128];
__device__ uint d_cthi[NTOK*128], d_ctlo[NTOK*128];
__device__ uint d_hhi [NTOK*128], d_hlo [NTOK*128];
__device__ uint d_nhi [NTOK*128], d_nlo [NTOK*128];
__device__ uint d_f1hi[NTOK*512], d_f1lo[NTOK*512];
__device__ uint d_ahi [NTOK*128], d_alo [NTOK*128];
__device__ uint d_q1hi[NTOK*128], d_q1lo[NTOK*128];
__device__ uint d_k1hi[NTOK*128], d_k1lo[NTOK*128];
__device__ uint d_q2hi[NTOK*128], d_q2lo[NTOK*128];
__device__ uint d_k2hi[NTOK*128], d_k2lo[NTOK*128];
__device__ uint d_vthi[32*32*864], d_vtlo[32*32*864];

__device__ uint d_Wpin_h[256*128], d_Wpin_l[256*128];
__device__ uint d_Wq1_h [256*128], d_Wq1_l [256*128];
__device__ uint d_Wq2_h [256*128], d_Wq2_l [256*128];
__device__ uint d_Wk_h  [256*128], d_Wk_l  [256*128];
__device__ uint d_Wv_h  [256*128], d_Wv_l  [256*128];
__device__ uint d_Wpout_h[256*128], d_Wpout_l[256*128];
__device__ uint d_Wff1_h[1024*128], d_Wff1_l[1024*128];
__device__ uint d_Wff2_h[256*512],  d_Wff2_l[256*512];

__device__ float d_bpin[U_], d_bq1[U_], d_bq2[U_], d_bff1[FF_];

// ---------------- prep_all (one launch) --------------------------------------
__global__ void __launch_bounds__(256) prep_all(
    const float* __restrict__ x,    const float* __restrict__ ctx,
    const float* __restrict__ bn_g, const float* __restrict__ bn_b,
    const float* __restrict__ bn_m, const float* __restrict__ bn_v,
    const float* __restrict__ ln1_g, const float* __restrict__ ln1_b,
    const float* __restrict__ ln2_g, const float* __restrict__ ln2_b,
    const float* __restrict__ ln3_g, const float* __restrict__ ln3_b,
    const float* __restrict__ pin_w, const float* __restrict__ pin_b,
    const float* __restrict__ q_w,  const float* __restrict__ q_b,
    const float* __restrict__ k_w,  const float* __restrict__ v_w,
    const float* __restrict__ ff1_w, const float* __restrict__ ff1_b,
    const float* __restrict__ ff2_w, const float* __restrict__ pout_w)
{
    int blk = blockIdx.x;
    int tid = threadIdx.x;

    if (blk < 1792) {
        int w = blk * 256 + tid;
        float w0, w1;
        uint *dh, *dl;
        size_t oidx;
        if (w < 196608) {
            int r = w >> 15;
            int idx = w & 32767;
            int u = idx >> 7, k2 = idx & 127;
            int k = k2 * 2;
            oidx = (size_t)u * 128 + k2;
            switch (r) {
            case 0: {
                float s0 = rsqrtf(bn_v[k] + EPS_) * bn_g[k];
                float s1 = rsqrtf(bn_v[k+1] + EPS_) * bn_g[k+1];
                w0 = s0 * pin_w[k*256 + u]; w1 = s1 * pin_w[(k+1)*256 + u];
                dh = d_Wpin_h; dl = d_Wpin_l; } break;
            case 1:
                w0 = ln1_g[k] * q_w[k*256 + u]; w1 = ln1_g[k+1] * q_w[(k+1)*256 + u];
                dh = d_Wq1_h; dl = d_Wq1_l; break;
            case 2:
                w0 = ln2_g[k] * q_w[k*256 + u]; w1 = ln2_g[k+1] * q_w[(k+1)*256 + u];
                dh = d_Wq2_h; dl = d_Wq2_l; break;
            case 3:
                w0 = k_w[k*256 + u]; w1 = k_w[(k+1)*256 + u];
                dh = d_Wk_h; dl = d_Wk_l; break;
            case 4:
                w0 = v_w[k*256 + u]; w1 = v_w[(k+1)*256 + u];
                dh = d_Wv_h; dl = d_Wv_l; break;
            default:
                w0 = pout_w[k*256 + u]; w1 = pout_w[(k+1)*256 + u];
                dh = d_Wpout_h; dl = d_Wpout_l; break;
            }
        } else if (w < 327680) {
            int idx = w - 196608;
            int u = idx >> 7, k2 = idx & 127;
            int k = k2 * 2;
            oidx = (size_t)u * 128 + k2;
            w0 = ln3_g[k] * ff1_w[k*1024 + u]; w1 = ln3_g[k+1] * ff1_w[(k+1)*1024 + u];
            dh = d_Wff1_h; dl = d_Wff1_l;
        } else {
            int idx = w - 327680;
            int u = idx >> 9, k2 = idx & 511;
            int k = k2 * 2;
            oidx = (size_t)u * 512 + k2;
            w0 = ff2_w[k*256 + u]; w1 = ff2_w[(k+1)*256 + u];
            dh = d_Wff2_h; dl = d_Wff2_l;
        }
        uint hi, lo; split_pair(w0, w1, hi, lo);
        dh[oidx] = hi; dl[oidx] = lo;
    } else if (blk < 5248) {
        int rel = blk - 1792;
        const float* s; uint *ph, *pl;
        if (rel < 1728) { s = x; ph = d_xhi; pl = d_xlo; }
        else { rel -= 1728; s = ctx; ph = d_cthi; pl = d_ctlo; }
        int i = rel * 256 + tid;
        float2 f = ((const float2*)s)[i];
        uint h, l; split_pair(f.x, f.y, h, l);
        ph[i] = h; pl[i] = l;
    } else {
        int gw = (blk - 5248) * 8 + (tid >> 5);
        int lane = tid & 31;
        float part = 0.f;
        int u;
        if (gw < 256) {
            u = gw;
            for (int k = lane; k < 256; k += 32) {
                float sc = rsqrtf(bn_v[k] + EPS_) * bn_g[k];
                part += (bn_b[k] - bn_m[k] * sc) * pin_w[k*256 + u];
            }
        } else if (gw < 512) {
            u = gw - 256;
            for (int k = lane; k < 256; k += 32) part += ln1_b[k] * q_w[k*256 + u];
        } else if (gw < 768) {
            u = gw - 512;
            for (int k = lane; k < 256; k += 32) part += ln2_b[k] * q_w[k*256 + u];
        } else {
            u = gw - 768;
            for (int k = lane; k < 256; k += 32) part += ln3_b[k] * ff1_w[k*1024 + u];
        }
        #pragma unroll
        for (int o = 16; o > 0; o >>= 1) part += __shfl_xor_sync(0xffffffffu, part, o);
        if (lane == 0) {
            if (gw < 256)      d_bpin[u] = pin_b[u] + part;
            else if (gw < 512) d_bq1[u]  = q_b[u]  + part;
            else if (gw < 768) d_bq2[u]  = q_b[u]  + part;
            else               d_bff1[u] = ff1_b[u] + part;
        }
    }
}

// ---------------- tensor-core batched GEMM: 64x128, K32 stages, ldmatrix ----
struct GOp {
    const uint* Ahi; const uint* Alo;
    const uint* Whi; const uint* Wlo;
    const float* bias; const float* resid;
    const float* sum1; const float* sum2; const float* sum3;
    float* out; uint* Ohi; uint* Olo;
    int N; int K; int flags; int tileStart;
};
struct GBatch { GOp op[8]; int nops; };

__global__ void __launch_bounds__(256, 2) gemmT(GBatch P)
{
    __shared__ __align__(16) uint As_hi[2][64][20],  As_lo[2][64][20];
    __shared__ __align__(16) uint Ws_hi[2][128][20], Ws_lo[2][128][20];

    int bid = blockIdx.x;
    int sel = 0;
    #pragma unroll
    for (int i = 1; i < 8; i++)
        if (i < P.nops && bid >= P.op[i].tileStart) sel = i;
    GOp g = P.op[sel];

    int local = bid - g.tileStart;
    int ntn = g.N >> 7;
    int mt = local / ntn;
    int nt = local - mt * ntn;
    int m0 = mt * 64, n0 = nt * 128;
    int tid = threadIdx.x;
    int warp = tid >> 5, lane = tid & 31;
    int gq = lane >> 2, t = lane & 3;
    int rw = warp & 3;
    int ch = warp >> 2;
    int K2 = g.K >> 1;

    int lrow = lane & 7, lm = lane >> 3;

    float acc[8][4];
    #pragma unroll
    for (int j = 0; j < 8; j++)
        #pragma unroll
        for (int i = 0; i < 4; i++) acc[j][i] = 0.f;

    // fill indices: 16 words per row per stage (K32)
    int arow = tid >> 1;                // A: tid<128
    int aw0  = (tid & 1) * 8;
    int wrow = tid >> 1;                // W: 0..127
    int ww0  = (tid & 1) * 8;
    const size_t abase = (size_t)(m0 + arow) * K2 + aw0;
    const size_t wbase = (size_t)(n0 + wrow) * K2 + ww0;

    int nst = K2 >> 4;                  // K32 stages

    {   // prefetch stage 0
        if (tid < 128) {
            cp16(sa(&As_hi[0][arow][aw0]),   g.Ahi + abase);
            cp16(sa(&As_hi[0][arow][aw0+4]), g.Ahi + abase + 4);
            cp16(sa(&As_lo[0][arow][aw0]),   g.Alo + abase);
            cp16(sa(&As_lo[0][arow][aw0+4]), g.Alo + abase + 4);
        }
        cp16(sa(&Ws_hi[0][wrow][ww0]),   g.Whi + wbase);
        cp16(sa(&Ws_hi[0][wrow][ww0+4]), g.Whi + wbase + 4);
        cp16(sa(&Ws_lo[0][wrow][ww0]),   g.Wlo + wbase);
        cp16(sa(&Ws_lo[0][wrow][ww0+4]), g.Wlo + wbase + 4);
        CP_COMMIT();
    }

    int a_r = (rw << 4) + ((lm & 1) << 3) + lrow;
    int a_w = (lm >> 1) << 2;
    int b_rbase = (ch << 6) + ((lm >> 1) << 3) + lrow;
    int b_w = (lm & 1) << 2;

    for (int c = 0; c < nst; c++) {
        CP_WAIT0();
        __syncthreads();
        int pc = c + 1;
        if (pc < nst) {
            int nb = pc & 1;
            size_t off = (size_t)pc * 16;
            if (tid < 128) {
                cp16(sa(&As_hi[nb][arow][aw0]),   g.Ahi + abase + off);
                cp16(sa(&As_hi[nb][arow][aw0+4]), g.Ahi + abase + off + 4);
                cp16(sa(&As_lo[nb][arow][aw0]),   g.Alo + abase + off);
                cp16(sa(&As_lo[nb][arow][aw0+4]), g.Alo + abase + off + 4);
            }
            cp16(sa(&Ws_hi[nb][wrow][ww0]),   g.Whi + wbase + off);
            cp16(sa(&Ws_hi[nb][wrow][ww0+4]), g.Whi + wbase + off + 4);
            cp16(sa(&Ws_lo[nb][wrow][ww0]),   g.Wlo + wbase + off);
            cp16(sa(&Ws_lo[nb][wrow][ww0+4]), g.Wlo + wbase + off + 4);
        }
        CP_COMMIT();

        int bb = c & 1;
        #pragma unroll
        for (int hf = 0; hf < 2; hf++) {
            int wo = hf * 8;
            uint a0h, a1h, a2h, a3h, a0l, a1l, a2l, a3l;
            ldsm4(a0h, a1h, a2h, a3h, sa(&As_hi[bb][a_r][a_w + wo]));
            ldsm4(a0l, a1l, a2l, a3l, sa(&As_lo[bb][a_r][a_w + wo]));

            #pragma unroll
            for (int jp = 0; jp < 4; jp++) {
                uint bh0, bh1, bh2, bh3, bl0, bl1, bl2, bl3;
                ldsm4(bh0, bh1, bh2, bh3, sa(&Ws_hi[bb][b_rbase + jp*16][b_w + wo]));
                ldsm4(bl0, bl1, bl2, bl3, sa(&Ws_lo[bb][b_rbase + jp*16][b_w + wo]));
                mma_bf16(acc[jp*2  ], a0h, a1h, a2h, a3h, bh0, bh1);
                mma_bf16(acc[jp*2  ], a0h, a1h, a2h, a3h, bl0, bl1);
                mma_bf16(acc[jp*2  ], a0l, a1l, a2l, a3l, bh0, bh1);
                mma_bf16(acc[jp*2+1], a0h, a1h, a2h, a3h, bh2, bh3);
                mma_bf16(acc[jp*2+1], a0h, a1h, a2h, a3h, bl2, bl3);
                mma_bf16(acc[jp*2+1], a0l, a1l, a2l, a3l, bh2, bh3);
            }
        }
    }

    int K2o = g.N >> 1;
    int r0 = m0 + rw*16 + gq;
    int r1 = r0 + 8;
    #pragma unroll
    for (int j = 0; j < 8; j++) {
        int c0 = n0 + ch*64 + j*8 + 2*t;
        float b0 = g.bias[c0], b1 = g.bias[c0+1];
        float v00 = acc[j][0] + b0, v01 = acc[j][1] + b1;
        float v10 = acc[j][2] + b0, v11 = acc[j][3] + b1;
        if (g.flags & FRELU) {
            v00 = fmaxf(v00, 0.f); v01 = fmaxf(v01, 0.f);
            v10 = fmaxf(v10, 0.f); v11 = fmaxf(v11, 0.f);
        }
        if (g.flags & FRESID) {
            float2 ra = *(const float2*)&g.resid[(size_t)r0*g.N + c0];
            float2 rb = *(const float2*)&g.resid[(size_t)r1*g.N + c0];
            v00 += ra.x; v01 += ra.y; v10 += rb.x; v11 += rb.y;
        }
        if (g.flags & FSUM3) {
            float2 a1 = *(const float2*)&g.sum1[(size_t)r0*g.N + c0];
            float2 a2 = *(const float2*)&g.sum2[(size_t)r0*g.N + c0];
            float2 a3 = *(const float2*)&g.sum3[(size_t)r0*g.N + c0];
            v00 += a1.x + a2.x + a3.x; v01 += a1.y + a2.y + a3.y;
            float2 c1 = *(const float2*)&g.sum1[(size_t)r1*g.N + c0];
            float2 c2 = *(const float2*)&g.sum2[(size_t)r1*g.N + c0];
            float2 c3 = *(const float2*)&g.sum3[(size_t)r1*g.N + c0];
            v10 += c1.x + c2.x + c3.x; v11 += c1.y + c2.y + c3.y;
        }
        if (g.flags & FOUT) {
            *(float2*)&g.out[(size_t)r0*g.N + c0] = make_float2(v00, v01);
            *(float2*)&g.out[(size_t)r1*g.N + c0] = make_float2(v10, v11);
        }
        if (g.flags & FPLANES) {
            uint h, l;
            split_pair(v00, v01, h, l);
            g.Ohi[(size_t)r0*K2o + (c0>>1)] = h; g.Olo[(size_t)r0*K2o + (c0>>1)] = l;
            split_pair(v10, v11, h, l);
            g.Ohi[(size_t)r1*K2o + (c0>>1)] = h; g.Olo[(size_t)r1*K2o + (c0>>1)] = l;
        }
    }
}

// ---------------- LayerNorm -> planes ----------------------------------------
__global__ void __launch_bounds__(256) lnorm_kernel(const float* __restrict__ h,
                                                    uint* __restrict__ nhi,
                                                    uint* __restrict__ nlo)
{
    int row = blockIdx.x;
    int tid = threadIdx.x;
    float v = h[(size_t)row * 256 + tid];
    __shared__ float red[8];
    float s = v;
    #pragma unroll
    for (int o = 16; o > 0; o >>= 1) s += __shfl_xor_sync(0xffffffffu, s, o);
    if ((tid & 31) == 0) red[tid >> 5] = s;
    __syncthreads();
    float tot = 0.f;
    #pragma unroll
    for (int i = 0; i < 8; i++) tot += red[i];
    float mu = tot * (1.f / 256.f);
    float d = v - mu;
    float s2 = d * d;
    #pragma unroll
    for (int o = 16; o > 0; o >>= 1) s2 += __shfl_xor_sync(0xffffffffu, s2, o);
    __syncthreads();
    if ((tid & 31) == 0) red[tid >> 5] = s2;
    __syncthreads();
    float tot2 = 0.f;
    #pragma unroll
    for (int i = 0; i < 8; i++) tot2 += red[i];
    float var = tot2 * (1.f / 256.f);
    float o = d * rsqrtf(var + EPS_);
    float pn = __shfl_xor_sync(0xffffffffu, o, 1);
    if (!(tid & 1)) {
        uint hi, lo; split_pair(o, pn, hi, lo);
        nhi[(size_t)row * 128 + (tid >> 1)] = hi;
        nlo[(size_t)row * 128 + (tid >> 1)] = lo;
    }
}

// ---------------- V transpose into packed key-pair planes -------------------
__global__ void __launch_bounds__(128) vplanes_T(
    const float* __restrict__ V1, const float* __restrict__ V2,
    uint* __restrict__ vthi, uint* __restrict__ vtlo)
{
    __shared__ float Vs[64][33];
    int tid = threadIdx.x;
    int kt = blockIdx.x;
    int head = blockIdx.y;
    int br = blockIdx.z >> 1, b = blockIdx.z & 1;
    const float* V = br ? V2 : V1;
    #pragma unroll
    for (int i = 0; i < 4; i++) {
        int idx = tid + i * 128;
        int key = idx >> 3, f4 = (idx & 7) * 4;
        const float* p = &V[(size_t)(b * L_ + kt * 64 + key) * 256 + head * 32 + f4];
        float4 t4 = *(const float4*)p;
        Vs[key][f4] = t4.x; Vs[key][f4+1] = t4.y;
        Vs[key][f4+2] = t4.z; Vs[key][f4+3] = t4.w;
    }
    __syncthreads();
    int g = (br * 2 + b) * 8 + head;
    #pragma unroll
    for (int i = 0; i < 8; i++) {
        int widx = tid + i * 128;
        int d = widx >> 5, kp = widx & 31;
        uint hi, lo;
        split_pair(Vs[2*kp][d], Vs[2*kp+1][d], hi, lo);
        size_t o = ((size_t)g * 32 + d) * 864 + kt * 32 + kp;
        vthi[o] = hi; vtlo[o] = lo;
    }
}

// ---------------- tensor-core flash attention (static max, 3-stage) ---------
__global__ void __launch_bounds__(128) attn_mma(
    const uint* __restrict__ Q1hi, const uint* __restrict__ Q1lo,
    const uint* __restrict__ K1hi, const uint* __restrict__ K1lo,
    const uint* __restrict__ Q2hi, const uint* __restrict__ Q2lo,
    const uint* __restrict__ K2hi, const uint* __restrict__ K2lo,
    const uint* __restrict__ VThi, const uint* __restrict__ VTlo,
    float* __restrict__ O1, float* __restrict__ O2)
{
    __shared__ __align__(16) uint Khi[3][64][20], Klo[3][64][20];
    __shared__ __align__(16) uint Vhi[3][32][36], Vlo[3][32][36];

    int tid = threadIdx.x, warp = tid >> 5, lane = tid & 31;
    int gq = lane >> 2, t = lane & 3;
    int lrow = lane & 7, lm = lane >> 3;
    int qt = blockIdx.x, head = blockIdx.y;
    int br = blockIdx.z >> 1, b = blockIdx.z & 1;
    const uint* Qhi = br ? Q2hi : Q1hi;
    const uint* Qlo = br ? Q2lo : Q1lo;
    const uint* KhG = br ? K2hi : K1hi;
    const uint* KlG = br ? K2lo : K1lo;
    float* Ob = br ? O2 : O1;
    const float scale2 = 0.0625f * 1.44269504089f;
    const float MSTAT  = 12.0f;

    int vg = (br * 2 + b) * 8 + head;

    int fkey = tid >> 1;
    int fkw  = (tid & 1) * 8;
    int fd   = tid >> 2;
    int fvw  = (tid & 3) * 8;
    const size_t kbase = (size_t)(b * L_ + fkey) * 128 + head * 16 + fkw;
    const size_t vbase = ((size_t)vg * 32 + fd) * 864 + fvw;

    #pragma unroll
    for (int s = 0; s < 2; s++) {
        size_t ko = kbase + (size_t)s * 64 * 128;
        size_t vo = vbase + (size_t)s * 32;
        cp16(sa(&Khi[s][fkey][fkw]),   KhG + ko);
        cp16(sa(&Khi[s][fkey][fkw+4]), KhG + ko + 4);
        cp16(sa(&Klo[s][fkey][fkw]),   KlG + ko);
        cp16(sa(&Klo[s][fkey][fkw+4]), KlG + ko + 4);
        cp16(sa(&Vhi[s][fd][fvw]),     VThi + vo);
        cp16(sa(&Vhi[s][fd][fvw+4]),   VThi + vo + 4);
        cp16(sa(&Vlo[s][fd][fvw]),     VTlo + vo);
        cp16(sa(&Vlo[s][fd][fvw+4]),   VTlo + vo + 4);
        CP_COMMIT();
    }

    int r0 = qt * 64 + warp * 16 + gq;
    int r1 = r0 + 8;

    uint qh[2][4], ql[2][4];
    {
        size_t q0 = (size_t)(b * L_ + r0) * 128 + head * 16;
        size_t q1 = (size_t)(b * L_ + r1) * 128 + head * 16;
        #pragma unroll
        for (int ks = 0; ks < 2; ks++) {
            qh[ks][0] = Qhi[q0 + ks*8 + t];     qh[ks][1] = Qhi[q1 + ks*8 + t];
            qh[ks][2] = Qhi[q0 + ks*8 + t + 4]; qh[ks][3] = Qhi[q1 + ks*8 + t + 4];
            ql[ks][0] = Qlo[q0 + ks*8 + t];     ql[ks][1] = Qlo[q1 + ks*8 + t];
            ql[ks][2] = Qlo[q0 + ks*8 + t + 4]; ql[ks][3] = Qlo[q1 + ks*8 + t + 4];
        }
    }

    float Oacc[4][4];
    #pragma unroll
    for (int j = 0; j < 4; j++)
        #pragma unroll
        for (int i = 0; i < 4; i++) Oacc[j][i] = 0.f;
    float l0r = 0.f, l1r = 0.f;

    int klw = lm << 2;

    for (int kt = 0; kt < NKT; kt++) {
        CP_WAIT1();
        __syncthreads();
        int pt = kt + 2;
        if (pt < NKT) {
            int nb = pt % 3;
            size_t ko = kbase + (size_t)pt * 64 * 128;
            size_t vo = vbase + (size_t)pt * 32;
            cp16(sa(&Khi[nb][fkey][fkw]),   KhG + ko);
            cp16(sa(&Khi[nb][fkey][fkw+4]), KhG + ko + 4);
            cp16(sa(&Klo[nb][fkey][fkw]),   KlG + ko);
            cp16(sa(&Klo[nb][fkey][fkw+4]), KlG + ko + 4);
            cp16(sa(&Vhi[nb][fd][fvw]),     VThi + vo);
            cp16(sa(&Vhi[nb][fd][fvw+4]),   VThi + vo + 4);
            cp16(sa(&Vlo[nb][fd][fvw]),     VTlo + vo);
            cp16(sa(&Vlo[nb][fd][fvw+4]),   VTlo + vo + 4);
        }
        CP_COMMIT();
        int bb = kt % 3;

        float s[8][4];
        #pragma unroll
        for (int j = 0; j < 8; j++) {
            s[j][0] = s[j][1] = s[j][2] = s[j][3] = 0.f;
            uint kh0, kh1, kh2, kh3, kl0, kl1, kl2, kl3;
            ldsm4(kh0, kh1, kh2, kh3, sa(&Khi[bb][j*8 + lrow][klw]));
            ldsm4(kl0, kl1, kl2, kl3, sa(&Klo[bb][j*8 + lrow][klw]));
            mma_bf16(s[j], qh[0][0], qh[0][1], qh[0][2], qh[0][3], kh0, kh1);
            mma_bf16(s[j], qh[0][0], qh[0][1], qh[0][2], qh[0][3], kl0, kl1);
            mma_bf16(s[j], ql[0][0], ql[0][1], ql[0][2], ql[0][3], kh0, kh1);
            mma_bf16(s[j], qh[1][0], qh[1][1], qh[1][2], qh[1][3], kh2, kh3);
            mma_bf16(s[j], qh[1][0], qh[1][1], qh[1][2], qh[1][3], kl2, kl3);
            mma_bf16(s[j], ql[1][0], ql[1][1], ql[1][2], ql[1][3], kh2, kh3);
            s[j][0] = ex2(fmaf(s[j][0], scale2, -MSTAT)); l0r += s[j][0];
            s[j][1] = ex2(fmaf(s[j][1], scale2, -MSTAT)); l0r += s[j][1];
            s[j][2] = ex2(fmaf(s[j][2], scale2, -MSTAT)); l1r += s[j][2];
            s[j][3] = ex2(fmaf(s[j][3], scale2, -MSTAT)); l1r += s[j][3];
        }

        uint ph[4][4], pl[4][4];
        #pragma unroll
        for (int ks = 0; ks < 4; ks++) {
            split_pair(s[2*ks  ][0], s[2*ks  ][1], ph[ks][0], pl[ks][0]);
            split_pair(s[2*ks  ][2], s[2*ks  ][3], ph[ks][1], pl[ks][1]);
            split_pair(s[2*ks+1][0], s[2*ks+1][1], ph[ks][2], pl[ks][2]);
            split_pair(s[2*ks+1][2], s[2*ks+1][3], ph[ks][3], pl[ks][3]);
        }

        #pragma unroll
        for (int jn = 0; jn < 4; jn++) {
            #pragma unroll
            for (int h2 = 0; h2 < 2; h2++) {
                uint vh0, vh1, vh2, vh3, vl0, vl1, vl2, vl3;
                ldsm4(vh0, vh1, vh2, vh3, sa(&Vhi[bb][jn*8 + lrow][(h2<<4) + klw]));
                ldsm4(vl0, vl1, vl2, vl3, sa(&Vlo[bb][jn*8 + lrow][(h2<<4) + klw]));
                int ka = 2*h2, kb2 = 2*h2 + 1;
                mma_bf16(Oacc[jn], ph[ka][0], ph[ka][1], ph[ka][2], ph[ka][3], vh0, vh1);
                mma_bf16(Oacc[jn], ph[ka][0], ph[ka][1], ph[ka][2], ph[ka][3], vl0, vl1);
                mma_bf16(Oacc[jn], pl[ka][0], pl[ka][1], pl[ka][2], pl[ka][3], vh0, vh1);
                mma_bf16(Oacc[jn], ph[kb2][0], ph[kb2][1], ph[kb2][2], ph[kb2][3], vh2, vh3);
                mma_bf16(Oacc[jn], ph[kb2][0], ph[kb2][1], ph[kb2][2], ph[kb2][3], vl2, vl3);
                mma_bf16(Oacc[jn], pl[kb2][0], pl[kb2][1], pl[kb2][2], pl[kb2][3], vh2, vh3);
            }
        }
    }

    l0r += __shfl_xor_sync(0xffffffffu, l0r, 1);
    l0r += __shfl_xor_sync(0xffffffffu, l0r, 2);
    l1r += __shfl_xor_sync(0xffffffffu, l1r, 1);
    l1r += __shfl_xor_sync(0xffffffffu, l1r, 2);

    float inv0 = 1.f / l0r, inv1 = 1.f / l1r;
    #pragma unroll
    for (int jn = 0; jn < 4; jn++) {
        int col = head * 32 + jn * 8 + 2 * t;
        *(float2*)&Ob[(size_t)(b * L_ + r0) * 256 + col] =
            make_float2(Oacc[jn][0] * inv0, Oacc[jn][1] * inv0);
        *(float2*)&Ob[(size_t)(b * L_ + r1) * 256 + col] =
            make_float2(Oacc[jn][2] * inv1, Oacc[jn][3] * inv1);
    }
}

// ---------------- launch --------------------------------------------------------
extern "C" void kernel_launch(void* const* d_in, const int* in_sizes, int n_in,
                              void* d_out, int out_size)
{
    const float* x       = (const float*)d_in[0];
    const float* context = (const float*)d_in[1];
    const float* bn_g = (const float*)d_in[2];
    const float* bn_b = (const float*)d_in[3];
    const float* bn_m = (const float*)d_in[4];
    const float* bn_v = (const float*)d_in[5];
    const float* ln1_g = (const float*)d_in[6];
    const float* ln1_b = (const float*)d_in[7];
    const float* ln2_g = (const float*)d_in[8];
    const float* ln2_b = (const float*)d_in[9];
    const float* ln3_g = (const float*)d_in[10];
    const float* ln3_b = (const float*)d_in[11];
    const float* pin_w = (const float*)d_in[12];
    const float* pin_b = (const float*)d_in[13];
    const float* q_w   = (const float*)d_in[14];
    const float* q_b   = (const float*)d_in[15];
    const float* k_w   = (const float*)d_in[16];
    const float* k_b   = (const float*)d_in[17];
    const float* v_w   = (const float*)d_in[18];
    const float* v_b   = (const float*)d_in[19];
    const float* ff1_w = (const float*)d_in[20];
    const float* ff1_b = (const float*)d_in[21];
    const float* ff2_w = (const float*)d_in[22];
    const float* ff2_b = (const float*)d_in[23];
    const float* pout_w = (const float*)d_in[24];
    const float* pout_b = (const float*)d_in[25];
    float* out = (float*)d_out;

    float *p_h, *p_v1, *p_v2, *p_O1, *p_O2;
    uint *p_xhi, *p_xlo, *p_cthi, *p_ctlo, *p_hhi, *p_hlo, *p_nhi, *p_nlo;
    uint *p_f1hi, *p_f1lo, *p_ahi, *p_alo;
    uint *p_q1hi, *p_q1lo, *p_k1hi, *p_k1lo, *p_q2hi, *p_q2lo, *p_k2hi, *p_k2lo;
    uint *p_vthi, *p_vtlo;
    uint *w_pin_h, *w_pin_l, *w_q1_h, *w_q1_l, *w_q2_h, *w_q2_l;
    uint *w_k_h, *w_k_l, *w_v_h, *w_v_l, *w_po_h, *w_po_l;
    uint *w_f1_h, *w_f1_l, *w_f2_h, *w_f2_l;
    float *p_bpin, *p_bq1, *p_bq2, *p_bff1;

    cudaGetSymbolAddress((void**)&p_h,    d_h);
    cudaGetSymbolAddress((void**)&p_v1,   d_v1);
    cudaGetSymbolAddress((void**)&p_v2,   d_v2);
    cudaGetSymbolAddress((void**)&p_O1,   d_O1);
    cudaGetSymbolAddress((void**)&p_O2,   d_O2);
    cudaGetSymbolAddress((void**)&p_xhi,  d_xhi);
    cudaGetSymbolAddress((void**)&p_xlo,  d_xlo);
    cudaGetSymbolAddress((void**)&p_cthi, d_cthi);
    cudaGetSymbolAddress((void**)&p_ctlo, d_ctlo);
    cudaGetSymbolAddress((void**)&p_hhi,  d_hhi);
    cudaGetSymbolAddress((void**)&p_hlo,  d_hlo);
    cudaGetSymbolAddress((void**)&p_nhi,  d_nhi);
    cudaGetSymbolAddress((void**)&p_nlo,  d_nlo);
    cudaGetSymbolAddress((void**)&p_f1hi, d_f1hi);
    cudaGetSymbolAddress((void**)&p_f1lo, d_f1lo);
    cudaGetSymbolAddress((void**)&p_ahi,  d_ahi);
    cudaGetSymbolAddress((void**)&p_alo,  d_alo);
    cudaGetSymbolAddress((void**)&p_q1hi, d_q1hi);
    cudaGetSymbolAddress((void**)&p_q1lo, d_q1lo);
    cudaGetSymbolAddress((void**)&p_k1hi, d_k1hi);
    cudaGetSymbolAddress((void**)&p_k1lo, d_k1lo);
    cudaGetSymbolAddress((void**)&p_q2hi, d_q2hi);
    cudaGetSymbolAddress((void**)&p_q2lo, d_q2lo);
    cudaGetSymbolAddress((void**)&p_k2hi, d_k2hi);
    cudaGetSymbolAddress((void**)&p_k2lo, d_k2lo);
    cudaGetSymbolAddress((void**)&p_vthi, d_vthi);
    cudaGetSymbolAddress((void**)&p_vtlo, d_vtlo);
    cudaGetSymbolAddress((void**)&w_pin_h, d_Wpin_h);
    cudaGetSymbolAddress((void**)&w_pin_l, d_Wpin_l);
    cudaGetSymbolAddress((void**)&w_q1_h,  d_Wq1_h);
    cudaGetSymbolAddress((void**)&w_q1_l,  d_Wq1_l);
    cudaGetSymbolAddress((void**)&w_q2_h,  d_Wq2_h);
    cudaGetSymbolAddress((void**)&w_q2_l,  d_Wq2_l);
    cudaGetSymbolAddress((void**)&w_k_h,   d_Wk_h);
    cudaGetSymbolAddress((void**)&w_k_l,   d_Wk_l);
    cudaGetSymbolAddress((void**)&w_v_h,   d_Wv_h);
    cudaGetSymbolAddress((void**)&w_v_l,   d_Wv_l);
    cudaGetSymbolAddress((void**)&w_po_h,  d_Wpout_h);
    cudaGetSymbolAddress((void**)&w_po_l,  d_Wpout_l);
    cudaGetSymbolAddress((void**)&w_f1_h,  d_Wff1_h);
    cudaGetSymbolAddress((void**)&w_f1_l,  d_Wff1_l);
    cudaGetSymbolAddress((void**)&w_f2_h,  d_Wff2_h);
    cudaGetSymbolAddress((void**)&w_f2_l,  d_Wff2_l);
    cudaGetSymbolAddress((void**)&p_bpin,  d_bpin);
    cudaGetSymbolAddress((void**)&p_bq1,   d_bq1);
    cudaGetSymbolAddress((void**)&p_bq2,   d_bq2);
    cudaGetSymbolAddress((void**)&p_bff1,  d_bff1);

    // 1. all prep
    prep_all<<<5472, 256>>>(x, context, bn_g, bn_b, bn_m, bn_v,
                            ln1_g, ln1_b, ln2_g, ln2_b, ln3_g, ln3_b,
                            pin_w, pin_b, q_w, q_b, k_w, v_w,
                            ff1_w, ff1_b, ff2_w, pout_w);

    auto mkop = [](const uint* Ahi, const uint* Alo, const uint* Whi, const uint* Wlo,
                   const float* bias, const float* resid, float* o,
                   uint* Ohi, uint* Olo, int N, int K, int flags, int start) {
        GOp g = {};
        g.Ahi = Ahi; g.Alo = Alo; g.Whi = Whi; g.Wlo = Wlo;
        g.bias = bias; g.resid = resid; g.out = o; g.Ohi = Ohi; g.Olo = Olo;
        g.N = N; g.K = K; g.flags = flags; g.tileStart = start;
        return g;
    };
    const int RT = NTOK / 64;
    const int T256 = RT * 2;

    // 2. batch A: pin + k2 + v2
    {
        GBatch P = {};
        P.op[0] = mkop(p_xhi, p_xlo, w_pin_h, w_pin_l, p_bpin, nullptr,
                       p_h, p_hhi, p_hlo, 256, 256, FOUT | FRELU | FPLANES, 0);
        P.op[1] = mkop(p_cthi, p_ctlo, w_k_h, w_k_l, k_b, nullptr,
                       nullptr, p_k2hi, p_k2lo, 256, 256, FPLANES, T256);
        P.op[2] = mkop(p_cthi, p_ctlo, w_v_h, w_v_l, v_b, nullptr,
                       p_v2, nullptr, nullptr, 256, 256, FOUT, T256*2);
        P.nops = 3;
        gemmT<<<T256*3, 256>>>(P);
    }

    // 3. hhat planes
    lnorm_kernel<<<NTOK, 256>>>(p_h, p_nhi, p_nlo);

    // 4. batch B: q1, k1, v1, q2, ff1
    {
        GBatch P = {};
        P.op[0] = mkop(p_nhi, p_nlo, w_q1_h, w_q1_l, p_bq1, nullptr,
                       nullptr, p_q1hi, p_q1lo, 256, 256, FPLANES, 0);
        P.op[1] = mkop(p_hhi, p_hlo, w_k_h, w_k_l, k_b, nullptr,
                       nullptr, p_k1hi, p_k1lo, 256, 256, FPLANES, T256);
        P.op[2] = mkop(p_hhi, p_hlo, w_v_h, w_v_l, v_b, nullptr,
                       p_v1, nullptr, nullptr, 256, 256, FOUT, T256*2);
        P.op[3] = mkop(p_nhi, p_nlo, w_q2_h, w_q2_l, p_bq2, nullptr,
                       nullptr, p_q2hi, p_q2lo, 256, 256, FPLANES, T256*3);
        P.op[4] = mkop(p_nhi, p_nlo, w_f1_h, w_f1_l, p_bff1, nullptr,
                       nullptr, p_f1hi, p_f1lo, 1024, 256, FRELU | FPLANES, T256*4);
        P.nops = 5;
        gemmT<<<T256*4 + RT*8, 256>>>(P);
    }

    // 5. V transpose planes
    {
        dim3 gv(NKT, H_, 4);
        vplanes_T<<<gv, 128>>>(p_v1, p_v2, p_vthi, p_vtlo);
    }

    // 6. attention
    {
        dim3 ga(NKT, H_, 4);
        attn_mma<<<ga, 128>>>(p_q1hi, p_q1lo, p_k1hi, p_k1lo,
                              p_q2hi, p_q2lo, p_k2hi, p_k2lo,
                              p_vthi, p_vtlo, p_O1, p_O2);
    }

    // 7. ff2 + combine fused: acc = ff2(f1) + h + O1 + O2 -> planes
    {
        GBatch P = {};
        P.op[0] = mkop(p_f1hi, p_f1lo, w_f2_h, w_f2_l, ff2_b, nullptr,
                       nullptr, p_ahi, p_alo, 256, 1024, FSUM3 | FPLANES, 0);
        P.op[0].sum1 = p_h;
        P.op[0].sum2 = p_O1;
        P.op[0].sum3 = p_O2;
        P.nops = 1;
        gemmT<<<T256, 256>>>(P);
    }

    // 8. out = relu(acc @ pout + b) + x
    {
        GBatch P = {};
        P.op[0] = mkop(p_ahi, p_alo, w_po_h, w_po_l, pout_b, x,
                       out, nullptr, nullptr, 256, 256, FOUT | FRELU | FRESID, 0);
        P.nops = 1;
        gemmT<<<T256, 256>>>(P);
    }
}

// round 13
// speedup vs baseline: 1.2328x; 1.0370x over previous
#include <cuda_runtime.h>
#include <math.h>

typedef unsigned long long ull;
typedef unsigned int uint;

#define B_    2
#define L_    1728
#define NTOK  3456
#define C_    256
#define U_    256
#define H_    8
#define HD    32
#define FF_   1024
#define EPS_  1e-3f
#define NKT   27

#define FRELU   1
#define FRESID  2
#define FPLANES 4
#define FOUT    8
#define FSUM3   16

// ---------------- cp.async helpers ------------------------------------------
__device__ __forceinline__ void cp16(uint saddr, const void* gptr) {
    asm volatile("cp.async.cg.shared.global [%0], [%1], 16;" :: "r"(saddr), "l"(gptr));
}
__device__ __forceinline__ uint sa(const void* p) {
    return (uint)__cvta_generic_to_shared(p);
}
#define CP_COMMIT() asm volatile("cp.async.commit_group;")
#define CP_WAIT0()  asm volatile("cp.async.wait_group 0;")
#define CP_WAIT1()  asm volatile("cp.async.wait_group 1;")

// ---------------- ldmatrix ----------------------------------------------------
__device__ __forceinline__ void ldsm4(uint& r0, uint& r1, uint& r2, uint& r3, uint saddr) {
    asm volatile("ldmatrix.sync.aligned.m8n8.x4.shared.b16 {%0,%1,%2,%3}, [%4];"
                 : "=r"(r0), "=r"(r1), "=r"(r2), "=r"(r3) : "r"(saddr));
}

// ---------------- fast exp2 --------------------------------------------------
__device__ __forceinline__ float ex2(float x) {
    float y; asm("ex2.approx.f32 %0,%1;" : "=f"(y) : "f"(x)); return y;
}

// ---------------- bf16 split helpers ---------------------------------------
__device__ __forceinline__ uint bf16_of(float f) {
    unsigned short u; asm("cvt.rn.bf16.f32 %0,%1;" : "=h"(u) : "f"(f));
    return (uint)u;
}
__device__ __forceinline__ void split_pair(float f0, float f1, uint& hi, uint& lo) {
    uint h0 = bf16_of(f0), h1 = bf16_of(f1);
    hi = h0 | (h1 << 16);
    float r0 = f0 - __uint_as_float(h0 << 16);
    float r1 = f1 - __uint_as_float(h1 << 16);
    lo = bf16_of(r0) | (bf16_of(r1) << 16);
}

// ---------------- mma m16n8k16 bf16 -----------------------------------------
__device__ __forceinline__ void mma_bf16(float* c, uint a0, uint a1, uint a2, uint a3,
                                         uint b0, uint b1) {
    asm volatile("mma.sync.aligned.m16n8k16.row.col.f32.bf16.bf16.f32 "
                 "{%0,%1,%2,%3},{%4,%5,%6,%7},{%8,%9},{%0,%1,%2,%3};"
                 : "+f"(c[0]), "+f"(c[1]), "+f"(c[2]), "+f"(c[3])
                 : "r"(a0), "r"(a1), "r"(a2), "r"(a3), "r"(b0), "r"(b1));
}

// ---------------- scratch ---------------------------------------------------
__device__ float d_h   [NTOK*U_];
__device__ float d_v1  [NTOK*U_];
__device__ float d_v2  [NTOK*U_];
__device__ float d_O1  [NTOK*U_];
__device__ float d_O2  [NTOK*U_];

__device__ uint d_xhi [NTOK*128], d_xlo [NTOK*128];
__device__ uint d_cthi[NTOK*128], d_ctlo[NTOK*128];
__device__ uint d_hhi [NTOK*128], d_hlo [NTOK*128];
__device__ uint d_nhi [NTOK*128], d_nlo [NTOK*128];
__device__ uint d_f1hi[NTOK*512], d_f1lo[NTOK*512];
__device__ uint d_ahi [NTOK*128], d_alo [NTOK*128];
__device__ uint d_q1hi[NTOK*128], d_q1lo[NTOK*128];
__device__ uint d_k1hi[NTOK*128], d_k1lo[NTOK*128];
__device__ uint d_q2hi[NTOK*128], d_q2lo[NTOK*128];
__device__ uint d_k2hi[NTOK*128], d_k2lo[NTOK*128];
__device__ uint d_vthi[32*32*864], d_vtlo[32*32*864];

__device__ uint d_Wpin_h[256*128], d_Wpin_l[256*128];
__device__ uint d_Wq1_h [256*128], d_Wq1_l [256*128];
__device__ uint d_Wq2_h [256*128], d_Wq2_l [256*128];
__device__ uint d_Wk_h  [256*128], d_Wk_l  [256*128];
__device__ uint d_Wv_h  [256*128], d_Wv_l  [256*128];
__device__ uint d_Wpout_h[256*128], d_Wpout_l[256*128];
__device__ uint d_Wff1_h[1024*128], d_Wff1_l[1024*128];
__device__ uint d_Wff2_h[256*512],  d_Wff2_l[256*512];

__device__ float d_bpin[U_], d_bq1[U_], d_bq2[U_], d_bff1[FF_];

// ---------------- prep_all (one launch) --------------------------------------
__global__ void __launch_bounds__(256) prep_all(
    const float* __restrict__ x,    const float* __restrict__ ctx,
    const float* __restrict__ bn_g, const float* __restrict__ bn_b,
    const float* __restrict__ bn_m, const float* __restrict__ bn_v,
    const float* __restrict__ ln1_g, const float* __restrict__ ln1_b,
    const float* __restrict__ ln2_g, const float* __restrict__ ln2_b,
    const float* __restrict__ ln3_g, const float* __restrict__ ln3_b,
    const float* __restrict__ pin_w, const float* __restrict__ pin_b,
    const float* __restrict__ q_w,  const float* __restrict__ q_b,
    const float* __restrict__ k_w,  const float* __restrict__ v_w,
    const float* __restrict__ ff1_w, const float* __restrict__ ff1_b,
    const float* __restrict__ ff2_w, const float* __restrict__ pout_w)
{
    int blk = blockIdx.x;
    int tid = threadIdx.x;

    if (blk < 1792) {
        int w = blk * 256 + tid;
        float w0, w1;
        uint *dh, *dl;
        size_t oidx;
        if (w < 196608) {
            int r = w >> 15;
            int idx = w & 32767;
            int u = idx >> 7, k2 = idx & 127;
            int k = k2 * 2;
            oidx = (size_t)u * 128 + k2;
            switch (r) {
            case 0: {
                float s0 = rsqrtf(bn_v[k] + EPS_) * bn_g[k];
                float s1 = rsqrtf(bn_v[k+1] + EPS_) * bn_g[k+1];
                w0 = s0 * pin_w[k*256 + u]; w1 = s1 * pin_w[(k+1)*256 + u];
                dh = d_Wpin_h; dl = d_Wpin_l; } break;
            case 1:
                w0 = ln1_g[k] * q_w[k*256 + u]; w1 = ln1_g[k+1] * q_w[(k+1)*256 + u];
                dh = d_Wq1_h; dl = d_Wq1_l; break;
            case 2:
                w0 = ln2_g[k] * q_w[k*256 + u]; w1 = ln2_g[k+1] * q_w[(k+1)*256 + u];
                dh = d_Wq2_h; dl = d_Wq2_l; break;
            case 3:
                w0 = k_w[k*256 + u]; w1 = k_w[(k+1)*256 + u];
                dh = d_Wk_h; dl = d_Wk_l; break;
            case 4:
                w0 = v_w[k*256 + u]; w1 = v_w[(k+1)*256 + u];
                dh = d_Wv_h; dl = d_Wv_l; break;
            default:
                w0 = pout_w[k*256 + u]; w1 = pout_w[(k+1)*256 + u];
                dh = d_Wpout_h; dl = d_Wpout_l; break;
            }
        } else if (w < 327680) {
            int idx = w - 196608;
            int u = idx >> 7, k2 = idx & 127;
            int k = k2 * 2;
            oidx = (size_t)u * 128 + k2;
            w0 = ln3_g[k] * ff1_w[k*1024 + u]; w1 = ln3_g[k+1] * ff1_w[(k+1)*1024 + u];
            dh = d_Wff1_h; dl = d_Wff1_l;
        } else {
            int idx = w - 327680;
            int u = idx >> 9, k2 = idx & 511;
            int k = k2 * 2;
            oidx = (size_t)u * 512 + k2;
            w0 = ff2_w[k*256 + u]; w1 = ff2_w[(k+1)*256 + u];
            dh = d_Wff2_h; dl = d_Wff2_l;
        }
        uint hi, lo; split_pair(w0, w1, hi, lo);
        dh[oidx] = hi; dl[oidx] = lo;
    } else if (blk < 5248) {
        int rel = blk - 1792;
        const float* s; uint *ph, *pl;
        if (rel < 1728) { s = x; ph = d_xhi; pl = d_xlo; }
        else { rel -= 1728; s = ctx; ph = d_cthi; pl = d_ctlo; }
        int i = rel * 256 + tid;
        float2 f = ((const float2*)s)[i];
        uint h, l; split_pair(f.x, f.y, h, l);
        ph[i] = h; pl[i] = l;
    } else {
        int gw = (blk - 5248) * 8 + (tid >> 5);
        int lane = tid & 31;
        float part = 0.f;
        int u;
        if (gw < 256) {
            u = gw;
            for (int k = lane; k < 256; k += 32) {
                float sc = rsqrtf(bn_v[k] + EPS_) * bn_g[k];
                part += (bn_b[k] - bn_m[k] * sc) * pin_w[k*256 + u];
            }
        } else if (gw < 512) {
            u = gw - 256;
            for (int k = lane; k < 256; k += 32) part += ln1_b[k] * q_w[k*256 + u];
        } else if (gw < 768) {
            u = gw - 512;
            for (int k = lane; k < 256; k += 32) part += ln2_b[k] * q_w[k*256 + u];
        } else {
            u = gw - 768;
            for (int k = lane; k < 256; k += 32) part += ln3_b[k] * ff1_w[k*1024 + u];
        }
        #pragma unroll
        for (int o = 16; o > 0; o >>= 1) part += __shfl_xor_sync(0xffffffffu, part, o);
        if (lane == 0) {
            if (gw < 256)      d_bpin[u] = pin_b[u] + part;
            else if (gw < 512) d_bq1[u]  = q_b[u]  + part;
            else if (gw < 768) d_bq2[u]  = q_b[u]  + part;
            else               d_bff1[u] = ff1_b[u] + part;
        }
    }
}

// ---------------- tensor-core batched GEMM: 64x128, K32 stages, ldmatrix ----
struct GOp {
    const uint* Ahi; const uint* Alo;
    const uint* Whi; const uint* Wlo;
    const float* bias; const float* resid;
    const float* sum1; const float* sum2; const float* sum3;
    float* out; uint* Ohi; uint* Olo;
    int N; int K; int flags; int tileStart;
};
struct GBatch { GOp op[8]; int nops; };

__global__ void __launch_bounds__(256, 2) gemmT(GBatch P)
{
    __shared__ __align__(16) uint As_hi[2][64][20],  As_lo[2][64][20];
    __shared__ __align__(16) uint Ws_hi[2][128][20], Ws_lo[2][128][20];

    int bid = blockIdx.x;
    int sel = 0;
    #pragma unroll
    for (int i = 1; i < 8; i++)
        if (i < P.nops && bid >= P.op[i].tileStart) sel = i;
    GOp g = P.op[sel];

    int local = bid - g.tileStart;
    int ntn = g.N >> 7;
    int mt = local / ntn;
    int nt = local - mt * ntn;
    int m0 = mt * 64, n0 = nt * 128;
    int tid = threadIdx.x;
    int warp = tid >> 5, lane = tid & 31;
    int gq = lane >> 2, t = lane & 3;
    int rw = warp & 3;
    int ch = warp >> 2;
    int K2 = g.K >> 1;

    int lrow = lane & 7, lm = lane >> 3;

    float acc[8][4];
    #pragma unroll
    for (int j = 0; j < 8; j++)
        #pragma unroll
        for (int i = 0; i < 4; i++) acc[j][i] = 0.f;

    int arow = tid >> 1;
    int aw0  = (tid & 1) * 8;
    int wrow = tid >> 1;
    int ww0  = (tid & 1) * 8;
    const size_t abase = (size_t)(m0 + arow) * K2 + aw0;
    const size_t wbase = (size_t)(n0 + wrow) * K2 + ww0;

    int nst = K2 >> 4;

    {
        if (tid < 128) {
            cp16(sa(&As_hi[0][arow][aw0]),   g.Ahi + abase);
            cp16(sa(&As_hi[0][arow][aw0+4]), g.Ahi + abase + 4);
            cp16(sa(&As_lo[0][arow][aw0]),   g.Alo + abase);
            cp16(sa(&As_lo[0][arow][aw0+4]), g.Alo + abase + 4);
        }
        cp16(sa(&Ws_hi[0][wrow][ww0]),   g.Whi + wbase);
        cp16(sa(&Ws_hi[0][wrow][ww0+4]), g.Whi + wbase + 4);
        cp16(sa(&Ws_lo[0][wrow][ww0]),   g.Wlo + wbase);
        cp16(sa(&Ws_lo[0][wrow][ww0+4]), g.Wlo + wbase + 4);
        CP_COMMIT();
    }

    int a_r = (rw << 4) + ((lm & 1) << 3) + lrow;
    int a_w = (lm >> 1) << 2;
    int b_rbase = (ch << 6) + ((lm >> 1) << 3) + lrow;
    int b_w = (lm & 1) << 2;

    for (int c = 0; c < nst; c++) {
        CP_WAIT0();
        __syncthreads();
        int pc = c + 1;
        if (pc < nst) {
            int nb = pc & 1;
            size_t off = (size_t)pc * 16;
            if (tid < 128) {
                cp16(sa(&As_hi[nb][arow][aw0]),   g.Ahi + abase + off);
                cp16(sa(&As_hi[nb][arow][aw0+4]), g.Ahi + abase + off + 4);
                cp16(sa(&As_lo[nb][arow][aw0]),   g.Alo + abase + off);
                cp16(sa(&As_lo[nb][arow][aw0+4]), g.Alo + abase + off + 4);
            }
            cp16(sa(&Ws_hi[nb][wrow][ww0]),   g.Whi + wbase + off);
            cp16(sa(&Ws_hi[nb][wrow][ww0+4]), g.Whi + wbase + off + 4);
            cp16(sa(&Ws_lo[nb][wrow][ww0]),   g.Wlo + wbase + off);
            cp16(sa(&Ws_lo[nb][wrow][ww0+4]), g.Wlo + wbase + off + 4);
        }
        CP_COMMIT();

        int bb = c & 1;
        #pragma unroll
        for (int hf = 0; hf < 2; hf++) {
            int wo = hf * 8;
            uint a0h, a1h, a2h, a3h, a0l, a1l, a2l, a3l;
            ldsm4(a0h, a1h, a2h, a3h, sa(&As_hi[bb][a_r][a_w + wo]));
            ldsm4(a0l, a1l, a2l, a3l, sa(&As_lo[bb][a_r][a_w + wo]));

            #pragma unroll
            for (int jp = 0; jp < 4; jp++) {
                uint bh0, bh1, bh2, bh3, bl0, bl1, bl2, bl3;
                ldsm4(bh0, bh1, bh2, bh3, sa(&Ws_hi[bb][b_rbase + jp*16][b_w + wo]));
                ldsm4(bl0, bl1, bl2, bl3, sa(&Ws_lo[bb][b_rbase + jp*16][b_w + wo]));
                mma_bf16(acc[jp*2  ], a0h, a1h, a2h, a3h, bh0, bh1);
                mma_bf16(acc[jp*2  ], a0h, a1h, a2h, a3h, bl0, bl1);
                mma_bf16(acc[jp*2  ], a0l, a1l, a2l, a3l, bh0, bh1);
                mma_bf16(acc[jp*2+1], a0h, a1h, a2h, a3h, bh2, bh3);
                mma_bf16(acc[jp*2+1], a0h, a1h, a2h, a3h, bl2, bl3);
                mma_bf16(acc[jp*2+1], a0l, a1l, a2l, a3l, bh2, bh3);
            }
        }
    }

    int K2o = g.N >> 1;
    int r0 = m0 + rw*16 + gq;
    int r1 = r0 + 8;
    #pragma unroll
    for (int j = 0; j < 8; j++) {
        int c0 = n0 + ch*64 + j*8 + 2*t;
        float b0 = g.bias[c0], b1 = g.bias[c0+1];
        float v00 = acc[j][0] + b0, v01 = acc[j][1] + b1;
        float v10 = acc[j][2] + b0, v11 = acc[j][3] + b1;
        if (g.flags & FRELU) {
            v00 = fmaxf(v00, 0.f); v01 = fmaxf(v01, 0.f);
            v10 = fmaxf(v10, 0.f); v11 = fmaxf(v11, 0.f);
        }
        if (g.flags & FRESID) {
            float2 ra = *(const float2*)&g.resid[(size_t)r0*g.N + c0];
            float2 rb = *(const float2*)&g.resid[(size_t)r1*g.N + c0];
            v00 += ra.x; v01 += ra.y; v10 += rb.x; v11 += rb.y;
        }
        if (g.flags & FSUM3) {
            float2 a1 = *(const float2*)&g.sum1[(size_t)r0*g.N + c0];
            float2 a2 = *(const float2*)&g.sum2[(size_t)r0*g.N + c0];
            float2 a3 = *(const float2*)&g.sum3[(size_t)r0*g.N + c0];
            v00 += a1.x + a2.x + a3.x; v01 += a1.y + a2.y + a3.y;
            float2 c1 = *(const float2*)&g.sum1[(size_t)r1*g.N + c0];
            float2 c2 = *(const float2*)&g.sum2[(size_t)r1*g.N + c0];
            float2 c3 = *(const float2*)&g.sum3[(size_t)r1*g.N + c0];
            v10 += c1.x + c2.x + c3.x; v11 += c1.y + c2.y + c3.y;
        }
        if (g.flags & FOUT) {
            *(float2*)&g.out[(size_t)r0*g.N + c0] = make_float2(v00, v01);
            *(float2*)&g.out[(size_t)r1*g.N + c0] = make_float2(v10, v11);
        }
        if (g.flags & FPLANES) {
            uint h, l;
            split_pair(v00, v01, h, l);
            g.Ohi[(size_t)r0*K2o + (c0>>1)] = h; g.Olo[(size_t)r0*K2o + (c0>>1)] = l;
            split_pair(v10, v11, h, l);
            g.Ohi[(size_t)r1*K2o + (c0>>1)] = h; g.Olo[(size_t)r1*K2o + (c0>>1)] = l;
        }
    }
}

// ---------------- LayerNorm -> planes ----------------------------------------
__global__ void __launch_bounds__(256) lnorm_kernel(const float* __restrict__ h,
                                                    uint* __restrict__ nhi,
                                                    uint* __restrict__ nlo)
{
    int row = blockIdx.x;
    int tid = threadIdx.x;
    float v = h[(size_t)row * 256 + tid];
    __shared__ float red[8];
    float s = v;
    #pragma unroll
    for (int o = 16; o > 0; o >>= 1) s += __shfl_xor_sync(0xffffffffu, s, o);
    if ((tid & 31) == 0) red[tid >> 5] = s;
    __syncthreads();
    float tot = 0.f;
    #pragma unroll
    for (int i = 0; i < 8; i++) tot += red[i];
    float mu = tot * (1.f / 256.f);
    float d = v - mu;
    float s2 = d * d;
    #pragma unroll
    for (int o = 16; o > 0; o >>= 1) s2 += __shfl_xor_sync(0xffffffffu, s2, o);
    __syncthreads();
    if ((tid & 31) == 0) red[tid >> 5] = s2;
    __syncthreads();
    float tot2 = 0.f;
    #pragma unroll
    for (int i = 0; i < 8; i++) tot2 += red[i];
    float var = tot2 * (1.f / 256.f);
    float o = d * rsqrtf(var + EPS_);
    float pn = __shfl_xor_sync(0xffffffffu, o, 1);
    if (!(tid & 1)) {
        uint hi, lo; split_pair(o, pn, hi, lo);
        nhi[(size_t)row * 128 + (tid >> 1)] = hi;
        nlo[(size_t)row * 128 + (tid >> 1)] = lo;
    }
}

// ---------------- V transpose into packed key-pair planes -------------------
__global__ void __launch_bounds__(128) vplanes_T(
    const float* __restrict__ V1, const float* __restrict__ V2,
    uint* __restrict__ vthi, uint* __restrict__ vtlo)
{
    __shared__ float Vs[64][33];
    int tid = threadIdx.x;
    int kt = blockIdx.x;
    int head = blockIdx.y;
    int br = blockIdx.z >> 1, b = blockIdx.z & 1;
    const float* V = br ? V2 : V1;
    #pragma unroll
    for (int i = 0; i < 4; i++) {
        int idx = tid + i * 128;
        int key = idx >> 3, f4 = (idx & 7) * 4;
        const float* p = &V[(size_t)(b * L_ + kt * 64 + key) * 256 + head * 32 + f4];
        float4 t4 = *(const float4*)p;
        Vs[key][f4] = t4.x; Vs[key][f4+1] = t4.y;
        Vs[key][f4+2] = t4.z; Vs[key][f4+3] = t4.w;
    }
    __syncthreads();
    int g = (br * 2 + b) * 8 + head;
    #pragma unroll
    for (int i = 0; i < 8; i++) {
        int widx = tid + i * 128;
        int d = widx >> 5, kp = widx & 31;
        uint hi, lo;
        split_pair(Vs[2*kp][d], Vs[2*kp+1][d], hi, lo);
        size_t o = ((size_t)g * 32 + d) * 864 + kt * 32 + kp;
        vthi[o] = hi; vtlo[o] = lo;
    }
}

// ---------------- tensor-core flash attention (QK x2, static max) -----------
__global__ void __launch_bounds__(128) attn_mma(
    const uint* __restrict__ Q1hi,
    const uint* __restrict__ K1hi, const uint* __restrict__ K1lo,
    const uint* __restrict__ Q2hi,
    const uint* __restrict__ K2hi, const uint* __restrict__ K2lo,
    const uint* __restrict__ VThi, const uint* __restrict__ VTlo,
    float* __restrict__ O1, float* __restrict__ O2)
{
    __shared__ __align__(16) uint Khi[3][64][20], Klo[3][64][20];
    __shared__ __align__(16) uint Vhi[3][32][36], Vlo[3][32][36];

    int tid = threadIdx.x, warp = tid >> 5, lane = tid & 31;
    int gq = lane >> 2, t = lane & 3;
    int lrow = lane & 7, lm = lane >> 3;
    int qt = blockIdx.x, head = blockIdx.y;
    int br = blockIdx.z >> 1, b = blockIdx.z & 1;
    const uint* Qhi = br ? Q2hi : Q1hi;
    const uint* KhG = br ? K2hi : K1hi;
    const uint* KlG = br ? K2lo : K1lo;
    float* Ob = br ? O2 : O1;
    const float scale2 = 0.0625f * 1.44269504089f;
    const float MSTAT  = 12.0f;

    int vg = (br * 2 + b) * 8 + head;

    int fkey = tid >> 1;
    int fkw  = (tid & 1) * 8;
    int fd   = tid >> 2;
    int fvw  = (tid & 3) * 8;
    const size_t kbase = (size_t)(b * L_ + fkey) * 128 + head * 16 + fkw;
    const size_t vbase = ((size_t)vg * 32 + fd) * 864 + fvw;

    #pragma unroll
    for (int s = 0; s < 2; s++) {
        size_t ko = kbase + (size_t)s * 64 * 128;
        size_t vo = vbase + (size_t)s * 32;
        cp16(sa(&Khi[s][fkey][fkw]),   KhG + ko);
        cp16(sa(&Khi[s][fkey][fkw+4]), KhG + ko + 4);
        cp16(sa(&Klo[s][fkey][fkw]),   KlG + ko);
        cp16(sa(&Klo[s][fkey][fkw+4]), KlG + ko + 4);
        cp16(sa(&Vhi[s][fd][fvw]),     VThi + vo);
        cp16(sa(&Vhi[s][fd][fvw+4]),   VThi + vo + 4);
        cp16(sa(&Vlo[s][fd][fvw]),     VTlo + vo);
        cp16(sa(&Vlo[s][fd][fvw+4]),   VTlo + vo + 4);
        CP_COMMIT();
    }

    int r0 = qt * 64 + warp * 16 + gq;
    int r1 = r0 + 8;

    uint qh[2][4];
    {
        size_t q0 = (size_t)(b * L_ + r0) * 128 + head * 16;
        size_t q1 = (size_t)(b * L_ + r1) * 128 + head * 16;
        #pragma unroll
        for (int ks = 0; ks < 2; ks++) {
            qh[ks][0] = Qhi[q0 + ks*8 + t];     qh[ks][1] = Qhi[q1 + ks*8 + t];
            qh[ks][2] = Qhi[q0 + ks*8 + t + 4]; qh[ks][3] = Qhi[q1 + ks*8 + t + 4];
        }
    }

    float Oacc[4][4];
    #pragma unroll
    for (int j = 0; j < 4; j++)
        #pragma unroll
        for (int i = 0; i < 4; i++) Oacc[j][i] = 0.f;
    float l0r = 0.f, l1r = 0.f;

    int klw = lm << 2;

    for (int kt = 0; kt < NKT; kt++) {
        CP_WAIT1();
        __syncthreads();
        int pt = kt + 2;
        if (pt < NKT) {
            int nb = pt % 3;
            size_t ko = kbase + (size_t)pt * 64 * 128;
            size_t vo = vbase + (size_t)pt * 32;
            cp16(sa(&Khi[nb][fkey][fkw]),   KhG + ko);
            cp16(sa(&Khi[nb][fkey][fkw+4]), KhG + ko + 4);
            cp16(sa(&Klo[nb][fkey][fkw]),   KlG + ko);
            cp16(sa(&Klo[nb][fkey][fkw+4]), KlG + ko + 4);
            cp16(sa(&Vhi[nb][fd][fvw]),     VThi + vo);
            cp16(sa(&Vhi[nb][fd][fvw+4]),   VThi + vo + 4);
            cp16(sa(&Vlo[nb][fd][fvw]),     VTlo + vo);
            cp16(sa(&Vlo[nb][fd][fvw+4]),   VTlo + vo + 4);
        }
        CP_COMMIT();
        int bb = kt % 3;

        // S = Q K^T (x2: qh*kh + qh*kl)
        float s[8][4];
        #pragma unroll
        for (int j = 0; j < 8; j++) {
            s[j][0] = s[j][1] = s[j][2] = s[j][3] = 0.f;
            uint kh0, kh1, kh2, kh3, kl0, kl1, kl2, kl3;
            ldsm4(kh0, kh1, kh2, kh3, sa(&Khi[bb][j*8 + lrow][klw]));
            ldsm4(kl0, kl1, kl2, kl3, sa(&Klo[bb][j*8 + lrow][klw]));
            mma_bf16(s[j], qh[0][0], qh[0][1], qh[0][2], qh[0][3], kh0, kh1);
            mma_bf16(s[j], qh[0][0], qh[0][1], qh[0][2], qh[0][3], kl0, kl1);
            mma_bf16(s[j], qh[1][0], qh[1][1], qh[1][2], qh[1][3], kh2, kh3);
            mma_bf16(s[j], qh[1][0], qh[1][1], qh[1][2], qh[1][3], kl2, kl3);
            s[j][0] = ex2(fmaf(s[j][0], scale2, -MSTAT)); l0r += s[j][0];
            s[j][1] = ex2(fmaf(s[j][1], scale2, -MSTAT)); l0r += s[j][1];
            s[j][2] = ex2(fmaf(s[j][2], scale2, -MSTAT)); l1r += s[j][2];
            s[j][3] = ex2(fmaf(s[j][3], scale2, -MSTAT)); l1r += s[j][3];
        }

        uint ph[4][4], pl[4][4];
        #pragma unroll
        for (int ks = 0; ks < 4; ks++) {
            split_pair(s[2*ks  ][0], s[2*ks  ][1], ph[ks][0], pl[ks][0]);
            split_pair(s[2*ks  ][2], s[2*ks  ][3], ph[ks][1], pl[ks][1]);
            split_pair(s[2*ks+1][0], s[2*ks+1][1], ph[ks][2], pl[ks][2]);
            split_pair(s[2*ks+1][2], s[2*ks+1][3], ph[ks][3], pl[ks][3]);
        }

        #pragma unroll
        for (int jn = 0; jn < 4; jn++) {
            #pragma unroll
            for (int h2 = 0; h2 < 2; h2++) {
                uint vh0, vh1, vh2, vh3, vl0, vl1, vl2, vl3;
                ldsm4(vh0, vh1, vh2, vh3, sa(&Vhi[bb][jn*8 + lrow][(h2<<4) + klw]));
                ldsm4(vl0, vl1, vl2, vl3, sa(&Vlo[bb][jn*8 + lrow][(h2<<4) + klw]));
                int ka = 2*h2, kb2 = 2*h2 + 1;
                mma_bf16(Oacc[jn], ph[ka][0], ph[ka][1], ph[ka][2], ph[ka][3], vh0, vh1);
                mma_bf16(Oacc[jn], ph[ka][0], ph[ka][1], ph[ka][2], ph[ka][3], vl0, vl1);
                mma_bf16(Oacc[jn], pl[ka][0], pl[ka][1], pl[ka][2], pl[ka][3], vh0, vh1);
                mma_bf16(Oacc[jn], ph[kb2][0], ph[kb2][1], ph[kb2][2], ph[kb2][3], vh2, vh3);
                mma_bf16(Oacc[jn], ph[kb2][0], ph[kb2][1], ph[kb2][2], ph[kb2][3], vl2, vl3);
                mma_bf16(Oacc[jn], pl[kb2][0], pl[kb2][1], pl[kb2][2], pl[kb2][3], vh2, vh3);
            }
        }
    }

    l0r += __shfl_xor_sync(0xffffffffu, l0r, 1);
    l0r += __shfl_xor_sync(0xffffffffu, l0r, 2);
    l1r += __shfl_xor_sync(0xffffffffu, l1r, 1);
    l1r += __shfl_xor_sync(0xffffffffu, l1r, 2);

    float inv0 = 1.f / l0r, inv1 = 1.f / l1r;
    #pragma unroll
    for (int jn = 0; jn < 4; jn++) {
        int col = head * 32 + jn * 8 + 2 * t;
        *(float2*)&Ob[(size_t)(b * L_ + r0) * 256 + col] =
            make_float2(Oacc[jn][0] * inv0, Oacc[jn][1] * inv0);
        *(float2*)&Ob[(size_t)(b * L_ + r1) * 256 + col] =
            make_float2(Oacc[jn][2] * inv1, Oacc[jn][3] * inv1);
    }
}

// ---------------- launch --------------------------------------------------------
extern "C" void kernel_launch(void* const* d_in, const int* in_sizes, int n_in,
                              void* d_out, int out_size)
{
    const float* x       = (const float*)d_in[0];
    const float* context = (const float*)d_in[1];
    const float* bn_g = (const float*)d_in[2];
    const float* bn_b = (const float*)d_in[3];
    const float* bn_m = (const float*)d_in[4];
    const float* bn_v = (const float*)d_in[5];
    const float* ln1_g = (const float*)d_in[6];
    const float* ln1_b = (const float*)d_in[7];
    const float* ln2_g = (const float*)d_in[8];
    const float* ln2_b = (const float*)d_in[9];
    const float* ln3_g = (const float*)d_in[10];
    const float* ln3_b = (const float*)d_in[11];
    const float* pin_w = (const float*)d_in[12];
    const float* pin_b = (const float*)d_in[13];
    const float* q_w   = (const float*)d_in[14];
    const float* q_b   = (const float*)d_in[15];
    const float* k_w   = (const float*)d_in[16];
    const float* k_b   = (const float*)d_in[17];
    const float* v_w   = (const float*)d_in[18];
    const float* v_b   = (const float*)d_in[19];
    const float* ff1_w = (const float*)d_in[20];
    const float* ff1_b = (const float*)d_in[21];
    const float* ff2_w = (const float*)d_in[22];
    const float* ff2_b = (const float*)d_in[23];
    const float* pout_w = (const float*)d_in[24];
    const float* pout_b = (const float*)d_in[25];
    float* out = (float*)d_out;

    float *p_h, *p_v1, *p_v2, *p_O1, *p_O2;
    uint *p_xhi, *p_xlo, *p_cthi, *p_ctlo, *p_hhi, *p_hlo, *p_nhi, *p_nlo;
    uint *p_f1hi, *p_f1lo, *p_ahi, *p_alo;
    uint *p_q1hi, *p_q1lo, *p_k1hi, *p_k1lo, *p_q2hi, *p_q2lo, *p_k2hi, *p_k2lo;
    uint *p_vthi, *p_vtlo;
    uint *w_pin_h, *w_pin_l, *w_q1_h, *w_q1_l, *w_q2_h, *w_q2_l;
    uint *w_k_h, *w_k_l, *w_v_h, *w_v_l, *w_po_h, *w_po_l;
    uint *w_f1_h, *w_f1_l, *w_f2_h, *w_f2_l;
    float *p_bpin, *p_bq1, *p_bq2, *p_bff1;

    cudaGetSymbolAddress((void**)&p_h,    d_h);
    cudaGetSymbolAddress((void**)&p_v1,   d_v1);
    cudaGetSymbolAddress((void**)&p_v2,   d_v2);
    cudaGetSymbolAddress((void**)&p_O1,   d_O1);
    cudaGetSymbolAddress((void**)&p_O2,   d_O2);
    cudaGetSymbolAddress((void**)&p_xhi,  d_xhi);
    cudaGetSymbolAddress((void**)&p_xlo,  d_xlo);
    cudaGetSymbolAddress((void**)&p_cthi, d_cthi);
    cudaGetSymbolAddress((void**)&p_ctlo, d_ctlo);
    cudaGetSymbolAddress((void**)&p_hhi,  d_hhi);
    cudaGetSymbolAddress((void**)&p_hlo,  d_hlo);
    cudaGetSymbolAddress((void**)&p_nhi,  d_nhi);
    cudaGetSymbolAddress((void**)&p_nlo,  d_nlo);
    cudaGetSymbolAddress((void**)&p_f1hi, d_f1hi);
    cudaGetSymbolAddress((void**)&p_f1lo, d_f1lo);
    cudaGetSymbolAddress((void**)&p_ahi,  d_ahi);
    cudaGetSymbolAddress((void**)&p_alo,  d_alo);
    cudaGetSymbolAddress((void**)&p_q1hi, d_q1hi);
    cudaGetSymbolAddress((void**)&p_q1lo, d_q1lo);
    cudaGetSymbolAddress((void**)&p_k1hi, d_k1hi);
    cudaGetSymbolAddress((void**)&p_k1lo, d_k1lo);
    cudaGetSymbolAddress((void**)&p_q2hi, d_q2hi);
    cudaGetSymbolAddress((void**)&p_q2lo, d_q2lo);
    cudaGetSymbolAddress((void**)&p_k2hi, d_k2hi);
    cudaGetSymbolAddress((void**)&p_k2lo, d_k2lo);
    cudaGetSymbolAddress((void**)&p_vthi, d_vthi);
    cudaGetSymbolAddress((void**)&p_vtlo, d_vtlo);
    cudaGetSymbolAddress((void**)&w_pin_h, d_Wpin_h);
    cudaGetSymbolAddress((void**)&w_pin_l, d_Wpin_l);
    cudaGetSymbolAddress((void**)&w_q1_h,  d_Wq1_h);
    cudaGetSymbolAddress((void**)&w_q1_l,  d_Wq1_l);
    cudaGetSymbolAddress((void**)&w_q2_h,  d_Wq2_h);
    cudaGetSymbolAddress((void**)&w_q2_l,  d_Wq2_l);
    cudaGetSymbolAddress((void**)&w_k_h,   d_Wk_h);
    cudaGetSymbolAddress((void**)&w_k_l,   d_Wk_l);
    cudaGetSymbolAddress((void**)&w_v_h,   d_Wv_h);
    cudaGetSymbolAddress((void**)&w_v_l,   d_Wv_l);
    cudaGetSymbolAddress((void**)&w_po_h,  d_Wpout_h);
    cudaGetSymbolAddress((void**)&w_po_l,  d_Wpout_l);
    cudaGetSymbolAddress((void**)&w_f1_h,  d_Wff1_h);
    cudaGetSymbolAddress((void**)&w_f1_l,  d_Wff1_l);
    cudaGetSymbolAddress((void**)&w_f2_h,  d_Wff2_h);
    cudaGetSymbolAddress((void**)&w_f2_l,  d_Wff2_l);
    cudaGetSymbolAddress((void**)&p_bpin,  d_bpin);
    cudaGetSymbolAddress((void**)&p_bq1,   d_bq1);
    cudaGetSymbolAddress((void**)&p_bq2,   d_bq2);
    cudaGetSymbolAddress((void**)&p_bff1,  d_bff1);

    // 1. all prep
    prep_all<<<5472, 256>>>(x, context, bn_g, bn_b, bn_m, bn_v,
                            ln1_g, ln1_b, ln2_g, ln2_b, ln3_g, ln3_b,
                            pin_w, pin_b, q_w, q_b, k_w, v_w,
                            ff1_w, ff1_b, ff2_w, pout_w);

    auto mkop = [](const uint* Ahi, const uint* Alo, const uint* Whi, const uint* Wlo,
                   const float* bias, const float* resid, float* o,
                   uint* Ohi, uint* Olo, int N, int K, int flags, int start) {
        GOp g = {};
        g.Ahi = Ahi; g.Alo = Alo; g.Whi = Whi; g.Wlo = Wlo;
        g.bias = bias; g.resid = resid; g.out = o; g.Ohi = Ohi; g.Olo = Olo;
        g.N = N; g.K = K; g.flags = flags; g.tileStart = start;
        return g;
    };
    const int RT = NTOK / 64;
    const int T256 = RT * 2;

    // 2. batch A: pin + k2 + v2
    {
        GBatch P = {};
        P.op[0] = mkop(p_xhi, p_xlo, w_pin_h, w_pin_l, p_bpin, nullptr,
                       p_h, p_hhi, p_hlo, 256, 256, FOUT | FRELU | FPLANES, 0);
        P.op[1] = mkop(p_cthi, p_ctlo, w_k_h, w_k_l, k_b, nullptr,
                       nullptr, p_k2hi, p_k2lo, 256, 256, FPLANES, T256);
        P.op[2] = mkop(p_cthi, p_ctlo, w_v_h, w_v_l, v_b, nullptr,
                       p_v2, nullptr, nullptr, 256, 256, FOUT, T256*2);
        P.nops = 3;
        gemmT<<<T256*3, 256>>>(P);
    }

    // 3. hhat planes
    lnorm_kernel<<<NTOK, 256>>>(p_h, p_nhi, p_nlo);

    // 4. batch B: q1, k1, v1, q2, ff1
    {
        GBatch P = {};
        P.op[0] = mkop(p_nhi, p_nlo, w_q1_h, w_q1_l, p_bq1, nullptr,
                       nullptr, p_q1hi, p_q1lo, 256, 256, FPLANES, 0);
        P.op[1] = mkop(p_hhi, p_hlo, w_k_h, w_k_l, k_b, nullptr,
                       nullptr, p_k1hi, p_k1lo, 256, 256, FPLANES, T256);
        P.op[2] = mkop(p_hhi, p_hlo, w_v_h, w_v_l, v_b, nullptr,
                       p_v1, nullptr, nullptr, 256, 256, FOUT, T256*2);
        P.op[3] = mkop(p_nhi, p_nlo, w_q2_h, w_q2_l, p_bq2, nullptr,
                       nullptr, p_q2hi, p_q2lo, 256, 256, FPLANES, T256*3);
        P.op[4] = mkop(p_nhi, p_nlo, w_f1_h, w_f1_l, p_bff1, nullptr,
                       nullptr, p_f1hi, p_f1lo, 1024, 256, FRELU | FPLANES, T256*4);
        P.nops = 5;
        gemmT<<<T256*4 + RT*8, 256>>>(P);
    }

    // 5. V transpose planes
    {
        dim3 gv(NKT, H_, 4);
        vplanes_T<<<gv, 128>>>(p_v1, p_v2, p_vthi, p_vtlo);
    }

    // 6. attention (QK x2)
    {
        dim3 ga(NKT, H_, 4);
        attn_mma<<<ga, 128>>>(p_q1hi, p_k1hi, p_k1lo,
                              p_q2hi, p_k2hi, p_k2lo,
                              p_vthi, p_vtlo, p_O1, p_O2);
    }

    // 7. ff2 + combine fused
    {
        GBatch P = {};
        P.op[0] = mkop(p_f1hi, p_f1lo, w_f2_h, w_f2_l, ff2_b, nullptr,
                       nullptr, p_ahi, p_alo, 256, 1024, FSUM3 | FPLANES, 0);
        P.op[0].sum1 = p_h;
        P.op[0].sum2 = p_O1;
        P.op[0].sum3 = p_O2;
        P.nops = 1;
        gemmT<<<T256, 256>>>(P);
    }

    // 8. out = relu(acc @ pout + b) + x
    {
        GBatch P = {};
        P.op[0] = mkop(p_ahi, p_alo, w_po_h, w_po_l, pout_b, x,
                       out, nullptr, nullptr, 256, 256, FOUT | FRELU | FRESID, 0);
        P.nops = 1;
        gemmT<<<T256, 256>>>(P);
    }
}

// round 14
// speedup vs baseline: 1.3943x; 1.1310x over previous
#include <cuda_runtime.h>
#include <math.h>

typedef unsigned long long ull;
typedef unsigned int uint;

#define B_    2
#define L_    1728
#define NTOK  3456
#define C_    256
#define U_    256
#define H_    8
#define HD    32
#define FF_   1024
#define EPS_  1e-3f
#define NKT   27

#define FRELU   1
#define FRESID  2
#define FPLANES 4
#define FOUT    8
#define FSUM3   16
#define FPLHI   32

// ---------------- cp.async helpers ------------------------------------------
__device__ __forceinline__ void cp16(uint saddr, const void* gptr) {
    asm volatile("cp.async.cg.shared.global [%0], [%1], 16;" :: "r"(saddr), "l"(gptr));
}
__device__ __forceinline__ uint sa(const void* p) {
    return (uint)__cvta_generic_to_shared(p);
}
#define CP_COMMIT() asm volatile("cp.async.commit_group;")
#define CP_WAIT0()  asm volatile("cp.async.wait_group 0;")
#define CP_WAIT1()  asm volatile("cp.async.wait_group 1;")

// ---------------- ldmatrix ----------------------------------------------------
__device__ __forceinline__ void ldsm4(uint& r0, uint& r1, uint& r2, uint& r3, uint saddr) {
    asm volatile("ldmatrix.sync.aligned.m8n8.x4.shared.b16 {%0,%1,%2,%3}, [%4];"
                 : "=r"(r0), "=r"(r1), "=r"(r2), "=r"(r3) : "r"(saddr));
}

// ---------------- fast exp2 --------------------------------------------------
__device__ __forceinline__ float ex2(float x) {
    float y; asm("ex2.approx.f32 %0,%1;" : "=f"(y) : "f"(x)); return y;
}

// ---------------- bf16 split helpers ---------------------------------------
__device__ __forceinline__ uint bf16_of(float f) {
    unsigned short u; asm("cvt.rn.bf16.f32 %0,%1;" : "=h"(u) : "f"(f));
    return (uint)u;
}
__device__ __forceinline__ void split_pair(float f0, float f1, uint& hi, uint& lo) {
    uint h0 = bf16_of(f0), h1 = bf16_of(f1);
    hi = h0 | (h1 << 16);
    float r0 = f0 - __uint_as_float(h0 << 16);
    float r1 = f1 - __uint_as_float(h1 << 16);
    lo = bf16_of(r0) | (bf16_of(r1) << 16);
}
__device__ __forceinline__ uint pack_hi(float f0, float f1) {
    return bf16_of(f0) | (bf16_of(f1) << 16);
}

// ---------------- mma m16n8k16 bf16 -----------------------------------------
__device__ __forceinline__ void mma_bf16(float* c, uint a0, uint a1, uint a2, uint a3,
                                         uint b0, uint b1) {
    asm volatile("mma.sync.aligned.m16n8k16.row.col.f32.bf16.bf16.f32 "
                 "{%0,%1,%2,%3},{%4,%5,%6,%7},{%8,%9},{%0,%1,%2,%3};"
                 : "+f"(c[0]), "+f"(c[1]), "+f"(c[2]), "+f"(c[3])
                 : "r"(a0), "r"(a1), "r"(a2), "r"(a3), "r"(b0), "r"(b1));
}

// ---------------- scratch ---------------------------------------------------
__device__ float d_h   [NTOK*U_];
__device__ float d_v1  [NTOK*U_];
__device__ float d_v2  [NTOK*U_];
__device__ float d_O1  [NTOK*U_];
__device__ float d_O2  [NTOK*U_];

__device__ uint d_xhi [NTOK*128], d_xlo [NTOK*128];
__device__ uint d_cthi[NTOK*128], d_ctlo[NTOK*128];
__device__ uint d_hhi [NTOK*128], d_hlo [NTOK*128];
__device__ uint d_nhi [NTOK*128], d_nlo [NTOK*128];
__device__ uint d_f1hi[NTOK*512], d_f1lo[NTOK*512];
__device__ uint d_ahi [NTOK*128], d_alo [NTOK*128];
__device__ uint d_q1hi[NTOK*128];
__device__ uint d_k1hi[NTOK*128];
__device__ uint d_q2hi[NTOK*128];
__device__ uint d_k2hi[NTOK*128];
__device__ uint d_vthi[32*32*864];

__device__ uint d_Wpin_h[256*128], d_Wpin_l[256*128];
__device__ uint d_Wq1_h [256*128], d_Wq1_l [256*128];
__device__ uint d_Wq2_h [256*128], d_Wq2_l [256*128];
__device__ uint d_Wk_h  [256*128], d_Wk_l  [256*128];
__device__ uint d_Wv_h  [256*128], d_Wv_l  [256*128];
__device__ uint d_Wpout_h[256*128], d_Wpout_l[256*128];
__device__ uint d_Wff1_h[1024*128], d_Wff1_l[1024*128];
__device__ uint d_Wff2_h[256*512],  d_Wff2_l[256*512];

__device__ float d_bpin[U_], d_bq1[U_], d_bq2[U_], d_bff1[FF_];

// ---------------- prep_all (one launch) --------------------------------------
__global__ void __launch_bounds__(256) prep_all(
    const float* __restrict__ x,    const float* __restrict__ ctx,
    const float* __restrict__ bn_g, const float* __restrict__ bn_b,
    const float* __restrict__ bn_m, const float* __restrict__ bn_v,
    const float* __restrict__ ln1_g, const float* __restrict__ ln1_b,
    const float* __restrict__ ln2_g, const float* __restrict__ ln2_b,
    const float* __restrict__ ln3_g, const float* __restrict__ ln3_b,
    const float* __restrict__ pin_w, const float* __restrict__ pin_b,
    const float* __restrict__ q_w,  const float* __restrict__ q_b,
    const float* __restrict__ k_w,  const float* __restrict__ v_w,
    const float* __restrict__ ff1_w, const float* __restrict__ ff1_b,
    const float* __restrict__ ff2_w, const float* __restrict__ pout_w)
{
    int blk = blockIdx.x;
    int tid = threadIdx.x;

    if (blk < 1792) {
        int w = blk * 256 + tid;
        float w0, w1;
        uint *dh, *dl;
        size_t oidx;
        if (w < 196608) {
            int r = w >> 15;
            int idx = w & 32767;
            int u = idx >> 7, k2 = idx & 127;
            int k = k2 * 2;
            oidx = (size_t)u * 128 + k2;
            switch (r) {
            case 0: {
                float s0 = rsqrtf(bn_v[k] + EPS_) * bn_g[k];
                float s1 = rsqrtf(bn_v[k+1] + EPS_) * bn_g[k+1];
                w0 = s0 * pin_w[k*256 + u]; w1 = s1 * pin_w[(k+1)*256 + u];
                dh = d_Wpin_h; dl = d_Wpin_l; } break;
            case 1:
                w0 = ln1_g[k] * q_w[k*256 + u]; w1 = ln1_g[k+1] * q_w[(k+1)*256 + u];
                dh = d_Wq1_h; dl = d_Wq1_l; break;
            case 2:
                w0 = ln2_g[k] * q_w[k*256 + u]; w1 = ln2_g[k+1] * q_w[(k+1)*256 + u];
                dh = d_Wq2_h; dl = d_Wq2_l; break;
            case 3:
                w0 = k_w[k*256 + u]; w1 = k_w[(k+1)*256 + u];
                dh = d_Wk_h; dl = d_Wk_l; break;
            case 4:
                w0 = v_w[k*256 + u]; w1 = v_w[(k+1)*256 + u];
                dh = d_Wv_h; dl = d_Wv_l; break;
            default:
                w0 = pout_w[k*256 + u]; w1 = pout_w[(k+1)*256 + u];
                dh = d_Wpout_h; dl = d_Wpout_l; break;
            }
        } else if (w < 327680) {
            int idx = w - 196608;
            int u = idx >> 7, k2 = idx & 127;
            int k = k2 * 2;
            oidx = (size_t)u * 128 + k2;
            w0 = ln3_g[k] * ff1_w[k*1024 + u]; w1 = ln3_g[k+1] * ff1_w[(k+1)*1024 + u];
            dh = d_Wff1_h; dl = d_Wff1_l;
        } else {
            int idx = w - 327680;
            int u = idx >> 9, k2 = idx & 511;
            int k = k2 * 2;
            oidx = (size_t)u * 512 + k2;
            w0 = ff2_w[k*256 + u]; w1 = ff2_w[(k+1)*256 + u];
            dh = d_Wff2_h; dl = d_Wff2_l;
        }
        uint hi, lo; split_pair(w0, w1, hi, lo);
        dh[oidx] = hi; dl[oidx] = lo;
    } else if (blk < 5248) {
        int rel = blk - 1792;
        const float* s; uint *ph, *pl;
        if (rel < 1728) { s = x; ph = d_xhi; pl = d_xlo; }
        else { rel -= 1728; s = ctx; ph = d_cthi; pl = d_ctlo; }
        int i = rel * 256 + tid;
        float2 f = ((const float2*)s)[i];
        uint h, l; split_pair(f.x, f.y, h, l);
        ph[i] = h; pl[i] = l;
    } else {
        int gw = (blk - 5248) * 8 + (tid >> 5);
        int lane = tid & 31;
        float part = 0.f;
        int u;
        if (gw < 256) {
            u = gw;
            for (int k = lane; k < 256; k += 32) {
                float sc = rsqrtf(bn_v[k] + EPS_) * bn_g[k];
                part += (bn_b[k] - bn_m[k] * sc) * pin_w[k*256 + u];
            }
        } else if (gw < 512) {
            u = gw - 256;
            for (int k = lane; k < 256; k += 32) part += ln1_b[k] * q_w[k*256 + u];
        } else if (gw < 768) {
            u = gw - 512;
            for (int k = lane; k < 256; k += 32) part += ln2_b[k] * q_w[k*256 + u];
        } else {
            u = gw - 768;
            for (int k = lane; k < 256; k += 32) part += ln3_b[k] * ff1_w[k*1024 + u];
        }
        #pragma unroll
        for (int o = 16; o > 0; o >>= 1) part += __shfl_xor_sync(0xffffffffu, part, o);
        if (lane == 0) {
            if (gw < 256)      d_bpin[u] = pin_b[u] + part;
            else if (gw < 512) d_bq1[u]  = q_b[u]  + part;
            else if (gw < 768) d_bq2[u]  = q_b[u]  + part;
            else               d_bff1[u] = ff1_b[u] + part;
        }
    }
}

// ---------------- tensor-core batched GEMM: 64x128, K32 stages, ldmatrix ----
struct GOp {
    const uint* Ahi; const uint* Alo;
    const uint* Whi; const uint* Wlo;
    const float* bias; const float* resid;
    const float* sum1; const float* sum2; const float* sum3;
    float* out; uint* Ohi; uint* Olo;
    int N; int K; int flags; int tileStart;
};
struct GBatch { GOp op[8]; int nops; };

__global__ void __launch_bounds__(256, 2) gemmT(GBatch P)
{
    __shared__ __align__(16) uint As_hi[2][64][20],  As_lo[2][64][20];
    __shared__ __align__(16) uint Ws_hi[2][128][20], Ws_lo[2][128][20];

    int bid = blockIdx.x;
    int sel = 0;
    #pragma unroll
    for (int i = 1; i < 8; i++)
        if (i < P.nops && bid >= P.op[i].tileStart) sel = i;
    GOp g = P.op[sel];

    int local = bid - g.tileStart;
    int ntn = g.N >> 7;
    int mt = local / ntn;
    int nt = local - mt * ntn;
    int m0 = mt * 64, n0 = nt * 128;
    int tid = threadIdx.x;
    int warp = tid >> 5, lane = tid & 31;
    int gq = lane >> 2, t = lane & 3;
    int rw = warp & 3;
    int ch = warp >> 2;
    int K2 = g.K >> 1;

    int lrow = lane & 7, lm = lane >> 3;

    float acc[8][4];
    #pragma unroll
    for (int j = 0; j < 8; j++)
        #pragma unroll
        for (int i = 0; i < 4; i++) acc[j][i] = 0.f;

    int arow = tid >> 1;
    int aw0  = (tid & 1) * 8;
    int wrow = tid >> 1;
    int ww0  = (tid & 1) * 8;
    const size_t abase = (size_t)(m0 + arow) * K2 + aw0;
    const size_t wbase = (size_t)(n0 + wrow) * K2 + ww0;

    int nst = K2 >> 4;

    {
        if (tid < 128) {
            cp16(sa(&As_hi[0][arow][aw0]),   g.Ahi + abase);
            cp16(sa(&As_hi[0][arow][aw0+4]), g.Ahi + abase + 4);
            cp16(sa(&As_lo[0][arow][aw0]),   g.Alo + abase);
            cp16(sa(&As_lo[0][arow][aw0+4]), g.Alo + abase + 4);
        }
        cp16(sa(&Ws_hi[0][wrow][ww0]),   g.Whi + wbase);
        cp16(sa(&Ws_hi[0][wrow][ww0+4]), g.Whi + wbase + 4);
        cp16(sa(&Ws_lo[0][wrow][ww0]),   g.Wlo + wbase);
        cp16(sa(&Ws_lo[0][wrow][ww0+4]), g.Wlo + wbase + 4);
        CP_COMMIT();
    }

    int a_r = (rw << 4) + ((lm & 1) << 3) + lrow;
    int a_w = (lm >> 1) << 2;
    int b_rbase = (ch << 6) + ((lm >> 1) << 3) + lrow;
    int b_w = (lm & 1) << 2;

    for (int c = 0; c < nst; c++) {
        CP_WAIT0();
        __syncthreads();
        int pc = c + 1;
        if (pc < nst) {
            int nb = pc & 1;
            size_t off = (size_t)pc * 16;
            if (tid < 128) {
                cp16(sa(&As_hi[nb][arow][aw0]),   g.Ahi + abase + off);
                cp16(sa(&As_hi[nb][arow][aw0+4]), g.Ahi + abase + off + 4);
                cp16(sa(&As_lo[nb][arow][aw0]),   g.Alo + abase + off);
                cp16(sa(&As_lo[nb][arow][aw0+4]), g.Alo + abase + off + 4);
            }
            cp16(sa(&Ws_hi[nb][wrow][ww0]),   g.Whi + wbase + off);
            cp16(sa(&Ws_hi[nb][wrow][ww0+4]), g.Whi + wbase + off + 4);
            cp16(sa(&Ws_lo[nb][wrow][ww0]),   g.Wlo + wbase + off);
            cp16(sa(&Ws_lo[nb][wrow][ww0+4]), g.Wlo + wbase + off + 4);
        }
        CP_COMMIT();

        int bb = c & 1;
        #pragma unroll
        for (int hf = 0; hf < 2; hf++) {
            int wo = hf * 8;
            uint a0h, a1h, a2h, a3h, a0l, a1l, a2l, a3l;
            ldsm4(a0h, a1h, a2h, a3h, sa(&As_hi[bb][a_r][a_w + wo]));
            ldsm4(a0l, a1l, a2l, a3l, sa(&As_lo[bb][a_r][a_w + wo]));

            #pragma unroll
            for (int jp = 0; jp < 4; jp++) {
                uint bh0, bh1, bh2, bh3, bl0, bl1, bl2, bl3;
                ldsm4(bh0, bh1, bh2, bh3, sa(&Ws_hi[bb][b_rbase + jp*16][b_w + wo]));
                ldsm4(bl0, bl1, bl2, bl3, sa(&Ws_lo[bb][b_rbase + jp*16][b_w + wo]));
                mma_bf16(acc[jp*2  ], a0h, a1h, a2h, a3h, bh0, bh1);
                mma_bf16(acc[jp*2  ], a0h, a1h, a2h, a3h, bl0, bl1);
                mma_bf16(acc[jp*2  ], a0l, a1l, a2l, a3l, bh0, bh1);
                mma_bf16(acc[jp*2+1], a0h, a1h, a2h, a3h, bh2, bh3);
                mma_bf16(acc[jp*2+1], a0h, a1h, a2h, a3h, bl2, bl3);
                mma_bf16(acc[jp*2+1], a0l, a1l, a2l, a3l, bh2, bh3);
            }
        }
    }

    int K2o = g.N >> 1;
    int r0 = m0 + rw*16 + gq;
    int r1 = r0 + 8;
    #pragma unroll
    for (int j = 0; j < 8; j++) {
        int c0 = n0 + ch*64 + j*8 + 2*t;
        float b0 = g.bias[c0], b1 = g.bias[c0+1];
        float v00 = acc[j][0] + b0, v01 = acc[j][1] + b1;
        float v10 = acc[j][2] + b0, v11 = acc[j][3] + b1;
        if (g.flags & FRELU) {
            v00 = fmaxf(v00, 0.f); v01 = fmaxf(v01, 0.f);
            v10 = fmaxf(v10, 0.f); v11 = fmaxf(v11, 0.f);
        }
        if (g.flags & FRESID) {
            float2 ra = *(const float2*)&g.resid[(size_t)r0*g.N + c0];
            float2 rb = *(const float2*)&g.resid[(size_t)r1*g.N + c0];
            v00 += ra.x; v01 += ra.y; v10 += rb.x; v11 += rb.y;
        }
        if (g.flags & FSUM3) {
            float2 a1 = *(const float2*)&g.sum1[(size_t)r0*g.N + c0];
            float2 a2 = *(const float2*)&g.sum2[(size_t)r0*g.N + c0];
            float2 a3 = *(const float2*)&g.sum3[(size_t)r0*g.N + c0];
            v00 += a1.x + a2.x + a3.x; v01 += a1.y + a2.y + a3.y;
            float2 c1 = *(const float2*)&g.sum1[(size_t)r1*g.N + c0];
            float2 c2 = *(const float2*)&g.sum2[(size_t)r1*g.N + c0];
            float2 c3 = *(const float2*)&g.sum3[(size_t)r1*g.N + c0];
            v10 += c1.x + c2.x + c3.x; v11 += c1.y + c2.y + c3.y;
        }
        if (g.flags & FOUT) {
            *(float2*)&g.out[(size_t)r0*g.N + c0] = make_float2(v00, v01);
            *(float2*)&g.out[(size_t)r1*g.N + c0] = make_float2(v10, v11);
        }
        if (g.flags & FPLANES) {
            uint h, l;
            split_pair(v00, v01, h, l);
            g.Ohi[(size_t)r0*K2o + (c0>>1)] = h; g.Olo[(size_t)r0*K2o + (c0>>1)] = l;
            split_pair(v10, v11, h, l);
            g.Ohi[(size_t)r1*K2o + (c0>>1)] = h; g.Olo[(size_t)r1*K2o + (c0>>1)] = l;
        } else if (g.flags & FPLHI) {
            g.Ohi[(size_t)r0*K2o + (c0>>1)] = pack_hi(v00, v01);
            g.Ohi[(size_t)r1*K2o + (c0>>1)] = pack_hi(v10, v11);
        }
    }
}

// ---------------- LayerNorm -> planes ----------------------------------------
__global__ void __launch_bounds__(256) lnorm_kernel(const float* __restrict__ h,
                                                    uint* __restrict__ nhi,
                                                    uint* __restrict__ nlo)
{
    int row = blockIdx.x;
    int tid = threadIdx.x;
    float v = h[(size_t)row * 256 + tid];
    __shared__ float red[8];
    float s = v;
    #pragma unroll
    for (int o = 16; o > 0; o >>= 1) s += __shfl_xor_sync(0xffffffffu, s, o);
    if ((tid & 31) == 0) red[tid >> 5] = s;
    __syncthreads();
    float tot = 0.f;
    #pragma unroll
    for (int i = 0; i < 8; i++) tot += red[i];
    float mu = tot * (1.f / 256.f);
    float d = v - mu;
    float s2 = d * d;
    #pragma unroll
    for (int o = 16; o > 0; o >>= 1) s2 += __shfl_xor_sync(0xffffffffu, s2, o);
    __syncthreads();
    if ((tid & 31) == 0) red[tid >> 5] = s2;
    __syncthreads();
    float tot2 = 0.f;
    #pragma unroll
    for (int i = 0; i < 8; i++) tot2 += red[i];
    float var = tot2 * (1.f / 256.f);
    float o = d * rsqrtf(var + EPS_);
    float pn = __shfl_xor_sync(0xffffffffu, o, 1);
    if (!(tid & 1)) {
        uint hi, lo; split_pair(o, pn, hi, lo);
        nhi[(size_t)row * 128 + (tid >> 1)] = hi;
        nlo[(size_t)row * 128 + (tid >> 1)] = lo;
    }
}

// ---------------- V transpose into packed key-pair planes (hi only) ---------
__global__ void __launch_bounds__(128) vplanes_T(
    const float* __restrict__ V1, const float* __restrict__ V2,
    uint* __restrict__ vthi)
{
    __shared__ float Vs[64][33];
    int tid = threadIdx.x;
    int kt = blockIdx.x;
    int head = blockIdx.y;
    int br = blockIdx.z >> 1, b = blockIdx.z & 1;
    const float* V = br ? V2 : V1;
    #pragma unroll
    for (int i = 0; i < 4; i++) {
        int idx = tid + i * 128;
        int key = idx >> 3, f4 = (idx & 7) * 4;
        const float* p = &V[(size_t)(b * L_ + kt * 64 + key) * 256 + head * 32 + f4];
        float4 t4 = *(const float4*)p;
        Vs[key][f4] = t4.x; Vs[key][f4+1] = t4.y;
        Vs[key][f4+2] = t4.z; Vs[key][f4+3] = t4.w;
    }
    __syncthreads();
    int g = (br * 2 + b) * 8 + head;
    #pragma unroll
    for (int i = 0; i < 8; i++) {
        int widx = tid + i * 128;
        int d = widx >> 5, kp = widx & 31;
        size_t o = ((size_t)g * 32 + d) * 864 + kt * 32 + kp;
        vthi[o] = pack_hi(Vs[2*kp][d], Vs[2*kp+1][d]);
    }
}

// ---------------- tensor-core flash attention (QK x1, PV x2, static max) ----
__global__ void __launch_bounds__(128) attn_mma(
    const uint* __restrict__ Q1hi, const uint* __restrict__ K1hi,
    const uint* __restrict__ Q2hi, const uint* __restrict__ K2hi,
    const uint* __restrict__ VThi,
    float* __restrict__ O1, float* __restrict__ O2)
{
    __shared__ __align__(16) uint Khi[3][64][20];
    __shared__ __align__(16) uint Vhi[3][32][36];

    int tid = threadIdx.x, warp = tid >> 5, lane = tid & 31;
    int gq = lane >> 2, t = lane & 3;
    int lrow = lane & 7, lm = lane >> 3;
    int qt = blockIdx.x, head = blockIdx.y;
    int br = blockIdx.z >> 1, b = blockIdx.z & 1;
    const uint* Qhi = br ? Q2hi : Q1hi;
    const uint* KhG = br ? K2hi : K1hi;
    float* Ob = br ? O2 : O1;
    const float scale2 = 0.0625f * 1.44269504089f;
    const float MSTAT  = 12.0f;

    int vg = (br * 2 + b) * 8 + head;

    int fkey = tid >> 1;
    int fkw  = (tid & 1) * 8;
    int fd   = tid >> 2;
    int fvw  = (tid & 3) * 8;
    const size_t kbase = (size_t)(b * L_ + fkey) * 128 + head * 16 + fkw;
    const size_t vbase = ((size_t)vg * 32 + fd) * 864 + fvw;

    #pragma unroll
    for (int s = 0; s < 2; s++) {
        size_t ko = kbase + (size_t)s * 64 * 128;
        size_t vo = vbase + (size_t)s * 32;
        cp16(sa(&Khi[s][fkey][fkw]),   KhG + ko);
        cp16(sa(&Khi[s][fkey][fkw+4]), KhG + ko + 4);
        cp16(sa(&Vhi[s][fd][fvw]),     VThi + vo);
        cp16(sa(&Vhi[s][fd][fvw+4]),   VThi + vo + 4);
        CP_COMMIT();
    }

    int r0 = qt * 64 + warp * 16 + gq;
    int r1 = r0 + 8;

    uint qh[2][4];
    {
        size_t q0 = (size_t)(b * L_ + r0) * 128 + head * 16;
        size_t q1 = (size_t)(b * L_ + r1) * 128 + head * 16;
        #pragma unroll
        for (int ks = 0; ks < 2; ks++) {
            qh[ks][0] = Qhi[q0 + ks*8 + t];     qh[ks][1] = Qhi[q1 + ks*8 + t];
            qh[ks][2] = Qhi[q0 + ks*8 + t + 4]; qh[ks][3] = Qhi[q1 + ks*8 + t + 4];
        }
    }

    float Oacc[4][4];
    #pragma unroll
    for (int j = 0; j < 4; j++)
        #pragma unroll
        for (int i = 0; i < 4; i++) Oacc[j][i] = 0.f;
    float l0r = 0.f, l1r = 0.f;

    int klw = lm << 2;

    for (int kt = 0; kt < NKT; kt++) {
        CP_WAIT1();
        __syncthreads();
        int pt = kt + 2;
        if (pt < NKT) {
            int nb = pt % 3;
            size_t ko = kbase + (size_t)pt * 64 * 128;
            size_t vo = vbase + (size_t)pt * 32;
            cp16(sa(&Khi[nb][fkey][fkw]),   KhG + ko);
            cp16(sa(&Khi[nb][fkey][fkw+4]), KhG + ko + 4);
            cp16(sa(&Vhi[nb][fd][fvw]),     VThi + vo);
            cp16(sa(&Vhi[nb][fd][fvw+4]),   VThi + vo + 4);
        }
        CP_COMMIT();
        int bb = kt % 3;

        // S = Q K^T (x1: qh*kh)
        float s[8][4];
        #pragma unroll
        for (int j = 0; j < 8; j++) {
            s[j][0] = s[j][1] = s[j][2] = s[j][3] = 0.f;
            uint kh0, kh1, kh2, kh3;
            ldsm4(kh0, kh1, kh2, kh3, sa(&Khi[bb][j*8 + lrow][klw]));
            mma_bf16(s[j], qh[0][0], qh[0][1], qh[0][2], qh[0][3], kh0, kh1);
            mma_bf16(s[j], qh[1][0], qh[1][1], qh[1][2], qh[1][3], kh2, kh3);
            s[j][0] = ex2(fmaf(s[j][0], scale2, -MSTAT)); l0r += s[j][0];
            s[j][1] = ex2(fmaf(s[j][1], scale2, -MSTAT)); l0r += s[j][1];
            s[j][2] = ex2(fmaf(s[j][2], scale2, -MSTAT)); l1r += s[j][2];
            s[j][3] = ex2(fmaf(s[j][3], scale2, -MSTAT)); l1r += s[j][3];
        }

        // P -> bf16x2 fragments (keep P rounding correction)
        uint ph[4][4], pl[4][4];
        #pragma unroll
        for (int ks = 0; ks < 4; ks++) {
            split_pair(s[2*ks  ][0], s[2*ks  ][1], ph[ks][0], pl[ks][0]);
            split_pair(s[2*ks  ][2], s[2*ks  ][3], ph[ks][1], pl[ks][1]);
            split_pair(s[2*ks+1][0], s[2*ks+1][1], ph[ks][2], pl[ks][2]);
            split_pair(s[2*ks+1][2], s[2*ks+1][3], ph[ks][3], pl[ks][3]);
        }

        // O += P V (x2: (ph+pl) * vh)
        #pragma unroll
        for (int jn = 0; jn < 4; jn++) {
            #pragma unroll
            for (int h2 = 0; h2 < 2; h2++) {
                uint vh0, vh1, vh2, vh3;
                ldsm4(vh0, vh1, vh2, vh3, sa(&Vhi[bb][jn*8 + lrow][(h2<<4) + klw]));
                int ka = 2*h2, kb2 = 2*h2 + 1;
                mma_bf16(Oacc[jn], ph[ka][0], ph[ka][1], ph[ka][2], ph[ka][3], vh0, vh1);
                mma_bf16(Oacc[jn], pl[ka][0], pl[ka][1], pl[ka][2], pl[ka][3], vh0, vh1);
                mma_bf16(Oacc[jn], ph[kb2][0], ph[kb2][1], ph[kb2][2], ph[kb2][3], vh2, vh3);
                mma_bf16(Oacc[jn], pl[kb2][0], pl[kb2][1], pl[kb2][2], pl[kb2][3], vh2, vh3);
            }
        }
    }

    l0r += __shfl_xor_sync(0xffffffffu, l0r, 1);
    l0r += __shfl_xor_sync(0xffffffffu, l0r, 2);
    l1r += __shfl_xor_sync(0xffffffffu, l1r, 1);
    l1r += __shfl_xor_sync(0xffffffffu, l1r, 2);

    float inv0 = 1.f / l0r, inv1 = 1.f / l1r;
    #pragma unroll
    for (int jn = 0; jn < 4; jn++) {
        int col = head * 32 + jn * 8 + 2 * t;
        *(float2*)&Ob[(size_t)(b * L_ + r0) * 256 + col] =
            make_float2(Oacc[jn][0] * inv0, Oacc[jn][1] * inv0);
        *(float2*)&Ob[(size_t)(b * L_ + r1) * 256 + col] =
            make_float2(Oacc[jn][2] * inv1, Oacc[jn][3] * inv1);
    }
}

// ---------------- launch --------------------------------------------------------
extern "C" void kernel_launch(void* const* d_in, const int* in_sizes, int n_in,
                              void* d_out, int out_size)
{
    const float* x       = (const float*)d_in[0];
    const float* context = (const float*)d_in[1];
    const float* bn_g = (const float*)d_in[2];
    const float* bn_b = (const float*)d_in[3];
    const float* bn_m = (const float*)d_in[4];
    const float* bn_v = (const float*)d_in[5];
    const float* ln1_g = (const float*)d_in[6];
    const float* ln1_b = (const float*)d_in[7];
    const float* ln2_g = (const float*)d_in[8];
    const float* ln2_b = (const float*)d_in[9];
    const float* ln3_g = (const float*)d_in[10];
    const float* ln3_b = (const float*)d_in[11];
    const float* pin_w = (const float*)d_in[12];
    const float* pin_b = (const float*)d_in[13];
    const float* q_w   = (const float*)d_in[14];
    const float* q_b   = (const float*)d_in[15];
    const float* k_w   = (const float*)d_in[16];
    const float* k_b   = (const float*)d_in[17];
    const float* v_w   = (const float*)d_in[18];
    const float* v_b   = (const float*)d_in[19];
    const float* ff1_w = (const float*)d_in[20];
    const float* ff1_b = (const float*)d_in[21];
    const float* ff2_w = (const float*)d_in[22];
    const float* ff2_b = (const float*)d_in[23];
    const float* pout_w = (const float*)d_in[24];
    const float* pout_b = (const float*)d_in[25];
    float* out = (float*)d_out;

    float *p_h, *p_v1, *p_v2, *p_O1, *p_O2;
    uint *p_xhi, *p_xlo, *p_cthi, *p_ctlo, *p_hhi, *p_hlo, *p_nhi, *p_nlo;
    uint *p_f1hi, *p_f1lo, *p_ahi, *p_alo;
    uint *p_q1hi, *p_k1hi, *p_q2hi, *p_k2hi;
    uint *p_vthi;
    uint *w_pin_h, *w_pin_l, *w_q1_h, *w_q1_l, *w_q2_h, *w_q2_l;
    uint *w_k_h, *w_k_l, *w_v_h, *w_v_l, *w_po_h, *w_po_l;
    uint *w_f1_h, *w_f1_l, *w_f2_h, *w_f2_l;
    float *p_bpin, *p_bq1, *p_bq2, *p_bff1;

    cudaGetSymbolAddress((void**)&p_h,    d_h);
    cudaGetSymbolAddress((void**)&p_v1,   d_v1);
    cudaGetSymbolAddress((void**)&p_v2,   d_v2);
    cudaGetSymbolAddress((void**)&p_O1,   d_O1);
    cudaGetSymbolAddress((void**)&p_O2,   d_O2);
    cudaGetSymbolAddress((void**)&p_xhi,  d_xhi);
    cudaGetSymbolAddress((void**)&p_xlo,  d_xlo);
    cudaGetSymbolAddress((void**)&p_cthi, d_cthi);
    cudaGetSymbolAddress((void**)&p_ctlo, d_ctlo);
    cudaGetSymbolAddress((void**)&p_hhi,  d_hhi);
    cudaGetSymbolAddress((void**)&p_hlo,  d_hlo);
    cudaGetSymbolAddress((void**)&p_nhi,  d_nhi);
    cudaGetSymbolAddress((void**)&p_nlo,  d_nlo);
    cudaGetSymbolAddress((void**)&p_f1hi, d_f1hi);
    cudaGetSymbolAddress((void**)&p_f1lo, d_f1lo);
    cudaGetSymbolAddress((void**)&p_ahi,  d_ahi);
    cudaGetSymbolAddress((void**)&p_alo,  d_alo);
    cudaGetSymbolAddress((void**)&p_q1hi, d_q1hi);
    cudaGetSymbolAddress((void**)&p_k1hi, d_k1hi);
    cudaGetSymbolAddress((void**)&p_q2hi, d_q2hi);
    cudaGetSymbolAddress((void**)&p_k2hi, d_k2hi);
    cudaGetSymbolAddress((void**)&p_vthi, d_vthi);
    cudaGetSymbolAddress((void**)&w_pin_h, d_Wpin_h);
    cudaGetSymbolAddress((void**)&w_pin_l, d_Wpin_l);
    cudaGetSymbolAddress((void**)&w_q1_h,  d_Wq1_h);
    cudaGetSymbolAddress((void**)&w_q1_l,  d_Wq1_l);
    cudaGetSymbolAddress((void**)&w_q2_h,  d_Wq2_h);
    cudaGetSymbolAddress((void**)&w_q2_l,  d_Wq2_l);
    cudaGetSymbolAddress((void**)&w_k_h,   d_Wk_h);
    cudaGetSymbolAddress((void**)&w_k_l,   d_Wk_l);
    cudaGetSymbolAddress((void**)&w_v_h,   d_Wv_h);
    cudaGetSymbolAddress((void**)&w_v_l,   d_Wv_l);
    cudaGetSymbolAddress((void**)&w_po_h,  d_Wpout_h);
    cudaGetSymbolAddress((void**)&w_po_l,  d_Wpout_l);
    cudaGetSymbolAddress((void**)&w_f1_h,  d_Wff1_h);
    cudaGetSymbolAddress((void**)&w_f1_l,  d_Wff1_l);
    cudaGetSymbolAddress((void**)&w_f2_h,  d_Wff2_h);
    cudaGetSymbolAddress((void**)&w_f2_l,  d_Wff2_l);
    cudaGetSymbolAddress((void**)&p_bpin,  d_bpin);
    cudaGetSymbolAddress((void**)&p_bq1,   d_bq1);
    cudaGetSymbolAddress((void**)&p_bq2,   d_bq2);
    cudaGetSymbolAddress((void**)&p_bff1,  d_bff1);

    // 1. all prep
    prep_all<<<5472, 256>>>(x, context, bn_g, bn_b, bn_m, bn_v,
                            ln1_g, ln1_b, ln2_g, ln2_b, ln3_g, ln3_b,
                            pin_w, pin_b, q_w, q_b, k_w, v_w,
                            ff1_w, ff1_b, ff2_w, pout_w);

    auto mkop = [](const uint* Ahi, const uint* Alo, const uint* Whi, const uint* Wlo,
                   const float* bias, const float* resid, float* o,
                   uint* Ohi, uint* Olo, int N, int K, int flags, int start) {
        GOp g = {};
        g.Ahi = Ahi; g.Alo = Alo; g.Whi = Whi; g.Wlo = Wlo;
        g.bias = bias; g.resid = resid; g.out = o; g.Ohi = Ohi; g.Olo = Olo;
        g.N = N; g.K = K; g.flags = flags; g.tileStart = start;
        return g;
    };
    const int RT = NTOK / 64;
    const int T256 = RT * 2;

    // 2. batch A: pin + k2 + v2
    {
        GBatch P = {};
        P.op[0] = mkop(p_xhi, p_xlo, w_pin_h, w_pin_l, p_bpin, nullptr,
                       p_h, p_hhi, p_hlo, 256, 256, FOUT | FRELU | FPLANES, 0);
        P.op[1] = mkop(p_cthi, p_ctlo, w_k_h, w_k_l, k_b, nullptr,
                       nullptr, p_k2hi, nullptr, 256, 256, FPLHI, T256);
        P.op[2] = mkop(p_cthi, p_ctlo, w_v_h, w_v_l, v_b, nullptr,
                       p_v2, nullptr, nullptr, 256, 256, FOUT, T256*2);
        P.nops = 3;
        gemmT<<<T256*3, 256>>>(P);
    }

    // 3. hhat planes
    lnorm_kernel<<<NTOK, 256>>>(p_h, p_nhi, p_nlo);

    // 4. batch B: q1, k1, v1, q2, ff1
    {
        GBatch P = {};
        P.op[0] = mkop(p_nhi, p_nlo, w_q1_h, w_q1_l, p_bq1, nullptr,
                       nullptr, p_q1hi, nullptr, 256, 256, FPLHI, 0);
        P.op[1] = mkop(p_hhi, p_hlo, w_k_h, w_k_l, k_b, nullptr,
                       nullptr, p_k1hi, nullptr, 256, 256, FPLHI, T256);
        P.op[2] = mkop(p_hhi, p_hlo, w_v_h, w_v_l, v_b, nullptr,
                       p_v1, nullptr, nullptr, 256, 256, FOUT, T256*2);
        P.op[3] = mkop(p_nhi, p_nlo, w_q2_h, w_q2_l, p_bq2, nullptr,
                       nullptr, p_q2hi, nullptr, 256, 256, FPLHI, T256*3);
        P.op[4] = mkop(p_nhi, p_nlo, w_f1_h, w_f1_l, p_bff1, nullptr,
                       nullptr, p_f1hi, p_f1lo, 1024, 256, FRELU | FPLANES, T256*4);
        P.nops = 5;
        gemmT<<<T256*4 + RT*8, 256>>>(P);
    }

    // 5. V transpose planes (hi only)
    {
        dim3 gv(NKT, H_, 4);
        vplanes_T<<<gv, 128>>>(p_v1, p_v2, p_vthi);
    }

    // 6. attention (QK x1, PV x2)
    {
        dim3 ga(NKT, H_, 4);
        attn_mma<<<ga, 128>>>(p_q1hi, p_k1hi, p_q2hi, p_k2hi,
                              p_vthi, p_O1, p_O2);
    }

    // 7. ff2 + combine fused
    {
        GBatch P = {};
        P.op[0] = mkop(p_f1hi, p_f1lo, w_f2_h, w_f2_l, ff2_b, nullptr,
                       nullptr, p_ahi, p_alo, 256, 1024, FSUM3 | FPLANES, 0);
        P.op[0].sum1 = p_h;
        P.op[0].sum2 = p_O1;
        P.op[0].sum3 = p_O2;
        P.nops = 1;
        gemmT<<<T256, 256>>>(P);
    }

    // 8. out = relu(acc @ pout + b) + x
    {
        GBatch P = {};
        P.op[0] = mkop(p_ahi, p_alo, w_po_h, w_po_l, pout_b, x,
                       out, nullptr, nullptr, 256, 256, FOUT | FRELU | FRESID, 0);
        P.nops = 1;
        gemmT<<<T256, 256>>>(P);
    }
}

// round 15
// speedup vs baseline: 1.6216x; 1.1630x over previous
#include <cuda_runtime.h>
#include <math.h>

typedef unsigned long long ull;
typedef unsigned int uint;

#define B_    2
#define L_    1728
#define NTOK  3456
#define C_    256
#define U_    256
#define H_    8
#define HD    32
#define FF_   1024
#define EPS_  1e-3f
#define NKT   27

#define FRELU   1
#define FRESID  2
#define FPLANES 4
#define FOUT    8
#define FSUM3   16
#define FPLHI   32
#define FX2     64

// ---------------- cp.async helpers ------------------------------------------
__device__ __forceinline__ void cp16(uint saddr, const void* gptr) {
    asm volatile("cp.async.cg.shared.global [%0], [%1], 16;" :: "r"(saddr), "l"(gptr));
}
__device__ __forceinline__ uint sa(const void* p) {
    return (uint)__cvta_generic_to_shared(p);
}
#define CP_COMMIT() asm volatile("cp.async.commit_group;")
#define CP_WAIT0()  asm volatile("cp.async.wait_group 0;")
#define CP_WAIT1()  asm volatile("cp.async.wait_group 1;")

// ---------------- ldmatrix ----------------------------------------------------
__device__ __forceinline__ void ldsm4(uint& r0, uint& r1, uint& r2, uint& r3, uint saddr) {
    asm volatile("ldmatrix.sync.aligned.m8n8.x4.shared.b16 {%0,%1,%2,%3}, [%4];"
                 : "=r"(r0), "=r"(r1), "=r"(r2), "=r"(r3) : "r"(saddr));
}

// ---------------- fast exp2 --------------------------------------------------
__device__ __forceinline__ float ex2(float x) {
    float y; asm("ex2.approx.f32 %0,%1;" : "=f"(y) : "f"(x)); return y;
}

// ---------------- bf16 split helpers ---------------------------------------
__device__ __forceinline__ uint bf16_of(float f) {
    unsigned short u; asm("cvt.rn.bf16.f32 %0,%1;" : "=h"(u) : "f"(f));
    return (uint)u;
}
__device__ __forceinline__ void split_pair(float f0, float f1, uint& hi, uint& lo) {
    uint h0 = bf16_of(f0), h1 = bf16_of(f1);
    hi = h0 | (h1 << 16);
    float r0 = f0 - __uint_as_float(h0 << 16);
    float r1 = f1 - __uint_as_float(h1 << 16);
    lo = bf16_of(r0) | (bf16_of(r1) << 16);
}
__device__ __forceinline__ uint pack_hi(float f0, float f1) {
    return bf16_of(f0) | (bf16_of(f1) << 16);
}

// ---------------- mma m16n8k16 bf16 -----------------------------------------
__device__ __forceinline__ void mma_bf16(float* c, uint a0, uint a1, uint a2, uint a3,
                                         uint b0, uint b1) {
    asm volatile("mma.sync.aligned.m16n8k16.row.col.f32.bf16.bf16.f32 "
                 "{%0,%1,%2,%3},{%4,%5,%6,%7},{%8,%9},{%0,%1,%2,%3};"
                 : "+f"(c[0]), "+f"(c[1]), "+f"(c[2]), "+f"(c[3])
                 : "r"(a0), "r"(a1), "r"(a2), "r"(a3), "r"(b0), "r"(b1));
}

// ---------------- scratch ---------------------------------------------------
__device__ float d_h   [NTOK*U_];
__device__ float d_v1  [NTOK*U_];
__device__ float d_v2  [NTOK*U_];
__device__ float d_O1  [NTOK*U_];
__device__ float d_O2  [NTOK*U_];

__device__ uint d_xhi [NTOK*128], d_xlo [NTOK*128];
__device__ uint d_cthi[NTOK*128], d_ctlo[NTOK*128];
__device__ uint d_hhi [NTOK*128], d_hlo [NTOK*128];
__device__ uint d_nhi [NTOK*128], d_nlo [NTOK*128];
__device__ uint d_f1hi[NTOK*512], d_f1lo[NTOK*512];
__device__ uint d_ahi [NTOK*128], d_alo [NTOK*128];
__device__ uint d_q1hi[NTOK*128];
__device__ uint d_k1hi[NTOK*128];
__device__ uint d_q2hi[NTOK*128];
__device__ uint d_k2hi[NTOK*128];
__device__ uint d_vthi[32*32*864];

__device__ uint d_Wpin_h[256*128], d_Wpin_l[256*128];
__device__ uint d_Wq1_h [256*128], d_Wq1_l [256*128];
__device__ uint d_Wq2_h [256*128], d_Wq2_l [256*128];
__device__ uint d_Wk_h  [256*128], d_Wk_l  [256*128];
__device__ uint d_Wv_h  [256*128], d_Wv_l  [256*128];
__device__ uint d_Wpout_h[256*128], d_Wpout_l[256*128];
__device__ uint d_Wff1_h[1024*128], d_Wff1_l[1024*128];
__device__ uint d_Wff2_h[256*512],  d_Wff2_l[256*512];

__device__ float d_bpin[U_], d_bq1[U_], d_bq2[U_], d_bff1[FF_];

// ---------------- prep_all (one launch) --------------------------------------
__global__ void __launch_bounds__(256) prep_all(
    const float* __restrict__ x,    const float* __restrict__ ctx,
    const float* __restrict__ bn_g, const float* __restrict__ bn_b,
    const float* __restrict__ bn_m, const float* __restrict__ bn_v,
    const float* __restrict__ ln1_g, const float* __restrict__ ln1_b,
    const float* __restrict__ ln2_g, const float* __restrict__ ln2_b,
    const float* __restrict__ ln3_g, const float* __restrict__ ln3_b,
    const float* __restrict__ pin_w, const float* __restrict__ pin_b,
    const float* __restrict__ q_w,  const float* __restrict__ q_b,
    const float* __restrict__ k_w,  const float* __restrict__ v_w,
    const float* __restrict__ ff1_w, const float* __restrict__ ff1_b,
    const float* __restrict__ ff2_w, const float* __restrict__ pout_w)
{
    int blk = blockIdx.x;
    int tid = threadIdx.x;

    if (blk < 1792) {
        int w = blk * 256 + tid;
        float w0, w1;
        uint *dh, *dl;
        size_t oidx;
        if (w < 196608) {
            int r = w >> 15;
            int idx = w & 32767;
            int u = idx >> 7, k2 = idx & 127;
            int k = k2 * 2;
            oidx = (size_t)u * 128 + k2;
            switch (r) {
            case 0: {
                float s0 = rsqrtf(bn_v[k] + EPS_) * bn_g[k];
                float s1 = rsqrtf(bn_v[k+1] + EPS_) * bn_g[k+1];
                w0 = s0 * pin_w[k*256 + u]; w1 = s1 * pin_w[(k+1)*256 + u];
                dh = d_Wpin_h; dl = d_Wpin_l; } break;
            case 1:
                w0 = ln1_g[k] * q_w[k*256 + u]; w1 = ln1_g[k+1] * q_w[(k+1)*256 + u];
                dh = d_Wq1_h; dl = d_Wq1_l; break;
            case 2:
                w0 = ln2_g[k] * q_w[k*256 + u]; w1 = ln2_g[k+1] * q_w[(k+1)*256 + u];
                dh = d_Wq2_h; dl = d_Wq2_l; break;
            case 3:
                w0 = k_w[k*256 + u]; w1 = k_w[(k+1)*256 + u];
                dh = d_Wk_h; dl = d_Wk_l; break;
            case 4:
                w0 = v_w[k*256 + u]; w1 = v_w[(k+1)*256 + u];
                dh = d_Wv_h; dl = d_Wv_l; break;
            default:
                w0 = pout_w[k*256 + u]; w1 = pout_w[(k+1)*256 + u];
                dh = d_Wpout_h; dl = d_Wpout_l; break;
            }
        } else if (w < 327680) {
            int idx = w - 196608;
            int u = idx >> 7, k2 = idx & 127;
            int k = k2 * 2;
            oidx = (size_t)u * 128 + k2;
            w0 = ln3_g[k] * ff1_w[k*1024 + u]; w1 = ln3_g[k+1] * ff1_w[(k+1)*1024 + u];
            dh = d_Wff1_h; dl = d_Wff1_l;
        } else {
            int idx = w - 327680;
            int u = idx >> 9, k2 = idx & 511;
            int k = k2 * 2;
            oidx = (size_t)u * 512 + k2;
            w0 = ff2_w[k*256 + u]; w1 = ff2_w[(k+1)*256 + u];
            dh = d_Wff2_h; dl = d_Wff2_l;
        }
        uint hi, lo; split_pair(w0, w1, hi, lo);
        dh[oidx] = hi; dl[oidx] = lo;
    } else if (blk < 5248) {
        int rel = blk - 1792;
        const float* s; uint *ph, *pl;
        if (rel < 1728) { s = x; ph = d_xhi; pl = d_xlo; }
        else { rel -= 1728; s = ctx; ph = d_cthi; pl = d_ctlo; }
        int i = rel * 256 + tid;
        float2 f = ((const float2*)s)[i];
        uint h, l; split_pair(f.x, f.y, h, l);
        ph[i] = h; pl[i] = l;
    } else {
        int gw = (blk - 5248) * 8 + (tid >> 5);
        int lane = tid & 31;
        float part = 0.f;
        int u;
        if (gw < 256) {
            u = gw;
            for (int k = lane; k < 256; k += 32) {
                float sc = rsqrtf(bn_v[k] + EPS_) * bn_g[k];
                part += (bn_b[k] - bn_m[k] * sc) * pin_w[k*256 + u];
            }
        } else if (gw < 512) {
            u = gw - 256;
            for (int k = lane; k < 256; k += 32) part += ln1_b[k] * q_w[k*256 + u];
        } else if (gw < 768) {
            u = gw - 512;
            for (int k = lane; k < 256; k += 32) part += ln2_b[k] * q_w[k*256 + u];
        } else {
            u = gw - 768;
            for (int k = lane; k < 256; k += 32) part += ln3_b[k] * ff1_w[k*1024 + u];
        }
        #pragma unroll
        for (int o = 16; o > 0; o >>= 1) part += __shfl_xor_sync(0xffffffffu, part, o);
        if (lane == 0) {
            if (gw < 256)      d_bpin[u] = pin_b[u] + part;
            else if (gw < 512) d_bq1[u]  = q_b[u]  + part;
            else if (gw < 768) d_bq2[u]  = q_b[u]  + part;
            else               d_bff1[u] = ff1_b[u] + part;
        }
    }
}

// ---------------- tensor-core batched GEMM: 64x128, K32 stages, ldmatrix ----
struct GOp {
    const uint* Ahi; const uint* Alo;
    const uint* Whi; const uint* Wlo;
    const float* bias; const float* resid;
    const float* sum1; const float* sum2; const float* sum3;
    float* out; uint* Ohi; uint* Olo;
    int N; int K; int flags; int tileStart;
};
struct GBatch { GOp op[8]; int nops; };

__global__ void __launch_bounds__(256, 2) gemmT(GBatch P)
{
    __shared__ __align__(16) uint As_hi[2][64][20],  As_lo[2][64][20];
    __shared__ __align__(16) uint Ws_hi[2][128][20], Ws_lo[2][128][20];

    int bid = blockIdx.x;
    int sel = 0;
    #pragma unroll
    for (int i = 1; i < 8; i++)
        if (i < P.nops && bid >= P.op[i].tileStart) sel = i;
    GOp g = P.op[sel];
    bool x2 = (g.flags & FX2) != 0;

    int local = bid - g.tileStart;
    int ntn = g.N >> 7;
    int mt = local / ntn;
    int nt = local - mt * ntn;
    int m0 = mt * 64, n0 = nt * 128;
    int tid = threadIdx.x;
    int warp = tid >> 5, lane = tid & 31;
    int gq = lane >> 2, t = lane & 3;
    int rw = warp & 3;
    int ch = warp >> 2;
    int K2 = g.K >> 1;

    int lrow = lane & 7, lm = lane >> 3;

    float acc[8][4];
    #pragma unroll
    for (int j = 0; j < 8; j++)
        #pragma unroll
        for (int i = 0; i < 4; i++) acc[j][i] = 0.f;

    int arow = tid >> 1;
    int aw0  = (tid & 1) * 8;
    int wrow = tid >> 1;
    int ww0  = (tid & 1) * 8;
    const size_t abase = (size_t)(m0 + arow) * K2 + aw0;
    const size_t wbase = (size_t)(n0 + wrow) * K2 + ww0;

    int nst = K2 >> 4;

    {
        if (tid < 128) {
            cp16(sa(&As_hi[0][arow][aw0]),   g.Ahi + abase);
            cp16(sa(&As_hi[0][arow][aw0+4]), g.Ahi + abase + 4);
            if (!x2) {
                cp16(sa(&As_lo[0][arow][aw0]),   g.Alo + abase);
                cp16(sa(&As_lo[0][arow][aw0+4]), g.Alo + abase + 4);
            }
        }
        cp16(sa(&Ws_hi[0][wrow][ww0]),   g.Whi + wbase);
        cp16(sa(&Ws_hi[0][wrow][ww0+4]), g.Whi + wbase + 4);
        cp16(sa(&Ws_lo[0][wrow][ww0]),   g.Wlo + wbase);
        cp16(sa(&Ws_lo[0][wrow][ww0+4]), g.Wlo + wbase + 4);
        CP_COMMIT();
    }

    int a_r = (rw << 4) + ((lm & 1) << 3) + lrow;
    int a_w = (lm >> 1) << 2;
    int b_rbase = (ch << 6) + ((lm >> 1) << 3) + lrow;
    int b_w = (lm & 1) << 2;

    for (int c = 0; c < nst; c++) {
        CP_WAIT0();
        __syncthreads();
        int pc = c + 1;
        if (pc < nst) {
            int nb = pc & 1;
            size_t off = (size_t)pc * 16;
            if (tid < 128) {
                cp16(sa(&As_hi[nb][arow][aw0]),   g.Ahi + abase + off);
                cp16(sa(&As_hi[nb][arow][aw0+4]), g.Ahi + abase + off + 4);
                if (!x2) {
                    cp16(sa(&As_lo[nb][arow][aw0]),   g.Alo + abase + off);
                    cp16(sa(&As_lo[nb][arow][aw0+4]), g.Alo + abase + off + 4);
                }
            }
            cp16(sa(&Ws_hi[nb][wrow][ww0]),   g.Whi + wbase + off);
            cp16(sa(&Ws_hi[nb][wrow][ww0+4]), g.Whi + wbase + off + 4);
            cp16(sa(&Ws_lo[nb][wrow][ww0]),   g.Wlo + wbase + off);
            cp16(sa(&Ws_lo[nb][wrow][ww0+4]), g.Wlo + wbase + off + 4);
        }
        CP_COMMIT();

        int bb = c & 1;
        #pragma unroll
        for (int hf = 0; hf < 2; hf++) {
            int wo = hf * 8;
            uint a0h, a1h, a2h, a3h;
            ldsm4(a0h, a1h, a2h, a3h, sa(&As_hi[bb][a_r][a_w + wo]));
            uint a0l = 0, a1l = 0, a2l = 0, a3l = 0;
            if (!x2) ldsm4(a0l, a1l, a2l, a3l, sa(&As_lo[bb][a_r][a_w + wo]));

            #pragma unroll
            for (int jp = 0; jp < 4; jp++) {
                uint bh0, bh1, bh2, bh3, bl0, bl1, bl2, bl3;
                ldsm4(bh0, bh1, bh2, bh3, sa(&Ws_hi[bb][b_rbase + jp*16][b_w + wo]));
                ldsm4(bl0, bl1, bl2, bl3, sa(&Ws_lo[bb][b_rbase + jp*16][b_w + wo]));
                mma_bf16(acc[jp*2  ], a0h, a1h, a2h, a3h, bh0, bh1);
                mma_bf16(acc[jp*2  ], a0h, a1h, a2h, a3h, bl0, bl1);
                mma_bf16(acc[jp*2+1], a0h, a1h, a2h, a3h, bh2, bh3);
                mma_bf16(acc[jp*2+1], a0h, a1h, a2h, a3h, bl2, bl3);
                if (!x2) {
                    mma_bf16(acc[jp*2  ], a0l, a1l, a2l, a3l, bh0, bh1);
                    mma_bf16(acc[jp*2+1], a0l, a1l, a2l, a3l, bh2, bh3);
                }
            }
        }
    }

    int K2o = g.N >> 1;
    int r0 = m0 + rw*16 + gq;
    int r1 = r0 + 8;
    #pragma unroll
    for (int j = 0; j < 8; j++) {
        int c0 = n0 + ch*64 + j*8 + 2*t;
        float b0 = g.bias[c0], b1 = g.bias[c0+1];
        float v00 = acc[j][0] + b0, v01 = acc[j][1] + b1;
        float v10 = acc[j][2] + b0, v11 = acc[j][3] + b1;
        if (g.flags & FRELU) {
            v00 = fmaxf(v00, 0.f); v01 = fmaxf(v01, 0.f);
            v10 = fmaxf(v10, 0.f); v11 = fmaxf(v11, 0.f);
        }
        if (g.flags & FRESID) {
            float2 ra = *(const float2*)&g.resid[(size_t)r0*g.N + c0];
            float2 rb = *(const float2*)&g.resid[(size_t)r1*g.N + c0];
            v00 += ra.x; v01 += ra.y; v10 += rb.x; v11 += rb.y;
        }
        if (g.flags & FSUM3) {
            float2 a1 = *(const float2*)&g.sum1[(size_t)r0*g.N + c0];
            float2 a2 = *(const float2*)&g.sum2[(size_t)r0*g.N + c0];
            float2 a3 = *(const float2*)&g.sum3[(size_t)r0*g.N + c0];
            v00 += a1.x + a2.x + a3.x; v01 += a1.y + a2.y + a3.y;
            float2 c1 = *(const float2*)&g.sum1[(size_t)r1*g.N + c0];
            float2 c2 = *(const float2*)&g.sum2[(size_t)r1*g.N + c0];
            float2 c3 = *(const float2*)&g.sum3[(size_t)r1*g.N + c0];
            v10 += c1.x + c2.x + c3.x; v11 += c1.y + c2.y + c3.y;
        }
        if (g.flags & FOUT) {
            *(float2*)&g.out[(size_t)r0*g.N + c0] = make_float2(v00, v01);
            *(float2*)&g.out[(size_t)r1*g.N + c0] = make_float2(v10, v11);
        }
        if (g.flags & FPLANES) {
            uint h, l;
            split_pair(v00, v01, h, l);
            g.Ohi[(size_t)r0*K2o + (c0>>1)] = h; g.Olo[(size_t)r0*K2o + (c0>>1)] = l;
            split_pair(v10, v11, h, l);
            g.Ohi[(size_t)r1*K2o + (c0>>1)] = h; g.Olo[(size_t)r1*K2o + (c0>>1)] = l;
        } else if (g.flags & FPLHI) {
            g.Ohi[(size_t)r0*K2o + (c0>>1)] = pack_hi(v00, v01);
            g.Ohi[(size_t)r1*K2o + (c0>>1)] = pack_hi(v10, v11);
        }
    }
}

// ---------------- LayerNorm -> planes ----------------------------------------
__global__ void __launch_bounds__(256) lnorm_kernel(const float* __restrict__ h,
                                                    uint* __restrict__ nhi,
                                                    uint* __restrict__ nlo)
{
    int row = blockIdx.x;
    int tid = threadIdx.x;
    float v = h[(size_t)row * 256 + tid];
    __shared__ float red[8];
    float s = v;
    #pragma unroll
    for (int o = 16; o > 0; o >>= 1) s += __shfl_xor_sync(0xffffffffu, s, o);
    if ((tid & 31) == 0) red[tid >> 5] = s;
    __syncthreads();
    float tot = 0.f;
    #pragma unroll
    for (int i = 0; i < 8; i++) tot += red[i];
    float mu = tot * (1.f / 256.f);
    float d = v - mu;
    float s2 = d * d;
    #pragma unroll
    for (int o = 16; o > 0; o >>= 1) s2 += __shfl_xor_sync(0xffffffffu, s2, o);
    __syncthreads();
    if ((tid & 31) == 0) red[tid >> 5] = s2;
    __syncthreads();
    float tot2 = 0.f;
    #pragma unroll
    for (int i = 0; i < 8; i++) tot2 += red[i];
    float var = tot2 * (1.f / 256.f);
    float o = d * rsqrtf(var + EPS_);
    float pn = __shfl_xor_sync(0xffffffffu, o, 1);
    if (!(tid & 1)) {
        uint hi, lo; split_pair(o, pn, hi, lo);
        nhi[(size_t)row * 128 + (tid >> 1)] = hi;
        nlo[(size_t)row * 128 + (tid >> 1)] = lo;
    }
}

// ---------------- V transpose into packed key-pair planes (hi only) ---------
__global__ void __launch_bounds__(128) vplanes_T(
    const float* __restrict__ V1, const float* __restrict__ V2,
    uint* __restrict__ vthi)
{
    __shared__ float Vs[64][33];
    int tid = threadIdx.x;
    int kt = blockIdx.x;
    int head = blockIdx.y;
    int br = blockIdx.z >> 1, b = blockIdx.z & 1;
    const float* V = br ? V2 : V1;
    #pragma unroll
    for (int i = 0; i < 4; i++) {
        int idx = tid + i * 128;
        int key = idx >> 3, f4 = (idx & 7) * 4;
        const float* p = &V[(size_t)(b * L_ + kt * 64 + key) * 256 + head * 32 + f4];
        float4 t4 = *(const float4*)p;
        Vs[key][f4] = t4.x; Vs[key][f4+1] = t4.y;
        Vs[key][f4+2] = t4.z; Vs[key][f4+3] = t4.w;
    }
    __syncthreads();
    int g = (br * 2 + b) * 8 + head;
    #pragma unroll
    for (int i = 0; i < 8; i++) {
        int widx = tid + i * 128;
        int d = widx >> 5, kp = widx & 31;
        size_t o = ((size_t)g * 32 + d) * 864 + kt * 32 + kp;
        vthi[o] = pack_hi(Vs[2*kp][d], Vs[2*kp+1][d]);
    }
}

// ---------------- tensor-core flash attention (QK x1, PV x1, static max) ----
__global__ void __launch_bounds__(128) attn_mma(
    const uint* __restrict__ Q1hi, const uint* __restrict__ K1hi,
    const uint* __restrict__ Q2hi, const uint* __restrict__ K2hi,
    const uint* __restrict__ VThi,
    float* __restrict__ O1, float* __restrict__ O2)
{
    __shared__ __align__(16) uint Khi[3][64][20];
    __shared__ __align__(16) uint Vhi[3][32][36];

    int tid = threadIdx.x, warp = tid >> 5, lane = tid & 31;
    int gq = lane >> 2, t = lane & 3;
    int lrow = lane & 7, lm = lane >> 3;
    int qt = blockIdx.x, head = blockIdx.y;
    int br = blockIdx.z >> 1, b = blockIdx.z & 1;
    const uint* Qhi = br ? Q2hi : Q1hi;
    const uint* KhG = br ? K2hi : K1hi;
    float* Ob = br ? O2 : O1;
    const float scale2 = 0.0625f * 1.44269504089f;
    const float MSTAT  = 12.0f;

    int vg = (br * 2 + b) * 8 + head;

    int fkey = tid >> 1;
    int fkw  = (tid & 1) * 8;
    int fd   = tid >> 2;
    int fvw  = (tid & 3) * 8;
    const size_t kbase = (size_t)(b * L_ + fkey) * 128 + head * 16 + fkw;
    const size_t vbase = ((size_t)vg * 32 + fd) * 864 + fvw;

    #pragma unroll
    for (int s = 0; s < 2; s++) {
        size_t ko = kbase + (size_t)s * 64 * 128;
        size_t vo = vbase + (size_t)s * 32;
        cp16(sa(&Khi[s][fkey][fkw]),   KhG + ko);
        cp16(sa(&Khi[s][fkey][fkw+4]), KhG + ko + 4);
        cp16(sa(&Vhi[s][fd][fvw]),     VThi + vo);
        cp16(sa(&Vhi[s][fd][fvw+4]),   VThi + vo + 4);
        CP_COMMIT();
    }

    int r0 = qt * 64 + warp * 16 + gq;
    int r1 = r0 + 8;

    uint qh[2][4];
    {
        size_t q0 = (size_t)(b * L_ + r0) * 128 + head * 16;
        size_t q1 = (size_t)(b * L_ + r1) * 128 + head * 16;
        #pragma unroll
        for (int ks = 0; ks < 2; ks++) {
            qh[ks][0] = Qhi[q0 + ks*8 + t];     qh[ks][1] = Qhi[q1 + ks*8 + t];
            qh[ks][2] = Qhi[q0 + ks*8 + t + 4]; qh[ks][3] = Qhi[q1 + ks*8 + t + 4];
        }
    }

    float Oacc[4][4];
    #pragma unroll
    for (int j = 0; j < 4; j++)
        #pragma unroll
        for (int i = 0; i < 4; i++) Oacc[j][i] = 0.f;
    float l0r = 0.f, l1r = 0.f;

    int klw = lm << 2;

    for (int kt = 0; kt < NKT; kt++) {
        CP_WAIT1();
        __syncthreads();
        int pt = kt + 2;
        if (pt < NKT) {
            int nb = pt % 3;
            size_t ko = kbase + (size_t)pt * 64 * 128;
            size_t vo = vbase + (size_t)pt * 32;
            cp16(sa(&Khi[nb][fkey][fkw]),   KhG + ko);
            cp16(sa(&Khi[nb][fkey][fkw+4]), KhG + ko + 4);
            cp16(sa(&Vhi[nb][fd][fvw]),     VThi + vo);
            cp16(sa(&Vhi[nb][fd][fvw+4]),   VThi + vo + 4);
        }
        CP_COMMIT();
        int bb = kt % 3;

        // S = Q K^T (x1)
        float s[8][4];
        #pragma unroll
        for (int j = 0; j < 8; j++) {
            s[j][0] = s[j][1] = s[j][2] = s[j][3] = 0.f;
            uint kh0, kh1, kh2, kh3;
            ldsm4(kh0, kh1, kh2, kh3, sa(&Khi[bb][j*8 + lrow][klw]));
            mma_bf16(s[j], qh[0][0], qh[0][1], qh[0][2], qh[0][3], kh0, kh1);
            mma_bf16(s[j], qh[1][0], qh[1][1], qh[1][2], qh[1][3], kh2, kh3);
            s[j][0] = ex2(fmaf(s[j][0], scale2, -MSTAT)); l0r += s[j][0];
            s[j][1] = ex2(fmaf(s[j][1], scale2, -MSTAT)); l0r += s[j][1];
            s[j][2] = ex2(fmaf(s[j][2], scale2, -MSTAT)); l1r += s[j][2];
            s[j][3] = ex2(fmaf(s[j][3], scale2, -MSTAT)); l1r += s[j][3];
        }

        // P -> bf16x2 fragments (hi only)
        uint ph[4][4];
        #pragma unroll
        for (int ks = 0; ks < 4; ks++) {
            ph[ks][0] = pack_hi(s[2*ks  ][0], s[2*ks  ][1]);
            ph[ks][1] = pack_hi(s[2*ks  ][2], s[2*ks  ][3]);
            ph[ks][2] = pack_hi(s[2*ks+1][0], s[2*ks+1][1]);
            ph[ks][3] = pack_hi(s[2*ks+1][2], s[2*ks+1][3]);
        }

        // O += P V (x1)
        #pragma unroll
        for (int jn = 0; jn < 4; jn++) {
            #pragma unroll
            for (int h2 = 0; h2 < 2; h2++) {
                uint vh0, vh1, vh2, vh3;
                ldsm4(vh0, vh1, vh2, vh3, sa(&Vhi[bb][jn*8 + lrow][(h2<<4) + klw]));
                int ka = 2*h2, kb2 = 2*h2 + 1;
                mma_bf16(Oacc[jn], ph[ka][0], ph[ka][1], ph[ka][2], ph[ka][3], vh0, vh1);
                mma_bf16(Oacc[jn], ph[kb2][0], ph[kb2][1], ph[kb2][2], ph[kb2][3], vh2, vh3);
            }
        }
    }

    l0r += __shfl_xor_sync(0xffffffffu, l0r, 1);
    l0r += __shfl_xor_sync(0xffffffffu, l0r, 2);
    l1r += __shfl_xor_sync(0xffffffffu, l1r, 1);
    l1r += __shfl_xor_sync(0xffffffffu, l1r, 2);

    float inv0 = 1.f / l0r, inv1 = 1.f / l1r;
    #pragma unroll
    for (int jn = 0; jn < 4; jn++) {
        int col = head * 32 + jn * 8 + 2 * t;
        *(float2*)&Ob[(size_t)(b * L_ + r0) * 256 + col] =
            make_float2(Oacc[jn][0] * inv0, Oacc[jn][1] * inv0);
        *(float2*)&Ob[(size_t)(b * L_ + r1) * 256 + col] =
            make_float2(Oacc[jn][2] * inv1, Oacc[jn][3] * inv1);
    }
}

// ---------------- launch --------------------------------------------------------
extern "C" void kernel_launch(void* const* d_in, const int* in_sizes, int n_in,
                              void* d_out, int out_size)
{
    const float* x       = (const float*)d_in[0];
    const float* context = (const float*)d_in[1];
    const float* bn_g = (const float*)d_in[2];
    const float* bn_b = (const float*)d_in[3];
    const float* bn_m = (const float*)d_in[4];
    const float* bn_v = (const float*)d_in[5];
    const float* ln1_g = (const float*)d_in[6];
    const float* ln1_b = (const float*)d_in[7];
    const float* ln2_g = (const float*)d_in[8];
    const float* ln2_b = (const float*)d_in[9];
    const float* ln3_g = (const float*)d_in[10];
    const float* ln3_b = (const float*)d_in[11];
    const float* pin_w = (const float*)d_in[12];
    const float* pin_b = (const float*)d_in[13];
    const float* q_w   = (const float*)d_in[14];
    const float* q_b   = (const float*)d_in[15];
    const float* k_w   = (const float*)d_in[16];
    const float* k_b   = (const float*)d_in[17];
    const float* v_w   = (const float*)d_in[18];
    const float* v_b   = (const float*)d_in[19];
    const float* ff1_w = (const float*)d_in[20];
    const float* ff1_b = (const float*)d_in[21];
    const float* ff2_w = (const float*)d_in[22];
    const float* ff2_b = (const float*)d_in[23];
    const float* pout_w = (const float*)d_in[24];
    const float* pout_b = (const float*)d_in[25];
    float* out = (float*)d_out;

    float *p_h, *p_v1, *p_v2, *p_O1, *p_O2;
    uint *p_xhi, *p_xlo, *p_cthi, *p_ctlo, *p_hhi, *p_hlo, *p_nhi, *p_nlo;
    uint *p_f1hi, *p_f1lo, *p_ahi, *p_alo;
    uint *p_q1hi, *p_k1hi, *p_q2hi, *p_k2hi;
    uint *p_vthi;
    uint *w_pin_h, *w_pin_l, *w_q1_h, *w_q1_l, *w_q2_h, *w_q2_l;
    uint *w_k_h, *w_k_l, *w_v_h, *w_v_l, *w_po_h, *w_po_l;
    uint *w_f1_h, *w_f1_l, *w_f2_h, *w_f2_l;
    float *p_bpin, *p_bq1, *p_bq2, *p_bff1;

    cudaGetSymbolAddress((void**)&p_h,    d_h);
    cudaGetSymbolAddress((void**)&p_v1,   d_v1);
    cudaGetSymbolAddress((void**)&p_v2,   d_v2);
    cudaGetSymbolAddress((void**)&p_O1,   d_O1);
    cudaGetSymbolAddress((void**)&p_O2,   d_O2);
    cudaGetSymbolAddress((void**)&p_xhi,  d_xhi);
    cudaGetSymbolAddress((void**)&p_xlo,  d_xlo);
    cudaGetSymbolAddress((void**)&p_cthi, d_cthi);
    cudaGetSymbolAddress((void**)&p_ctlo, d_ctlo);
    cudaGetSymbolAddress((void**)&p_hhi,  d_hhi);
    cudaGetSymbolAddress((void**)&p_hlo,  d_hlo);
    cudaGetSymbolAddress((void**)&p_nhi,  d_nhi);
    cudaGetSymbolAddress((void**)&p_nlo,  d_nlo);
    cudaGetSymbolAddress((void**)&p_f1hi, d_f1hi);
    cudaGetSymbolAddress((void**)&p_f1lo, d_f1lo);
    cudaGetSymbolAddress((void**)&p_ahi,  d_ahi);
    cudaGetSymbolAddress((void**)&p_alo,  d_alo);
    cudaGetSymbolAddress((void**)&p_q1hi, d_q1hi);
    cudaGetSymbolAddress((void**)&p_k1hi, d_k1hi);
    cudaGetSymbolAddress((void**)&p_q2hi, d_q2hi);
    cudaGetSymbolAddress((void**)&p_k2hi, d_k2hi);
    cudaGetSymbolAddress((void**)&p_vthi, d_vthi);
    cudaGetSymbolAddress((void**)&w_pin_h, d_Wpin_h);
    cudaGetSymbolAddress((void**)&w_pin_l, d_Wpin_l);
    cudaGetSymbolAddress((void**)&w_q1_h,  d_Wq1_h);
    cudaGetSymbolAddress((void**)&w_q1_l,  d_Wq1_l);
    cudaGetSymbolAddress((void**)&w_q2_h,  d_Wq2_h);
    cudaGetSymbolAddress((void**)&w_q2_l,  d_Wq2_l);
    cudaGetSymbolAddress((void**)&w_k_h,   d_Wk_h);
    cudaGetSymbolAddress((void**)&w_k_l,   d_Wk_l);
    cudaGetSymbolAddress((void**)&w_v_h,   d_Wv_h);
    cudaGetSymbolAddress((void**)&w_v_l,   d_Wv_l);
    cudaGetSymbolAddress((void**)&w_po_h,  d_Wpout_h);
    cudaGetSymbolAddress((void**)&w_po_l,  d_Wpout_l);
    cudaGetSymbolAddress((void**)&w_f1_h,  d_Wff1_h);
    cudaGetSymbolAddress((void**)&w_f1_l,  d_Wff1_l);
    cudaGetSymbolAddress((void**)&w_f2_h,  d_Wff2_h);
    cudaGetSymbolAddress((void**)&w_f2_l,  d_Wff2_l);
    cudaGetSymbolAddress((void**)&p_bpin,  d_bpin);
    cudaGetSymbolAddress((void**)&p_bq1,   d_bq1);
    cudaGetSymbolAddress((void**)&p_bq2,   d_bq2);
    cudaGetSymbolAddress((void**)&p_bff1,  d_bff1);

    // 1. all prep
    prep_all<<<5472, 256>>>(x, context, bn_g, bn_b, bn_m, bn_v,
                            ln1_g, ln1_b, ln2_g, ln2_b, ln3_g, ln3_b,
                            pin_w, pin_b, q_w, q_b, k_w, v_w,
                            ff1_w, ff1_b, ff2_w, pout_w);

    auto mkop = [](const uint* Ahi, const uint* Alo, const uint* Whi, const uint* Wlo,
                   const float* bias, const float* resid, float* o,
                   uint* Ohi, uint* Olo, int N, int K, int flags, int start) {
        GOp g = {};
        g.Ahi = Ahi; g.Alo = Alo; g.Whi = Whi; g.Wlo = Wlo;
        g.bias = bias; g.resid = resid; g.out = o; g.Ohi = Ohi; g.Olo = Olo;
        g.N = N; g.K = K; g.flags = flags; g.tileStart = start;
        return g;
    };
    const int RT = NTOK / 64;
    const int T256 = RT * 2;

    // 2. batch A: pin (x3) + k2, v2 (x2)
    {
        GBatch P = {};
        P.op[0] = mkop(p_xhi, p_xlo, w_pin_h, w_pin_l, p_bpin, nullptr,
                       p_h, p_hhi, p_hlo, 256, 256, FOUT | FRELU | FPLANES, 0);
        P.op[1] = mkop(p_cthi, nullptr, w_k_h, w_k_l, k_b, nullptr,
                       nullptr, p_k2hi, nullptr, 256, 256, FPLHI | FX2, T256);
        P.op[2] = mkop(p_cthi, nullptr, w_v_h, w_v_l, v_b, nullptr,
                       p_v2, nullptr, nullptr, 256, 256, FOUT | FX2, T256*2);
        P.nops = 3;
        gemmT<<<T256*3, 256>>>(P);
    }

    // 3. hhat planes
    lnorm_kernel<<<NTOK, 256>>>(p_h, p_nhi, p_nlo);

    // 4. batch B: q1, k1, v1, q2 (x2), ff1 (x3)
    {
        GBatch P = {};
        P.op[0] = mkop(p_nhi, nullptr, w_q1_h, w_q1_l, p_bq1, nullptr,
                       nullptr, p_q1hi, nullptr, 256, 256, FPLHI | FX2, 0);
        P.op[1] = mkop(p_hhi, nullptr, w_k_h, w_k_l, k_b, nullptr,
                       nullptr, p_k1hi, nullptr, 256, 256, FPLHI | FX2, T256);
        P.op[2] = mkop(p_hhi, nullptr, w_v_h, w_v_l, v_b, nullptr,
                       p_v1, nullptr, nullptr, 256, 256, FOUT | FX2, T256*2);
        P.op[3] = mkop(p_nhi, nullptr, w_q2_h, w_q2_l, p_bq2, nullptr,
                       nullptr, p_q2hi, nullptr, 256, 256, FPLHI | FX2, T256*3);
        P.op[4] = mkop(p_nhi, p_nlo, w_f1_h, w_f1_l, p_bff1, nullptr,
                       nullptr, p_f1hi, p_f1lo, 1024, 256, FRELU | FPLANES, T256*4);
        P.nops = 5;
        gemmT<<<T256*4 + RT*8, 256>>>(P);
    }

    // 5. V transpose planes (hi only)
    {
        dim3 gv(NKT, H_, 4);
        vplanes_T<<<gv, 128>>>(p_v1, p_v2, p_vthi);
    }

    // 6. attention (QK x1, PV x1)
    {
        dim3 ga(NKT, H_, 4);
        attn_mma<<<ga, 128>>>(p_q1hi, p_k1hi, p_q2hi, p_k2hi,
                              p_vthi, p_O1, p_O2);
    }

    // 7. ff2 + combine fused
    {
        GBatch P = {};
        P.op[0] = mkop(p_f1hi, p_f1lo, w_f2_h, w_f2_l, ff2_b, nullptr,
                       nullptr, p_ahi, p_alo, 256, 1024, FSUM3 | FPLANES, 0);
        P.op[0].sum1 = p_h;
        P.op[0].sum2 = p_O1;
        P.op[0].sum3 = p_O2;
        P.nops = 1;
        gemmT<<<T256, 256>>>(P);
    }

    // 8. out = relu(acc @ pout + b) + x
    {
        GBatch P = {};
        P.op[0] = mkop(p_ahi, p_alo, w_po_h, w_po_l, pout_b, x,
                       out, nullptr, nullptr, 256, 256, FOUT | FRELU | FRESID, 0);
        P.nops = 1;
        gemmT<<<T256, 256>>>(P);
    }
}

// round 16
// speedup vs baseline: 1.6775x; 1.0344x over previous
#include <cuda_runtime.h>
#include <math.h>

typedef unsigned long long ull;
typedef unsigned int uint;

#define B_    2
#define L_    1728
#define NTOK  3456
#define C_    256
#define U_    256
#define H_    8
#define HD    32
#define FF_   1024
#define EPS_  1e-3f
#define NKT   27

#define FRELU   1
#define FRESID  2
#define FPLANES 4
#define FOUT    8
#define FSUM3   16
#define FPLHI   32
#define FX2     64
#define FVT     128

// ---------------- cp.async helpers ------------------------------------------
__device__ __forceinline__ void cp16(uint saddr, const void* gptr) {
    asm volatile("cp.async.cg.shared.global [%0], [%1], 16;" :: "r"(saddr), "l"(gptr));
}
__device__ __forceinline__ uint sa(const void* p) {
    return (uint)__cvta_generic_to_shared(p);
}
#define CP_COMMIT() asm volatile("cp.async.commit_group;")
#define CP_WAIT0()  asm volatile("cp.async.wait_group 0;")
#define CP_WAIT1()  asm volatile("cp.async.wait_group 1;")

// ---------------- ldmatrix ----------------------------------------------------
__device__ __forceinline__ void ldsm4(uint& r0, uint& r1, uint& r2, uint& r3, uint saddr) {
    asm volatile("ldmatrix.sync.aligned.m8n8.x4.shared.b16 {%0,%1,%2,%3}, [%4];"
                 : "=r"(r0), "=r"(r1), "=r"(r2), "=r"(r3) : "r"(saddr));
}

// ---------------- fast exp2 --------------------------------------------------
__device__ __forceinline__ float ex2(float x) {
    float y; asm("ex2.approx.f32 %0,%1;" : "=f"(y) : "f"(x)); return y;
}

// ---------------- bf16 split helpers ---------------------------------------
__device__ __forceinline__ uint bf16_of(float f) {
    unsigned short u; asm("cvt.rn.bf16.f32 %0,%1;" : "=h"(u) : "f"(f));
    return (uint)u;
}
__device__ __forceinline__ void split_pair(float f0, float f1, uint& hi, uint& lo) {
    uint h0 = bf16_of(f0), h1 = bf16_of(f1);
    hi = h0 | (h1 << 16);
    float r0 = f0 - __uint_as_float(h0 << 16);
    float r1 = f1 - __uint_as_float(h1 << 16);
    lo = bf16_of(r0) | (bf16_of(r1) << 16);
}
__device__ __forceinline__ uint pack_hi(float f0, float f1) {
    return bf16_of(f0) | (bf16_of(f1) << 16);
}

// ---------------- mma m16n8k16 bf16 -----------------------------------------
__device__ __forceinline__ void mma_bf16(float* c, uint a0, uint a1, uint a2, uint a3,
                                         uint b0, uint b1) {
    asm volatile("mma.sync.aligned.m16n8k16.row.col.f32.bf16.bf16.f32 "
                 "{%0,%1,%2,%3},{%4,%5,%6,%7},{%8,%9},{%0,%1,%2,%3};"
                 : "+f"(c[0]), "+f"(c[1]), "+f"(c[2]), "+f"(c[3])
                 : "r"(a0), "r"(a1), "r"(a2), "r"(a3), "r"(b0), "r"(b1));
}

// ---------------- scratch ---------------------------------------------------
__device__ float d_h   [NTOK*U_];
__device__ float d_O1  [NTOK*U_];
__device__ float d_O2  [NTOK*U_];

__device__ uint d_xhi [NTOK*128], d_xlo [NTOK*128];
__device__ uint d_cthi[NTOK*128], d_ctlo[NTOK*128];
__device__ uint d_hhi [NTOK*128], d_hlo [NTOK*128];
__device__ uint d_nhi [NTOK*128], d_nlo [NTOK*128];
__device__ uint d_f1hi[NTOK*512];
__device__ uint d_ahi [NTOK*128], d_alo [NTOK*128];
__device__ uint d_q1hi[NTOK*128];
__device__ uint d_k1hi[NTOK*128];
__device__ uint d_q2hi[NTOK*128];
__device__ uint d_k2hi[NTOK*128];
__device__ uint d_vthi[32*32*864];

__device__ uint d_Wpin_h[256*128], d_Wpin_l[256*128];
__device__ uint d_Wq1_h [256*128], d_Wq1_l [256*128];
__device__ uint d_Wq2_h [256*128], d_Wq2_l [256*128];
__device__ uint d_Wk_h  [256*128], d_Wk_l  [256*128];
__device__ uint d_Wv_h  [256*128], d_Wv_l  [256*128];
__device__ uint d_Wpout_h[256*128], d_Wpout_l[256*128];
__device__ uint d_Wff1_h[1024*128], d_Wff1_l[1024*128];
__device__ uint d_Wff2_h[256*512],  d_Wff2_l[256*512];

__device__ float d_bpin[U_], d_bq1[U_], d_bq2[U_], d_bff1[FF_];

// ---------------- prep_all (one launch) --------------------------------------
__global__ void __launch_bounds__(256) prep_all(
    const float* __restrict__ x,    const float* __restrict__ ctx,
    const float* __restrict__ bn_g, const float* __restrict__ bn_b,
    const float* __restrict__ bn_m, const float* __restrict__ bn_v,
    const float* __restrict__ ln1_g, const float* __restrict__ ln1_b,
    const float* __restrict__ ln2_g, const float* __restrict__ ln2_b,
    const float* __restrict__ ln3_g, const float* __restrict__ ln3_b,
    const float* __restrict__ pin_w, const float* __restrict__ pin_b,
    const float* __restrict__ q_w,  const float* __restrict__ q_b,
    const float* __restrict__ k_w,  const float* __restrict__ v_w,
    const float* __restrict__ ff1_w, const float* __restrict__ ff1_b,
    const float* __restrict__ ff2_w, const float* __restrict__ pout_w)
{
    int blk = blockIdx.x;
    int tid = threadIdx.x;

    if (blk < 1792) {
        int w = blk * 256 + tid;
        float w0, w1;
        uint *dh, *dl;
        size_t oidx;
        if (w < 196608) {
            int r = w >> 15;
            int idx = w & 32767;
            int u = idx >> 7, k2 = idx & 127;
            int k = k2 * 2;
            oidx = (size_t)u * 128 + k2;
            switch (r) {
            case 0: {
                float s0 = rsqrtf(bn_v[k] + EPS_) * bn_g[k];
                float s1 = rsqrtf(bn_v[k+1] + EPS_) * bn_g[k+1];
                w0 = s0 * pin_w[k*256 + u]; w1 = s1 * pin_w[(k+1)*256 + u];
                dh = d_Wpin_h; dl = d_Wpin_l; } break;
            case 1:
                w0 = ln1_g[k] * q_w[k*256 + u]; w1 = ln1_g[k+1] * q_w[(k+1)*256 + u];
                dh = d_Wq1_h; dl = d_Wq1_l; break;
            case 2:
                w0 = ln2_g[k] * q_w[k*256 + u]; w1 = ln2_g[k+1] * q_w[(k+1)*256 + u];
                dh = d_Wq2_h; dl = d_Wq2_l; break;
            case 3:
                w0 = k_w[k*256 + u]; w1 = k_w[(k+1)*256 + u];
                dh = d_Wk_h; dl = d_Wk_l; break;
            case 4:
                w0 = v_w[k*256 + u]; w1 = v_w[(k+1)*256 + u];
                dh = d_Wv_h; dl = d_Wv_l; break;
            default:
                w0 = pout_w[k*256 + u]; w1 = pout_w[(k+1)*256 + u];
                dh = d_Wpout_h; dl = d_Wpout_l; break;
            }
        } else if (w < 327680) {
            int idx = w - 196608;
            int u = idx >> 7, k2 = idx & 127;
            int k = k2 * 2;
            oidx = (size_t)u * 128 + k2;
            w0 = ln3_g[k] * ff1_w[k*1024 + u]; w1 = ln3_g[k+1] * ff1_w[(k+1)*1024 + u];
            dh = d_Wff1_h; dl = d_Wff1_l;
        } else {
            int idx = w - 327680;
            int u = idx >> 9, k2 = idx & 511;
            int k = k2 * 2;
            oidx = (size_t)u * 512 + k2;
            w0 = ff2_w[k*256 + u]; w1 = ff2_w[(k+1)*256 + u];
            dh = d_Wff2_h; dl = d_Wff2_l;
        }
        uint hi, lo; split_pair(w0, w1, hi, lo);
        dh[oidx] = hi; dl[oidx] = lo;
    } else if (blk < 5248) {
        int rel = blk - 1792;
        const float* s; uint *ph, *pl;
        if (rel < 1728) { s = x; ph = d_xhi; pl = d_xlo; }
        else { rel -= 1728; s = ctx; ph = d_cthi; pl = d_ctlo; }
        int i = rel * 256 + tid;
        float2 f = ((const float2*)s)[i];
        uint h, l; split_pair(f.x, f.y, h, l);
        ph[i] = h; pl[i] = l;
    } else {
        int gw = (blk - 5248) * 8 + (tid >> 5);
        int lane = tid & 31;
        float part = 0.f;
        int u;
        if (gw < 256) {
            u = gw;
            for (int k = lane; k < 256; k += 32) {
                float sc = rsqrtf(bn_v[k] + EPS_) * bn_g[k];
                part += (bn_b[k] - bn_m[k] * sc) * pin_w[k*256 + u];
            }
        } else if (gw < 512) {
            u = gw - 256;
            for (int k = lane; k < 256; k += 32) part += ln1_b[k] * q_w[k*256 + u];
        } else if (gw < 768) {
            u = gw - 512;
            for (int k = lane; k < 256; k += 32) part += ln2_b[k] * q_w[k*256 + u];
        } else {
            u = gw - 768;
            for (int k = lane; k < 256; k += 32) part += ln3_b[k] * ff1_w[k*1024 + u];
        }
        #pragma unroll
        for (int o = 16; o > 0; o >>= 1) part += __shfl_xor_sync(0xffffffffu, part, o);
        if (lane == 0) {
            if (gw < 256)      d_bpin[u] = pin_b[u] + part;
            else if (gw < 512) d_bq1[u]  = q_b[u]  + part;
            else if (gw < 768) d_bq2[u]  = q_b[u]  + part;
            else               d_bff1[u] = ff1_b[u] + part;
        }
    }
}

// ---------------- tensor-core batched GEMM: 64x128, K32 stages, ldmatrix ----
struct GOp {
    const uint* Ahi; const uint* Alo;
    const uint* Whi; const uint* Wlo;
    const float* bias; const float* resid;
    const float* sum1; const float* sum2; const float* sum3;
    float* out; uint* Ohi; uint* Olo;
    uint* vt; int vbr;
    int N; int K; int flags; int tileStart;
};
struct GBatch { GOp op[8]; int nops; };

__global__ void __launch_bounds__(256, 2) gemmT(GBatch P)
{
    __shared__ __align__(16) uint As_hi[2][64][20],  As_lo[2][64][20];
    __shared__ __align__(16) uint Ws_hi[2][128][20], Ws_lo[2][128][20];

    int bid = blockIdx.x;
    int sel = 0;
    #pragma unroll
    for (int i = 1; i < 8; i++)
        if (i < P.nops && bid >= P.op[i].tileStart) sel = i;
    GOp g = P.op[sel];
    bool x2 = (g.flags & FX2) != 0;

    int local = bid - g.tileStart;
    int ntn = g.N >> 7;
    int mt = local / ntn;
    int nt = local - mt * ntn;
    int m0 = mt * 64, n0 = nt * 128;
    int tid = threadIdx.x;
    int warp = tid >> 5, lane = tid & 31;
    int gq = lane >> 2, t = lane & 3;
    int rw = warp & 3;
    int ch = warp >> 2;
    int K2 = g.K >> 1;

    int lrow = lane & 7, lm = lane >> 3;

    float acc[8][4];
    #pragma unroll
    for (int j = 0; j < 8; j++)
        #pragma unroll
        for (int i = 0; i < 4; i++) acc[j][i] = 0.f;

    int arow = tid >> 1;
    int aw0  = (tid & 1) * 8;
    int wrow = tid >> 1;
    int ww0  = (tid & 1) * 8;
    const size_t abase = (size_t)(m0 + arow) * K2 + aw0;
    const size_t wbase = (size_t)(n0 + wrow) * K2 + ww0;

    int nst = K2 >> 4;

    {
        if (tid < 128) {
            cp16(sa(&As_hi[0][arow][aw0]),   g.Ahi + abase);
            cp16(sa(&As_hi[0][arow][aw0+4]), g.Ahi + abase + 4);
            if (!x2) {
                cp16(sa(&As_lo[0][arow][aw0]),   g.Alo + abase);
                cp16(sa(&As_lo[0][arow][aw0+4]), g.Alo + abase + 4);
            }
        }
        cp16(sa(&Ws_hi[0][wrow][ww0]),   g.Whi + wbase);
        cp16(sa(&Ws_hi[0][wrow][ww0+4]), g.Whi + wbase + 4);
        cp16(sa(&Ws_lo[0][wrow][ww0]),   g.Wlo + wbase);
        cp16(sa(&Ws_lo[0][wrow][ww0+4]), g.Wlo + wbase + 4);
        CP_COMMIT();
    }

    int a_r = (rw << 4) + ((lm & 1) << 3) + lrow;
    int a_w = (lm >> 1) << 2;
    int b_rbase = (ch << 6) + ((lm >> 1) << 3) + lrow;
    int b_w = (lm & 1) << 2;

    for (int c = 0; c < nst; c++) {
        CP_WAIT0();
        __syncthreads();
        int pc = c + 1;
        if (pc < nst) {
            int nb = pc & 1;
            size_t off = (size_t)pc * 16;
            if (tid < 128) {
                cp16(sa(&As_hi[nb][arow][aw0]),   g.Ahi + abase + off);
                cp16(sa(&As_hi[nb][arow][aw0+4]), g.Ahi + abase + off + 4);
                if (!x2) {
                    cp16(sa(&As_lo[nb][arow][aw0]),   g.Alo + abase + off);
                    cp16(sa(&As_lo[nb][arow][aw0+4]), g.Alo + abase + off + 4);
                }
            }
            cp16(sa(&Ws_hi[nb][wrow][ww0]),   g.Whi + wbase + off);
            cp16(sa(&Ws_hi[nb][wrow][ww0+4]), g.Whi + wbase + off + 4);
            cp16(sa(&Ws_lo[nb][wrow][ww0]),   g.Wlo + wbase + off);
            cp16(sa(&Ws_lo[nb][wrow][ww0+4]), g.Wlo + wbase + off + 4);
        }
        CP_COMMIT();

        int bb = c & 1;
        #pragma unroll
        for (int hf = 0; hf < 2; hf++) {
            int wo = hf * 8;
            uint a0h, a1h, a2h, a3h;
            ldsm4(a0h, a1h, a2h, a3h, sa(&As_hi[bb][a_r][a_w + wo]));
            uint a0l = 0, a1l = 0, a2l = 0, a3l = 0;
            if (!x2) ldsm4(a0l, a1l, a2l, a3l, sa(&As_lo[bb][a_r][a_w + wo]));

            #pragma unroll
            for (int jp = 0; jp < 4; jp++) {
                uint bh0, bh1, bh2, bh3, bl0, bl1, bl2, bl3;
                ldsm4(bh0, bh1, bh2, bh3, sa(&Ws_hi[bb][b_rbase + jp*16][b_w + wo]));
                ldsm4(bl0, bl1, bl2, bl3, sa(&Ws_lo[bb][b_rbase + jp*16][b_w + wo]));
                mma_bf16(acc[jp*2  ], a0h, a1h, a2h, a3h, bh0, bh1);
                mma_bf16(acc[jp*2  ], a0h, a1h, a2h, a3h, bl0, bl1);
                mma_bf16(acc[jp*2+1], a0h, a1h, a2h, a3h, bh2, bh3);
                mma_bf16(acc[jp*2+1], a0h, a1h, a2h, a3h, bl2, bl3);
                if (!x2) {
                    mma_bf16(acc[jp*2  ], a0l, a1l, a2l, a3l, bh0, bh1);
                    mma_bf16(acc[jp*2+1], a0l, a1l, a2l, a3l, bh2, bh3);
                }
            }
        }
    }

    int K2o = g.N >> 1;
    int r0 = m0 + rw*16 + gq;
    int r1 = r0 + 8;
    #pragma unroll
    for (int j = 0; j < 8; j++) {
        int c0 = n0 + ch*64 + j*8 + 2*t;
        float b0 = g.bias[c0], b1 = g.bias[c0+1];
        float v00 = acc[j][0] + b0, v01 = acc[j][1] + b1;
        float v10 = acc[j][2] + b0, v11 = acc[j][3] + b1;
        if (g.flags & FRELU) {
            v00 = fmaxf(v00, 0.f); v01 = fmaxf(v01, 0.f);
            v10 = fmaxf(v10, 0.f); v11 = fmaxf(v11, 0.f);
        }
        if (g.flags & FRESID) {
            float2 ra = *(const float2*)&g.resid[(size_t)r0*g.N + c0];
            float2 rb = *(const float2*)&g.resid[(size_t)r1*g.N + c0];
            v00 += ra.x; v01 += ra.y; v10 += rb.x; v11 += rb.y;
        }
        if (g.flags & FSUM3) {
            float2 a1 = *(const float2*)&g.sum1[(size_t)r0*g.N + c0];
            float2 a2 = *(const float2*)&g.sum2[(size_t)r0*g.N + c0];
            float2 a3 = *(const float2*)&g.sum3[(size_t)r0*g.N + c0];
            v00 += a1.x + a2.x + a3.x; v01 += a1.y + a2.y + a3.y;
            float2 c1 = *(const float2*)&g.sum1[(size_t)r1*g.N + c0];
            float2 c2 = *(const float2*)&g.sum2[(size_t)r1*g.N + c0];
            float2 c3 = *(const float2*)&g.sum3[(size_t)r1*g.N + c0];
            v10 += c1.x + c2.x + c3.x; v11 += c1.y + c2.y + c3.y;
        }
        if (g.flags & FVT) {
            // pack adjacent-token pairs via lane-xor-4 partner (gq^1)
            float p00 = __shfl_xor_sync(0xffffffffu, v00, 4);
            float p01 = __shfl_xor_sync(0xffffffffu, v01, 4);
            float p10 = __shfl_xor_sync(0xffffffffu, v10, 4);
            float p11 = __shfl_xor_sync(0xffffffffu, v11, 4);
            if (!(gq & 1)) {
                int bidx = r0 / L_;
                int key0 = r0 - bidx * L_;
                int head = c0 >> 5, d = c0 & 31;
                int gg = (g.vbr * 2 + bidx) * 8 + head;
                size_t base = ((size_t)gg * 32 + d) * 864;
                g.vt[base + (key0 >> 1)]       = pack_hi(v00, p00);
                g.vt[base + 864 + (key0 >> 1)] = pack_hi(v01, p01);
                int kp1 = (key0 >> 1) + 4;
                g.vt[base + kp1]       = pack_hi(v10, p10);
                g.vt[base + 864 + kp1] = pack_hi(v11, p11);
            }
        }
        if (g.flags & FOUT) {
            *(float2*)&g.out[(size_t)r0*g.N + c0] = make_float2(v00, v01);
            *(float2*)&g.out[(size_t)r1*g.N + c0] = make_float2(v10, v11);
        }
        if (g.flags & FPLANES) {
            uint h, l;
            split_pair(v00, v01, h, l);
            g.Ohi[(size_t)r0*K2o + (c0>>1)] = h; g.Olo[(size_t)r0*K2o + (c0>>1)] = l;
            split_pair(v10, v11, h, l);
            g.Ohi[(size_t)r1*K2o + (c0>>1)] = h; g.Olo[(size_t)r1*K2o + (c0>>1)] = l;
        } else if (g.flags & FPLHI) {
            g.Ohi[(size_t)r0*K2o + (c0>>1)] = pack_hi(v00, v01);
            g.Ohi[(size_t)r1*K2o + (c0>>1)] = pack_hi(v10, v11);
        }
    }
}

// ---------------- LayerNorm -> planes ----------------------------------------
__global__ void __launch_bounds__(256) lnorm_kernel(const float* __restrict__ h,
                                                    uint* __restrict__ nhi,
                                                    uint* __restrict__ nlo)
{
    int row = blockIdx.x;
    int tid = threadIdx.x;
    float v = h[(size_t)row * 256 + tid];
    __shared__ float red[8];
    float s = v;
    #pragma unroll
    for (int o = 16; o > 0; o >>= 1) s += __shfl_xor_sync(0xffffffffu, s, o);
    if ((tid & 31) == 0) red[tid >> 5] = s;
    __syncthreads();
    float tot = 0.f;
    #pragma unroll
    for (int i = 0; i < 8; i++) tot += red[i];
    float mu = tot * (1.f / 256.f);
    float d = v - mu;
    float s2 = d * d;
    #pragma unroll
    for (int o = 16; o > 0; o >>= 1) s2 += __shfl_xor_sync(0xffffffffu, s2, o);
    __syncthreads();
    if ((tid & 31) == 0) red[tid >> 5] = s2;
    __syncthreads();
    float tot2 = 0.f;
    #pragma unroll
    for (int i = 0; i < 8; i++) tot2 += red[i];
    float var = tot2 * (1.f / 256.f);
    float o = d * rsqrtf(var + EPS_);
    float pn = __shfl_xor_sync(0xffffffffu, o, 1);
    if (!(tid & 1)) {
        uint hi, lo; split_pair(o, pn, hi, lo);
        nhi[(size_t)row * 128 + (tid >> 1)] = hi;
        nlo[(size_t)row * 128 + (tid >> 1)] = lo;
    }
}

// ---------------- tensor-core flash attention (QK x1, PV x1, static max) ----
__global__ void __launch_bounds__(128) attn_mma(
    const uint* __restrict__ Q1hi, const uint* __restrict__ K1hi,
    const uint* __restrict__ Q2hi, const uint* __restrict__ K2hi,
    const uint* __restrict__ VThi,
    float* __restrict__ O1, float* __restrict__ O2)
{
    __shared__ __align__(16) uint Khi[3][64][20];
    __shared__ __align__(16) uint Vhi[3][32][36];

    int tid = threadIdx.x, warp = tid >> 5, lane = tid & 31;
    int gq = lane >> 2, t = lane & 3;
    int lrow = lane & 7, lm = lane >> 3;
    int qt = blockIdx.x, head = blockIdx.y;
    int br = blockIdx.z >> 1, b = blockIdx.z & 1;
    const uint* Qhi = br ? Q2hi : Q1hi;
    const uint* KhG = br ? K2hi : K1hi;
    float* Ob = br ? O2 : O1;
    const float scale2 = 0.0625f * 1.44269504089f;
    const float MSTAT  = 12.0f;

    int vg = (br * 2 + b) * 8 + head;

    int fkey = tid >> 1;
    int fkw  = (tid & 1) * 8;
    int fd   = tid >> 2;
    int fvw  = (tid & 3) * 8;
    const size_t kbase = (size_t)(b * L_ + fkey) * 128 + head * 16 + fkw;
    const size_t vbase = ((size_t)vg * 32 + fd) * 864 + fvw;

    #pragma unroll
    for (int s = 0; s < 2; s++) {
        size_t ko = kbase + (size_t)s * 64 * 128;
        size_t vo = vbase + (size_t)s * 32;
        cp16(sa(&Khi[s][fkey][fkw]),   KhG + ko);
        cp16(sa(&Khi[s][fkey][fkw+4]), KhG + ko + 4);
        cp16(sa(&Vhi[s][fd][fvw]),     VThi + vo);
        cp16(sa(&Vhi[s][fd][fvw+4]),   VThi + vo + 4);
        CP_COMMIT();
    }

    int r0 = qt * 64 + warp * 16 + gq;
    int r1 = r0 + 8;

    uint qh[2][4];
    {
        size_t q0 = (size_t)(b * L_ + r0) * 128 + head * 16;
        size_t q1 = (size_t)(b * L_ + r1) * 128 + head * 16;
        #pragma unroll
        for (int ks = 0; ks < 2; ks++) {
            qh[ks][0] = Qhi[q0 + ks*8 + t];     qh[ks][1] = Qhi[q1 + ks*8 + t];
            qh[ks][2] = Qhi[q0 + ks*8 + t + 4]; qh[ks][3] = Qhi[q1 + ks*8 + t + 4];
        }
    }

    float Oacc[4][4];
    #pragma unroll
    for (int j = 0; j < 4; j++)
        #pragma unroll
        for (int i = 0; i < 4; i++) Oacc[j][i] = 0.f;
    float l0r = 0.f, l1r = 0.f;

    int klw = lm << 2;

    for (int kt = 0; kt < NKT; kt++) {
        CP_WAIT1();
        __syncthreads();
        int pt = kt + 2;
        if (pt < NKT) {
            int nb = pt % 3;
            size_t ko = kbase + (size_t)pt * 64 * 128;
            size_t vo = vbase + (size_t)pt * 32;
            cp16(sa(&Khi[nb][fkey][fkw]),   KhG + ko);
            cp16(sa(&Khi[nb][fkey][fkw+4]), KhG + ko + 4);
            cp16(sa(&Vhi[nb][fd][fvw]),     VThi + vo);
            cp16(sa(&Vhi[nb][fd][fvw+4]),   VThi + vo + 4);
        }
        CP_COMMIT();
        int bb = kt % 3;

        float s[8][4];
        #pragma unroll
        for (int j = 0; j < 8; j++) {
            s[j][0] = s[j][1] = s[j][2] = s[j][3] = 0.f;
            uint kh0, kh1, kh2, kh3;
            ldsm4(kh0, kh1, kh2, kh3, sa(&Khi[bb][j*8 + lrow][klw]));
            mma_bf16(s[j], qh[0][0], qh[0][1], qh[0][2], qh[0][3], kh0, kh1);
            mma_bf16(s[j], qh[1][0], qh[1][1], qh[1][2], qh[1][3], kh2, kh3);
            s[j][0] = ex2(fmaf(s[j][0], scale2, -MSTAT)); l0r += s[j][0];
            s[j][1] = ex2(fmaf(s[j][1], scale2, -MSTAT)); l0r += s[j][1];
            s[j][2] = ex2(fmaf(s[j][2], scale2, -MSTAT)); l1r += s[j][2];
            s[j][3] = ex2(fmaf(s[j][3], scale2, -MSTAT)); l1r += s[j][3];
        }

        uint ph[4][4];
        #pragma unroll
        for (int ks = 0; ks < 4; ks++) {
            ph[ks][0] = pack_hi(s[2*ks  ][0], s[2*ks  ][1]);
            ph[ks][1] = pack_hi(s[2*ks  ][2], s[2*ks  ][3]);
            ph[ks][2] = pack_hi(s[2*ks+1][0], s[2*ks+1][1]);
            ph[ks][3] = pack_hi(s[2*ks+1][2], s[2*ks+1][3]);
        }

        #pragma unroll
        for (int jn = 0; jn < 4; jn++) {
            #pragma unroll
            for (int h2 = 0; h2 < 2; h2++) {
                uint vh0, vh1, vh2, vh3;
                ldsm4(vh0, vh1, vh2, vh3, sa(&Vhi[bb][jn*8 + lrow][(h2<<4) + klw]));
                int ka = 2*h2, kb2 = 2*h2 + 1;
                mma_bf16(Oacc[jn], ph[ka][0], ph[ka][1], ph[ka][2], ph[ka][3], vh0, vh1);
                mma_bf16(Oacc[jn], ph[kb2][0], ph[kb2][1], ph[kb2][2], ph[kb2][3], vh2, vh3);
            }
        }
    }

    l0r += __shfl_xor_sync(0xffffffffu, l0r, 1);
    l0r += __shfl_xor_sync(0xffffffffu, l0r, 2);
    l1r += __shfl_xor_sync(0xffffffffu, l1r, 1);
    l1r += __shfl_xor_sync(0xffffffffu, l1r, 2);

    float inv0 = 1.f / l0r, inv1 = 1.f / l1r;
    #pragma unroll
    for (int jn = 0; jn < 4; jn++) {
        int col = head * 32 + jn * 8 + 2 * t;
        *(float2*)&Ob[(size_t)(b * L_ + r0) * 256 + col] =
            make_float2(Oacc[jn][0] * inv0, Oacc[jn][1] * inv0);
        *(float2*)&Ob[(size_t)(b * L_ + r1) * 256 + col] =
            make_float2(Oacc[jn][2] * inv1, Oacc[jn][3] * inv1);
    }
}

// ---------------- launch --------------------------------------------------------
extern "C" void kernel_launch(void* const* d_in, const int* in_sizes, int n_in,
                              void* d_out, int out_size)
{
    const float* x       = (const float*)d_in[0];
    const float* context = (const float*)d_in[1];
    const float* bn_g = (const float*)d_in[2];
    const float* bn_b = (const float*)d_in[3];
    const float* bn_m = (const float*)d_in[4];
    const float* bn_v = (const float*)d_in[5];
    const float* ln1_g = (const float*)d_in[6];
    const float* ln1_b = (const float*)d_in[7];
    const float* ln2_g = (const float*)d_in[8];
    const float* ln2_b = (const float*)d_in[9];
    const float* ln3_g = (const float*)d_in[10];
    const float* ln3_b = (const float*)d_in[11];
    const float* pin_w = (const float*)d_in[12];
    const float* pin_b = (const float*)d_in[13];
    const float* q_w   = (const float*)d_in[14];
    const float* q_b   = (const float*)d_in[15];
    const float* k_w   = (const float*)d_in[16];
    const float* k_b   = (const float*)d_in[17];
    const float* v_w   = (const float*)d_in[18];
    const float* v_b   = (const float*)d_in[19];
    const float* ff1_w = (const float*)d_in[20];
    const float* ff1_b = (const float*)d_in[21];
    const float* ff2_w = (const float*)d_in[22];
    const float* ff2_b = (const float*)d_in[23];
    const float* pout_w = (const float*)d_in[24];
    const float* pout_b = (const float*)d_in[25];
    float* out = (float*)d_out;

    float *p_h, *p_O1, *p_O2;
    uint *p_xhi, *p_xlo, *p_cthi, *p_ctlo, *p_hhi, *p_hlo, *p_nhi, *p_nlo;
    uint *p_f1hi, *p_ahi, *p_alo;
    uint *p_q1hi, *p_k1hi, *p_q2hi, *p_k2hi;
    uint *p_vthi;
    uint *w_pin_h, *w_pin_l, *w_q1_h, *w_q1_l, *w_q2_h, *w_q2_l;
    uint *w_k_h, *w_k_l, *w_v_h, *w_v_l, *w_po_h, *w_po_l;
    uint *w_f1_h, *w_f1_l, *w_f2_h, *w_f2_l;
    float *p_bpin, *p_bq1, *p_bq2, *p_bff1;

    cudaGetSymbolAddress((void**)&p_h,    d_h);
    cudaGetSymbolAddress((void**)&p_O1,   d_O1);
    cudaGetSymbolAddress((void**)&p_O2,   d_O2);
    cudaGetSymbolAddress((void**)&p_xhi,  d_xhi);
    cudaGetSymbolAddress((void**)&p_xlo,  d_xlo);
    cudaGetSymbolAddress((void**)&p_cthi, d_cthi);
    cudaGetSymbolAddress((void**)&p_ctlo, d_ctlo);
    cudaGetSymbolAddress((void**)&p_hhi,  d_hhi);
    cudaGetSymbolAddress((void**)&p_hlo,  d_hlo);
    cudaGetSymbolAddress((void**)&p_nhi,  d_nhi);
    cudaGetSymbolAddress((void**)&p_nlo,  d_nlo);
    cudaGetSymbolAddress((void**)&p_f1hi, d_f1hi);
    cudaGetSymbolAddress((void**)&p_ahi,  d_ahi);
    cudaGetSymbolAddress((void**)&p_alo,  d_alo);
    cudaGetSymbolAddress((void**)&p_q1hi, d_q1hi);
    cudaGetSymbolAddress((void**)&p_k1hi, d_k1hi);
    cudaGetSymbolAddress((void**)&p_q2hi, d_q2hi);
    cudaGetSymbolAddress((void**)&p_k2hi, d_k2hi);
    cudaGetSymbolAddress((void**)&p_vthi, d_vthi);
    cudaGetSymbolAddress((void**)&w_pin_h, d_Wpin_h);
    cudaGetSymbolAddress((void**)&w_pin_l, d_Wpin_l);
    cudaGetSymbolAddress((void**)&w_q1_h,  d_Wq1_h);
    cudaGetSymbolAddress((void**)&w_q1_l,  d_Wq1_l);
    cudaGetSymbolAddress((void**)&w_q2_h,  d_Wq2_h);
    cudaGetSymbolAddress((void**)&w_q2_l,  d_Wq2_l);
    cudaGetSymbolAddress((void**)&w_k_h,   d_Wk_h);
    cudaGetSymbolAddress((void**)&w_k_l,   d_Wk_l);
    cudaGetSymbolAddress((void**)&w_v_h,   d_Wv_h);
    cudaGetSymbolAddress((void**)&w_v_l,   d_Wv_l);
    cudaGetSymbolAddress((void**)&w_po_h,  d_Wpout_h);
    cudaGetSymbolAddress((void**)&w_po_l,  d_Wpout_l);
    cudaGetSymbolAddress((void**)&w_f1_h,  d_Wff1_h);
    cudaGetSymbolAddress((void**)&w_f1_l,  d_Wff1_l);
    cudaGetSymbolAddress((void**)&w_f2_h,  d_Wff2_h);
    cudaGetSymbolAddress((void**)&w_f2_l,  d_Wff2_l);
    cudaGetSymbolAddress((void**)&p_bpin,  d_bpin);
    cudaGetSymbolAddress((void**)&p_bq1,   d_bq1);
    cudaGetSymbolAddress((void**)&p_bq2,   d_bq2);
    cudaGetSymbolAddress((void**)&p_bff1,  d_bff1);

    // 1. all prep
    prep_all<<<5472, 256>>>(x, context, bn_g, bn_b, bn_m, bn_v,
                            ln1_g, ln1_b, ln2_g, ln2_b, ln3_g, ln3_b,
                            pin_w, pin_b, q_w, q_b, k_w, v_w,
                            ff1_w, ff1_b, ff2_w, pout_w);

    auto mkop = [](const uint* Ahi, const uint* Alo, const uint* Whi, const uint* Wlo,
                   const float* bias, const float* resid, float* o,
                   uint* Ohi, uint* Olo, int N, int K, int flags, int start) {
        GOp g = {};
        g.Ahi = Ahi; g.Alo = Alo; g.Whi = Whi; g.Wlo = Wlo;
        g.bias = bias; g.resid = resid; g.out = o; g.Ohi = Ohi; g.Olo = Olo;
        g.N = N; g.K = K; g.flags = flags; g.tileStart = start;
        return g;
    };
    const int RT = NTOK / 64;
    const int T256 = RT * 2;

    // 2. batch A: pin (x3) + k2 (x2) + v2 (x2, fused V-transpose)
    {
        GBatch P = {};
        P.op[0] = mkop(p_xhi, p_xlo, w_pin_h, w_pin_l, p_bpin, nullptr,
                       p_h, p_hhi, p_hlo, 256, 256, FOUT | FRELU | FPLANES, 0);
        P.op[1] = mkop(p_cthi, nullptr, w_k_h, w_k_l, k_b, nullptr,
                       nullptr, p_k2hi, nullptr, 256, 256, FPLHI | FX2, T256);
        P.op[2] = mkop(p_cthi, nullptr, w_v_h, w_v_l, v_b, nullptr,
                       nullptr, nullptr, nullptr, 256, 256, FVT | FX2, T256*2);
        P.op[2].vt = p_vthi; P.op[2].vbr = 1;
        P.nops = 3;
        gemmT<<<T256*3, 256>>>(P);
    }

    // 3. hhat planes
    lnorm_kernel<<<NTOK, 256>>>(p_h, p_nhi, p_nlo);

    // 4. batch B: q1, k1 (x2), v1 (x2 + fused V-transpose), q2 (x2), ff1 (x3)
    {
        GBatch P = {};
        P.op[0] = mkop(p_nhi, nullptr, w_q1_h, w_q1_l, p_bq1, nullptr,
                       nullptr, p_q1hi, nullptr, 256, 256, FPLHI | FX2, 0);
        P.op[1] = mkop(p_hhi, nullptr, w_k_h, w_k_l, k_b, nullptr,
                       nullptr, p_k1hi, nullptr, 256, 256, FPLHI | FX2, T256);
        P.op[2] = mkop(p_hhi, nullptr, w_v_h, w_v_l, v_b, nullptr,
                       nullptr, nullptr, nullptr, 256, 256, FVT | FX2, T256*2);
        P.op[2].vt = p_vthi; P.op[2].vbr = 0;
        P.op[3] = mkop(p_nhi, nullptr, w_q2_h, w_q2_l, p_bq2, nullptr,
                       nullptr, p_q2hi, nullptr, 256, 256, FPLHI | FX2, T256*3);
        P.op[4] = mkop(p_nhi, p_nlo, w_f1_h, w_f1_l, p_bff1, nullptr,
                       nullptr, p_f1hi, nullptr, 1024, 256, FRELU | FPLHI, T256*4);
        P.nops = 5;
        gemmT<<<T256*4 + RT*8, 256>>>(P);
    }

    // 5. attention (QK x1, PV x1)
    {
        dim3 ga(NKT, H_, 4);
        attn_mma<<<ga, 128>>>(p_q1hi, p_k1hi, p_q2hi, p_k2hi,
                              p_vthi, p_O1, p_O2);
    }

    // 6. ff2 (x2) + combine fused
    {
        GBatch P = {};
        P.op[0] = mkop(p_f1hi, nullptr, w_f2_h, w_f2_l, ff2_b, nullptr,
                       nullptr, p_ahi, p_alo, 256, 1024, FSUM3 | FPLANES | FX2, 0);
        P.op[0].sum1 = p_h;
        P.op[0].sum2 = p_O1;
        P.op[0].sum3 = p_O2;
        P.nops = 1;
        gemmT<<<T256, 256>>>(P);
    }

    // 7. out = relu(acc @ pout + b) + x
    {
        GBatch P = {};
        P.op[0] = mkop(p_ahi, p_alo, w_po_h, w_po_l, pout_b, x,
                       out, nullptr, nullptr, 256, 256, FOUT | FRELU | FRESID, 0);
        P.nops = 1;
        gemmT<<<T256, 256>>>(P);
    }
}